// round 9
// baseline (speedup 1.0000x reference)
#include <cuda_runtime.h>
#include <cuda_fp16.h>
#include <math.h>

// ---------------------------------------------------------------------------
// MultiScaleCrossAttn — fp16 MMA GEMMs, fp16 residual streams,
// single-A-stage multi-chunk qkv.
// ---------------------------------------------------------------------------

#define ROWS0 12544      // 64*14*14
#define ROWS1 200704     // 64*56*56
#define ROWS2 65536      // 64*32*32
#define KVROWS 313600    // 64*196*25

__device__ __align__(16) __half g_t0[ROWS0 * 96];
__device__ __align__(16) __half g_t1[ROWS1 * 96];
__device__ __align__(16) __half g_t2[ROWS2 * 96];
__device__ __align__(16) __half g_qkv[ROWS1 * 288];
__device__ __align__(16) __half g_ob[ROWS1 * 96];
__device__ __align__(16) __half g_kv[KVROWS * 96];
__device__ __align__(16) __half g_k[KVROWS * 96];
__device__ __align__(16) __half g_v[KVROWS * 96];
__device__ __align__(16) __half g_q[ROWS0 * 96];
__device__ __align__(16) __half g_co[ROWS0 * 96];

static constexpr int AS_U4 = 6 * 8 * 32;   // 24KB
static constexpr int BS_U4 = 6 * 6 * 32;   // 18KB

__device__ __forceinline__ unsigned f2h2(float lo, float hi) {
    __half2 h = __floats2half2_rn(lo, hi);
    return *reinterpret_cast<unsigned*>(&h);
}

__device__ __forceinline__ void mma16(float c[4], uint4 a, unsigned b0, unsigned b1) {
    asm volatile(
        "mma.sync.aligned.m16n8k16.row.col.f32.f16.f16.f32 "
        "{%0,%1,%2,%3}, {%4,%5,%6,%7}, {%8,%9}, {%0,%1,%2,%3};\n"
        : "+f"(c[0]), "+f"(c[1]), "+f"(c[2]), "+f"(c[3])
        : "r"(a.x), "r"(a.y), "r"(a.z), "r"(a.w), "r"(b0), "r"(b1));
}

__device__ __forceinline__ float gelu_f(float v) {
    return 0.5f * v * (1.f + erff(v * 0.70710678118654752f));
}

__device__ __forceinline__ void gemm_main(float acc[2][6][4], const uint4* As4,
                                          const uint4* Bs4, int mg, int nh, int lane) {
#pragma unroll
    for (int m = 0; m < 2; ++m)
#pragma unroll
        for (int j = 0; j < 6; ++j)
#pragma unroll
            for (int i = 0; i < 4; ++i) acc[m][j][i] = 0.f;
#pragma unroll
    for (int kt = 0; kt < 6; ++kt) {
        uint4 a0 = As4[(kt * 8 + mg * 2) * 32 + lane];
        uint4 a1 = As4[(kt * 8 + mg * 2 + 1) * 32 + lane];
        uint4 b0 = Bs4[(kt * 6 + nh * 3) * 32 + lane];
        uint4 b1 = Bs4[(kt * 6 + nh * 3 + 1) * 32 + lane];
        uint4 b2 = Bs4[(kt * 6 + nh * 3 + 2) * 32 + lane];
        mma16(acc[0][0], a0, b0.x, b0.y); mma16(acc[0][1], a0, b0.z, b0.w);
        mma16(acc[0][2], a0, b1.x, b1.y); mma16(acc[0][3], a0, b1.z, b1.w);
        mma16(acc[0][4], a0, b2.x, b2.y); mma16(acc[0][5], a0, b2.z, b2.w);
        mma16(acc[1][0], a1, b0.x, b0.y); mma16(acc[1][1], a1, b0.z, b0.w);
        mma16(acc[1][2], a1, b1.x, b1.y); mma16(acc[1][3], a1, b1.z, b1.w);
        mma16(acc[1][4], a1, b2.x, b2.y); mma16(acc[1][5], a1, b2.z, b2.w);
    }
}

__device__ __forceinline__ void stage_B(unsigned* Bs, const float* W, int ldw,
                                        int ncol0, int tid) {
    for (int idx = tid; idx < BS_U4 * 4; idx += 256) {
        int kt = idx / 768;
        int r = idx - kt * 768;
        int jp = r >> 7;
        int r2 = r & 127;
        int ln = r2 >> 2, c = r2 & 3;
        int tig = ln & 3, gid = ln >> 2;
        int n = ncol0 + ((jp << 1) + (c >> 1)) * 8 + gid;
        int k = kt * 16 + 2 * tig + ((c & 1) << 3);
        Bs[idx] = f2h2(__ldg(&W[k * ldw + n]), __ldg(&W[(k + 1) * ldw + n]));
    }
}

// ---------------------------------------------------------------------------
// generic GEMM. TA/TO in {float,__half}; LNF (any TA); GELU; EPI 0/1/2 (res
// is TA-typed for EPI=2); DUAL picks (W,out)/(W2,out2); NCH: n-chunks looped
// inside the block with a single A stage (ncol advances by 96).
// ---------------------------------------------------------------------------
template <class TA, class TO, bool LNF, bool GELU, int EPI, bool DUAL, int NCH>
__global__ __launch_bounds__(256, 3) void gemm_tc(const TA* __restrict__ A,
                                                  const float* __restrict__ W,
                                                  const float* __restrict__ W2,
                                                  const float* __restrict__ bias,
                                                  const float* __restrict__ lng,
                                                  const float* __restrict__ lnb,
                                                  const TA* __restrict__ res,
                                                  TO* __restrict__ out,
                                                  TO* __restrict__ out2, int ldw) {
    constexpr bool TAH = (sizeof(TA) == 2);
    constexpr bool TOH = (sizeof(TO) == 2);
    __shared__ uint4 As4[AS_U4];
    __shared__ uint4 Bs4[BS_U4];
    unsigned* As = (unsigned*)As4;
    unsigned* Bs = (unsigned*)Bs4;
    const int tid = threadIdx.x, lane = tid & 31, warp = tid >> 5;
    const int row0 = blockIdx.x * 128;
    int ncbase = 0;
    if (DUAL) {
        if (blockIdx.y) { W = W2; out = out2; }
    } else if (NCH == 1) {
        ncbase = blockIdx.y * 96;
    }

    stage_B(Bs, W, ldw, ncbase, tid);

    // ---- stage A (2 threads per row, 48 contiguous k each) ----
    {
        const int row = tid >> 1, sub = tid & 1;
        const int mt = row >> 4, r16 = row & 15;
        const int gid8 = r16 & 7, rowhi = r16 >> 3;
        if constexpr (TAH && !LNF) {
            const uint4* ap = (const uint4*)((const __half*)A + (size_t)(row0 + row) * 96 + sub * 48);
#pragma unroll
            for (int j = 0; j < 6; ++j) {
                uint4 u = __ldg(&ap[j]);
                unsigned w[4] = {u.x, u.y, u.z, u.w};
#pragma unroll
                for (int wi = 0; wi < 4; ++wi) {
                    int P = sub * 24 + j * 4 + wi;
                    int kt = P >> 3, hi = (P >> 2) & 1, tg = P & 3;
                    As[(((kt * 8 + mt) * 32) + (gid8 << 2) + tg) * 4 + (rowhi | (hi << 1))] = w[wi];
                }
            }
        } else {
            float4 vals[12];
            if constexpr (TAH) {
                const uint4* ap = (const uint4*)((const __half*)A + (size_t)(row0 + row) * 96 + sub * 48);
#pragma unroll
                for (int j = 0; j < 6; ++j) {
                    uint4 u = __ldg(&ap[j]);
                    __half2* h2 = (__half2*)&u;
                    float2 f0 = __half22float2(h2[0]);
                    float2 f1 = __half22float2(h2[1]);
                    float2 f2v = __half22float2(h2[2]);
                    float2 f3 = __half22float2(h2[3]);
                    vals[2 * j] = make_float4(f0.x, f0.y, f1.x, f1.y);
                    vals[2 * j + 1] = make_float4(f2v.x, f2v.y, f3.x, f3.y);
                }
            } else {
                const float* ap = (const float*)A + (size_t)(row0 + row) * 96 + sub * 48;
#pragma unroll
                for (int j = 0; j < 12; ++j) vals[j] = __ldg((const float4*)(ap + j * 4));
            }
            float mean = 0.f, rstd = 0.f;
            if (LNF) {
                float s = 0.f, s2 = 0.f;
#pragma unroll
                for (int j = 0; j < 12; ++j) {
                    float4 v = vals[j];
                    s += v.x + v.y + v.z + v.w;
                    s2 += v.x * v.x + v.y * v.y + v.z * v.z + v.w * v.w;
                }
                s += __shfl_xor_sync(0xffffffffu, s, 1);
                s2 += __shfl_xor_sync(0xffffffffu, s2, 1);
                mean = s * (1.f / 96.f);
                float var = fmaf(-mean, mean, s2 * (1.f / 96.f));
                rstd = rsqrtf(var + 1e-5f);
            }
#pragma unroll
            for (int j = 0; j < 12; ++j) {
                int k0 = sub * 48 + j * 4;
                float4 v = vals[j];
                if (LNF) {
                    float4 g = __ldg((const float4*)(lng + k0));
                    float4 bb = __ldg((const float4*)(lnb + k0));
                    v.x = (v.x - mean) * rstd * g.x + bb.x;
                    v.y = (v.y - mean) * rstd * g.y + bb.y;
                    v.z = (v.z - mean) * rstd * g.z + bb.z;
                    v.w = (v.w - mean) * rstd * g.w + bb.w;
                }
                int kt = k0 >> 4, kk = k0 & 15;
                int hi = kk >> 3, tig = (kk & 7) >> 1;
                unsigned base = (((kt * 8 + mt) * 32) + (gid8 << 2) + tig) * 4;
                As[base + (rowhi | (hi << 1))] = f2h2(v.x, v.y);
                As[base + 4 + (rowhi | (hi << 1))] = f2h2(v.z, v.w);
            }
        }
    }
    __syncthreads();

    const int mg = warp & 3, nh = warp >> 2;
    const int gid = lane >> 2, tig = lane & 3;
    float acc[2][6][4];

#pragma unroll
    for (int ch = 0; ch < NCH; ++ch) {
        if (ch > 0) {
            __syncthreads();                 // prior gemm_main reads done
            stage_B(Bs, W, ldw, ch * 96, tid);
            __syncthreads();
        }
        gemm_main(acc, As4, Bs4, mg, nh, lane);
        const int ncol0 = (NCH > 1) ? ch * 96 : ncbase;

#pragma unroll
        for (int m = 0; m < 2; ++m) {
            int rr = row0 + (mg * 2 + m) * 16 + gid;
#pragma unroll
            for (int j = 0; j < 6; ++j) {
                int nc = ncol0 + (nh * 6 + j) * 8 + tig * 2;
                float bx = 0.f, by = 0.f;
                if (bias) {
                    float2 bv = *(const float2*)&bias[nc];
                    bx = bv.x; by = bv.y;
                }
                float x0 = acc[m][j][0] + bx, x1 = acc[m][j][1] + by;
                float x2 = acc[m][j][2] + bx, x3 = acc[m][j][3] + by;
                if (GELU) { x0 = gelu_f(x0); x1 = gelu_f(x1); x2 = gelu_f(x2); x3 = gelu_f(x3); }
                if constexpr (TOH) {
                    __half2* p0 = (__half2*)((__half*)out + (size_t)rr * ldw + nc);
                    __half2* p1 = (__half2*)((__half*)out + (size_t)(rr + 8) * ldw + nc);
                    if constexpr (EPI == 1) {
                        float2 o0 = __half22float2(*p0), o1 = __half22float2(*p1);
                        x0 += o0.x; x1 += o0.y; x2 += o1.x; x3 += o1.y;
                    }
                    *p0 = __floats2half2_rn(x0, x1);
                    *p1 = __floats2half2_rn(x2, x3);
                } else {
                    float* p0 = (float*)out + (size_t)rr * ldw + nc;
                    float* p1 = (float*)out + (size_t)(rr + 8) * ldw + nc;
                    if constexpr (EPI == 0) {
                        *(float2*)p0 = make_float2(x0, x1);
                        *(float2*)p1 = make_float2(x2, x3);
                    } else if constexpr (EPI == 1) {
                        float2 o0 = *(float2*)p0, o1 = *(float2*)p1;
                        *(float2*)p0 = make_float2(o0.x + x0, o0.y + x1);
                        *(float2*)p1 = make_float2(o1.x + x2, o1.y + x3);
                    } else {
                        float r0x, r0y, r1x, r1y;
                        if constexpr (TAH) {
                            float2 r0 = __half22float2(*(const __half2*)((const __half*)res + (size_t)rr * 96 + nc));
                            float2 r1 = __half22float2(*(const __half2*)((const __half*)res + (size_t)(rr + 8) * 96 + nc));
                            r0x = r0.x; r0y = r0.y; r1x = r1.x; r1y = r1.y;
                        } else {
                            float2 r0 = *(const float2*)((const float*)res + (size_t)rr * 96 + nc);
                            float2 r1 = *(const float2*)((const float*)res + (size_t)(rr + 8) * 96 + nc);
                            r0x = r0.x; r0y = r0.y; r1x = r1.x; r1y = r1.y;
                        }
                        *(float2*)p0 = make_float2(r0x + x0, r0y + x1);
                        *(float2*)p1 = make_float2(r1x + x2, r1y + x3);
                    }
                }
            }
        }
    }
}

// ---------------------------------------------------------------------------
// patch merge (fp32 image in, fp16 residual out), fp16 MMA, K chunks of 96
// ---------------------------------------------------------------------------
template <int DF, int KTOT, int WOUT>
__global__ __launch_bounds__(256, 3) void patch_tc(const float* __restrict__ x,
                                                   const float* __restrict__ w,
                                                   const float* __restrict__ bias,
                                                   __half* __restrict__ out) {
    constexpr int KPAD = (KTOT + 15) & ~15;
    __shared__ uint4 As4[AS_U4];
    __shared__ uint4 Bs4[BS_U4];
    unsigned* As = (unsigned*)As4;
    unsigned* Bs = (unsigned*)Bs4;
    const int tid = threadIdx.x, lane = tid & 31, warp = tid >> 5;
    const int row0 = blockIdx.x * 128;
    const int T = WOUT * WOUT;
    const int mg = warp & 3, nh = warp >> 2;

    float acc[2][6][4];
#pragma unroll
    for (int m = 0; m < 2; ++m)
#pragma unroll
        for (int j = 0; j < 6; ++j)
#pragma unroll
            for (int i = 0; i < 4; ++i) acc[m][j][i] = 0.f;

    for (int kc = 0; kc < KPAD; kc += 96) {
        const int cl = (KPAD - kc) < 96 ? (KPAD - kc) : 96;
        const int nkt = cl >> 4;

        for (int idx = tid; idx < nkt * 768; idx += 256) {
            int kt = idx / 768;
            int r = idx - kt * 768;
            int jp = r >> 7;
            int r2 = r & 127;
            int ln = r2 >> 2, c = r2 & 3;
            int tig = ln & 3, gid = ln >> 2;
            int n = ((jp << 1) + (c >> 1)) * 8 + gid;
            int k = kc + kt * 16 + 2 * tig + ((c & 1) << 3);
            float lo = (k < KTOT) ? __ldg(&w[k * 96 + n]) : 0.f;
            float hi = (k + 1 < KTOT) ? __ldg(&w[(k + 1) * 96 + n]) : 0.f;
            Bs[idx] = f2h2(lo, hi);
        }
        {
            const int row = tid >> 1, sub = tid & 1;
            const int tok = row0 + row;
            const int b = tok / T, hw = tok - b * T;
            const int h = hw / WOUT, ww = hw - h * WOUT;
            const int mt = row >> 4, r16 = row & 15;
            const int gid8 = r16 & 7, rowhi = r16 >> 3;
#pragma unroll
            for (int j = 0; j < 12; ++j) {
                int k0 = sub * 48 + j * 4;
                if (k0 >= cl) break;
                float v[4];
#pragma unroll
                for (int e = 0; e < 4; ++e) {
                    int f = kc + k0 + e;
                    float vv = 0.f;
                    if (f < KTOT) {
                        int c2 = f / (DF * DF), rem = f - c2 * DF * DF;
                        int ki = rem / DF, kj = rem - ki * DF;
                        vv = __ldg(&x[((b * 3 + c2) * 224 + h * DF + ki) * 224 + ww * DF + kj]);
                    }
                    v[e] = vv;
                }
                int kt = k0 >> 4, kk = k0 & 15;
                int hi = kk >> 3, tig = (kk & 7) >> 1;
                unsigned base = (((kt * 8 + mt) * 32) + (gid8 << 2) + tig) * 4;
                As[base + (rowhi | (hi << 1))] = f2h2(v[0], v[1]);
                As[base + 4 + (rowhi | (hi << 1))] = f2h2(v[2], v[3]);
            }
        }
        __syncthreads();

        for (int kt = 0; kt < nkt; ++kt) {
            uint4 a0 = As4[(kt * 8 + mg * 2) * 32 + lane];
            uint4 a1 = As4[(kt * 8 + mg * 2 + 1) * 32 + lane];
            uint4 b0 = Bs4[(kt * 6 + nh * 3) * 32 + lane];
            uint4 b1 = Bs4[(kt * 6 + nh * 3 + 1) * 32 + lane];
            uint4 b2 = Bs4[(kt * 6 + nh * 3 + 2) * 32 + lane];
            mma16(acc[0][0], a0, b0.x, b0.y); mma16(acc[0][1], a0, b0.z, b0.w);
            mma16(acc[0][2], a0, b1.x, b1.y); mma16(acc[0][3], a0, b1.z, b1.w);
            mma16(acc[0][4], a0, b2.x, b2.y); mma16(acc[0][5], a0, b2.z, b2.w);
            mma16(acc[1][0], a1, b0.x, b0.y); mma16(acc[1][1], a1, b0.z, b0.w);
            mma16(acc[1][2], a1, b1.x, b1.y); mma16(acc[1][3], a1, b1.z, b1.w);
            mma16(acc[1][4], a1, b2.x, b2.y); mma16(acc[1][5], a1, b2.z, b2.w);
        }
        __syncthreads();
    }

    const int gid = lane >> 2, tig = lane & 3;
#pragma unroll
    for (int m = 0; m < 2; ++m) {
        int rr = row0 + (mg * 2 + m) * 16 + gid;
#pragma unroll
        for (int j = 0; j < 6; ++j) {
            int nc = (nh * 6 + j) * 8 + tig * 2;
            float2 bv = *(const float2*)&bias[nc];
            *(__half2*)&out[(size_t)rr * 96 + nc] =
                __floats2half2_rn(acc[m][j][0] + bv.x, acc[m][j][1] + bv.y);
            *(__half2*)&out[(size_t)(rr + 8) * 96 + nc] =
                __floats2half2_rn(acc[m][j][2] + bv.x, acc[m][j][3] + bv.y);
        }
    }
}

// ---------------------------------------------------------------------------
// window attention: 3 heads parallel, vectorized uint4 loads
// ---------------------------------------------------------------------------
template <int WS>
__global__ __launch_bounds__(128) void win_attn_k(const __half* __restrict__ qkv,
                                                  __half* __restrict__ o,
                                                  int Wout, int nw) {
    constexpr int NT = WS * WS;
    extern __shared__ float wsm[];
    float* sq = wsm;
    float* sk = sq + 3 * NT * 33;
    float* sv = sk + 3 * NT * 33;
    float* sS = sv + 3 * NT * 33;
    const int b = blockIdx.x / (nw * nw);
    const int win = blockIdx.x % (nw * nw);
    const int wr = win / nw, wc = win % nw;
    const int t = threadIdx.x;
    const int T = Wout * Wout;
    const float scale = 0.17677669529663687f;

    for (int idx = t; idx < NT * 36; idx += 128) {
        int p = idx / 36, u = idx - p * 36;
        int wi = p / WS, wj = p - wi * WS;
        int r = b * T + (wr * WS + wi) * Wout + wc * WS + wj;
        uint4 val = __ldg((const uint4*)(qkv + (size_t)r * 288) + u);
        int sec = u / 12, uu = u - sec * 12;
        int head = uu >> 2, c0 = (uu & 3) * 8;
        float* dst = (sec == 0 ? sq : sec == 1 ? sk : sv) + (head * NT + p) * 33 + c0;
        __half2* h2 = (__half2*)&val;
#pragma unroll
        for (int e = 0; e < 4; ++e) {
            float2 f = __half22float2(h2[e]);
            dst[2 * e] = f.x;
            dst[2 * e + 1] = f.y;
        }
    }
    __syncthreads();

    for (int idx = t; idx < 3 * NT * NT; idx += 128) {
        int h = idx / (NT * NT);
        int ij = idx - h * NT * NT;
        int i = ij / NT, j = ij - i * NT;
        const float* qi = sq + (h * NT + i) * 33;
        const float* kj = sk + (h * NT + j) * 33;
        float s = 0.f;
#pragma unroll
        for (int c = 0; c < 32; ++c) s = fmaf(qi[c], kj[c], s);
        sS[idx] = s * scale;
    }
    __syncthreads();

    for (int row = t; row < 3 * NT; row += 128) {
        float* p = sS + row * NT;
        float m = -1e30f;
        for (int j = 0; j < NT; ++j) m = fmaxf(m, p[j]);
        float Z = 0.f;
        for (int j = 0; j < NT; ++j) {
            float e = __expf(p[j] - m);
            p[j] = e;
            Z += e;
        }
        float inv = 1.f / Z;
        for (int j = 0; j < NT; ++j) p[j] *= inv;
    }
    __syncthreads();

    for (int idx = t; idx < 3 * NT * 32; idx += 128) {
        int h = idx / (NT * 32);
        int rest = idx - h * NT * 32;
        int i = rest >> 5, c = rest & 31;
        const float* pw = sS + (h * NT + i) * NT;
        const float* vb = sv + h * NT * 33 + c;
        float acc = 0.f;
        for (int j = 0; j < NT; ++j) acc = fmaf(pw[j], vb[j * 33], acc);
        int wi = i / WS, wj = i - wi * WS;
        int r = b * T + (wr * WS + wi) * Wout + wc * WS + wj;
        o[(size_t)r * 96 + h * 32 + c] = __float2half(acc);
    }
}

// ---------------------------------------------------------------------------
// neighbor gather + LN (fp16 residual inputs), warp-per-row LN
// ---------------------------------------------------------------------------
__global__ __launch_bounds__(256) void gather_ln_k(const __half* __restrict__ t1,
                                                   const __half* __restrict__ t2,
                                                   const float* __restrict__ g,
                                                   const float* __restrict__ bb,
                                                   __half* __restrict__ kv) {
    const int bl = blockIdx.x;
    const int b = bl / 196, l = bl % 196;
    const int i1 = l / 14, j1 = l % 14;
    __shared__ float s1[16 * 100];
    __shared__ float s2[9 * 100];
    const int tid = threadIdx.x, warp = tid >> 5, lane = tid & 31;

    // 16 rows of scale-1 4x4 patch: 12 uint4 (96 halves) per row
    for (int idx = tid; idx < 16 * 12; idx += 256) {
        int p = idx / 12, q = idx - p * 12;
        int ki = p >> 2, kj = p & 3;
        uint4 u = __ldg((const uint4*)(t1 +
            (size_t)((b * 56 + i1 * 4 + ki) * 56 + j1 * 4 + kj) * 96) + q);
        __half2* h2 = (__half2*)&u;
        float* dst = &s1[p * 100 + q * 8];
#pragma unroll
        for (int e = 0; e < 4; ++e) {
            float2 f = __half22float2(h2[e]);
            dst[2 * e] = f.x;
            dst[2 * e + 1] = f.y;
        }
    }
    // 9 rows of scale-2 padded 3x3 patch
    for (int idx = tid; idx < 9 * 12; idx += 256) {
        int p = idx / 12, q = idx - p * 12;
        int ki = p / 3, kj = p - ki * 3;
        int rr = i1 * 3 + ki - 5, cc = j1 * 3 + kj - 5;
        float* dst = &s2[p * 100 + q * 8];
        if (rr >= 0 && rr < 32 && cc >= 0 && cc < 32) {
            uint4 u = __ldg((const uint4*)(t2 + (size_t)((b * 32 + rr) * 32 + cc) * 96) + q);
            __half2* h2 = (__half2*)&u;
#pragma unroll
            for (int e = 0; e < 4; ++e) {
                float2 f = __half22float2(h2[e]);
                dst[2 * e] = f.x;
                dst[2 * e + 1] = f.y;
            }
        } else {
#pragma unroll
            for (int e = 0; e < 8; ++e) dst[e] = 0.f;
        }
    }
    __syncthreads();

    float gv[3], bv[3];
#pragma unroll
    for (int i = 0; i < 3; ++i) {
        gv[i] = __ldg(&g[lane + 32 * i]);
        bv[i] = __ldg(&bb[lane + 32 * i]);
    }

    for (int k = warp; k < 25; k += 8) {
        float v[3];
#pragma unroll
        for (int i = 0; i < 3; ++i) {
            int c = lane + 32 * i;
            if (k < 16) {
                int F = k * 96 + c;
                v[i] = s1[(F & 15) * 100 + (F >> 4)];
            } else {
                int F = (k - 16) * 96 + c;
                v[i] = s2[(F % 9) * 100 + (F / 9)];
            }
        }
        float s = v[0] + v[1] + v[2];
        float q = v[0] * v[0] + v[1] * v[1] + v[2] * v[2];
#pragma unroll
        for (int off = 16; off > 0; off >>= 1) {
            s += __shfl_xor_sync(0xffffffffu, s, off);
            q += __shfl_xor_sync(0xffffffffu, q, off);
        }
        float mean = s * (1.f / 96.f);
        float var = fmaf(-mean, mean, q * (1.f / 96.f));
        float rstd = rsqrtf(var + 1e-5f);
        __half* dst = kv + ((size_t)bl * 25 + k) * 96;
#pragma unroll
        for (int i = 0; i < 3; ++i)
            dst[lane + 32 * i] = __float2half((v[i] - mean) * rstd * gv[i] + bv[i]);
    }
}

// ---------------------------------------------------------------------------
// cross attention: contiguous 25x96 K/V staged via uint4
// ---------------------------------------------------------------------------
__global__ __launch_bounds__(128) void cross_attn_k(const __half* __restrict__ q,
                                                    const __half* __restrict__ kbuf,
                                                    const __half* __restrict__ vbuf,
                                                    __half* __restrict__ o) {
    const int rl = blockIdx.x;
    __shared__ __half hk[2400], hv[2400];
    __shared__ float sqf[96], ss[25];
    const int t = threadIdx.x;

    const uint4* ksrc = (const uint4*)(kbuf + (size_t)rl * 2400);
    const uint4* vsrc = (const uint4*)(vbuf + (size_t)rl * 2400);
    for (int idx = t; idx < 300; idx += 128) {
        ((uint4*)hk)[idx] = __ldg(ksrc + idx);
        ((uint4*)hv)[idx] = __ldg(vsrc + idx);
    }
    if (t < 96) sqf[t] = __half2float(__ldg(q + (size_t)rl * 96 + t));
    __syncthreads();

    if (t < 25) {
        const __half* kr = hk + t * 96;
        float s = 0.f;
#pragma unroll 8
        for (int c = 0; c < 96; ++c) s = fmaf(sqf[c], __half2float(kr[c]), s);
        ss[t] = s * 0.10206207261596575f;
    }
    __syncthreads();

    if (t < 96) {
        float m = -1e30f;
#pragma unroll
        for (int k = 0; k < 25; ++k) m = fmaxf(m, ss[k]);
        float Z = 0.f, acc = 0.f;
#pragma unroll
        for (int k = 0; k < 25; ++k) {
            float e = __expf(ss[k] - m);
            Z += e;
            acc = fmaf(e, __half2float(hv[k * 96 + t]), acc);
        }
        o[(size_t)rl * 96 + t] = __float2half(acc / Z);
    }
}

// ---------------------------------------------------------------------------
extern "C" void kernel_launch(void* const* d_in, const int* in_sizes, int n_in,
                              void* d_out, int out_size) {
    const float* x       = (const float*)d_in[0];
    const float* pw[3]   = {(const float*)d_in[1], (const float*)d_in[3], (const float*)d_in[5]};
    const float* pb[3]   = {(const float*)d_in[2], (const float*)d_in[4], (const float*)d_in[6]};
    const float* wa_ln_g = (const float*)d_in[7];
    const float* wa_ln_b = (const float*)d_in[8];
    const float* wa_qkv  = (const float*)d_in[9];
    const float* wa_ow   = (const float*)d_in[10];
    const float* wa_ob   = (const float*)d_in[11];
    const float* ff_ln_g = (const float*)d_in[12];
    const float* ff_ln_b = (const float*)d_in[13];
    const float* ff_w1   = (const float*)d_in[14];
    const float* ff_b1   = (const float*)d_in[15];
    const float* ff_w2   = (const float*)d_in[16];
    const float* ff_b2   = (const float*)d_in[17];
    const float* lnn_g   = (const float*)d_in[18];
    const float* lnn_b   = (const float*)d_in[19];
    const float* ca_wq   = (const float*)d_in[20];
    const float* ca_wk   = (const float*)d_in[21];
    const float* ca_wv   = (const float*)d_in[22];
    const float* ca_wo   = (const float*)d_in[23];
    const float* ca_bo   = (const float*)d_in[24];
    const float* fi_ln_g = (const float*)d_in[25];
    const float* fi_ln_b = (const float*)d_in[26];
    const float* fi_w1   = (const float*)d_in[27];
    const float* fi_b1   = (const float*)d_in[28];
    const float* fi_w2   = (const float*)d_in[29];
    const float* fi_b2   = (const float*)d_in[30];
    float* out = (float*)d_out;

    __half *t0, *t1, *t2, *qkv, *ob, *kv, *kk, *vv, *qq, *co;
    cudaGetSymbolAddress((void**)&t0, g_t0);
    cudaGetSymbolAddress((void**)&t1, g_t1);
    cudaGetSymbolAddress((void**)&t2, g_t2);
    cudaGetSymbolAddress((void**)&qkv, g_qkv);
    cudaGetSymbolAddress((void**)&ob, g_ob);
    cudaGetSymbolAddress((void**)&kv, g_kv);
    cudaGetSymbolAddress((void**)&kk, g_k);
    cudaGetSymbolAddress((void**)&vv, g_v);
    cudaGetSymbolAddress((void**)&qq, g_q);
    cudaGetSymbolAddress((void**)&co, g_co);

    const int WSM7 = (3 * 49 * 33 * 3 + 3 * 49 * 49) * 4;
    const int WSM4 = (3 * 16 * 33 * 3 + 3 * 16 * 16) * 4;
    cudaFuncSetAttribute(win_attn_k<7>, cudaFuncAttributeMaxDynamicSharedMemorySize, WSM7);
    cudaFuncSetAttribute(win_attn_k<4>, cudaFuncAttributeMaxDynamicSharedMemorySize, WSM4);

    // patch merges -> fp16 residual streams
    patch_tc<16, 768, 14><<<ROWS0 / 128, 256>>>(x, pw[0], pb[0], t0);
    patch_tc<4, 48, 56><<<ROWS1 / 128, 256>>>(x, pw[1], pb[1], t1);
    patch_tc<7, 147, 32><<<ROWS2 / 128, 256>>>(x, pw[2], pb[2], t2);

    const int rows[3] = {ROWS0, ROWS1, ROWS2};
    __half* tb[3] = {t0, t1, t2};
    for (int i = 0; i < 3; ++i) {
        const int R = rows[i];
        __half* t = tb[i];
        // qkv(fp16) = LN(t) @ Wqkv — single A stage, 3 chunks in-block
        gemm_tc<__half, __half, true, false, 0, false, 3><<<R / 128, 256>>>(
            t, wa_qkv + i * 96 * 288, nullptr, nullptr,
            wa_ln_g + i * 96, wa_ln_b + i * 96, nullptr, qkv, nullptr, 288);
        if (i == 0)      win_attn_k<7><<<64 * 2 * 2, 128, WSM7>>>(qkv, ob, 14, 2);
        else if (i == 1) win_attn_k<4><<<64 * 14 * 14, 128, WSM4>>>(qkv, ob, 56, 14);
        else             win_attn_k<4><<<64 * 8 * 8, 128, WSM4>>>(qkv, ob, 32, 8);
        // t(fp16) += ob @ Wo + bo
        gemm_tc<__half, __half, false, false, 1, false, 1><<<R / 128, 256>>>(
            ob, wa_ow + i * 9216, nullptr, wa_ob + i * 96,
            nullptr, nullptr, nullptr, t, nullptr, 96);
        // h(fp16) = gelu(LN(t) @ W1 + b1)
        gemm_tc<__half, __half, true, true, 0, false, 1><<<R / 128, 256>>>(
            t, ff_w1 + i * 9216, nullptr, ff_b1 + i * 96,
            ff_ln_g + i * 96, ff_ln_b + i * 96, nullptr, ob, nullptr, 96);
        // t(fp16) += h @ W2 + b2
        gemm_tc<__half, __half, false, false, 1, false, 1><<<R / 128, 256>>>(
            ob, ff_w2 + i * 9216, nullptr, ff_b2 + i * 96,
            nullptr, nullptr, nullptr, t, nullptr, 96);
    }

    // neighbor gather + LN -> kv(fp16)
    gather_ln_k<<<64 * 196, 256>>>(t1, t2, lnn_g, lnn_b, kv);
    // k/v projections (dual launch)
    gemm_tc<__half, __half, false, false, 0, true, 1><<<dim3(KVROWS / 128, 2), 256>>>(
        kv, ca_wk, ca_wv, nullptr, nullptr, nullptr, nullptr, kk, vv, 96);
    // q(fp16) = LN(t0) @ Wq
    gemm_tc<__half, __half, true, false, 0, false, 1><<<ROWS0 / 128, 256>>>(
        t0, ca_wq, nullptr, nullptr, lnn_g, lnn_b, nullptr, qq, nullptr, 96);
    // cross attention
    cross_attn_k<<<12544, 128>>>(qq, kk, vv, co);
    // out(fp32) = t0(fp16) + co @ Wo + bo
    gemm_tc<__half, float, false, false, 2, false, 1><<<ROWS0 / 128, 256>>>(
        co, ca_wo, nullptr, ca_bo, nullptr, nullptr, t0, out, nullptr, 96);
    // out += gelu(LN(out) @ w1 + b1) @ w2 + b2  (fp32 out path)
    gemm_tc<float, __half, true, true, 0, false, 1><<<ROWS0 / 128, 256>>>(
        out, fi_w1, nullptr, fi_b1, fi_ln_g, fi_ln_b, nullptr, ob, nullptr, 96);
    gemm_tc<__half, float, false, false, 1, false, 1><<<ROWS0 / 128, 256>>>(
        ob, fi_w2, nullptr, fi_b2, nullptr, nullptr, nullptr, out, nullptr, 96);
}

// round 10
// speedup vs baseline: 1.0876x; 1.0876x over previous
#include <cuda_runtime.h>
#include <cuda_fp16.h>
#include <math.h>

// ---------------------------------------------------------------------------
// MultiScaleCrossAttn — fp16 MMA GEMMs, scale-merged launches, fused tail
// ---------------------------------------------------------------------------

#define ROWS0 12544      // 64*14*14
#define ROWS1 200704     // 64*56*56
#define ROWS2 65536      // 64*32*32
#define RTOT  278784     // ROWS0+ROWS1+ROWS2
#define KVROWS 313600    // 64*196*25

// block boundaries in the concatenated 128-row-block space
#define BLK0 98          // ROWS0/128
#define BLK01 1666       // (ROWS0+ROWS1)/128

__device__ __align__(16) __half g_t[RTOT * 96];
__device__ __align__(16) __half g_qkv[RTOT * 288];
__device__ __align__(16) __half g_ob[RTOT * 96];
__device__ __align__(16) __half g_kv[KVROWS * 96];
__device__ __align__(16) __half g_k[KVROWS * 96];
__device__ __align__(16) __half g_v[KVROWS * 96];
__device__ __align__(16) __half g_q[ROWS0 * 96];
__device__ __align__(16) __half g_co[ROWS0 * 96];

static constexpr int AS_U4 = 6 * 8 * 32;   // 24KB
static constexpr int BS_U4 = 6 * 6 * 32;   // 18KB
static constexpr int TF_LD = 100;
static constexpr int RES_SMEM = 128 * TF_LD * 4 + AS_U4 * 16 + BS_U4 * 16;  // 94208

__device__ __forceinline__ unsigned f2h2(float lo, float hi) {
    __half2 h = __floats2half2_rn(lo, hi);
    return *reinterpret_cast<unsigned*>(&h);
}

__device__ __forceinline__ void mma16(float c[4], uint4 a, unsigned b0, unsigned b1) {
    asm volatile(
        "mma.sync.aligned.m16n8k16.row.col.f32.f16.f16.f32 "
        "{%0,%1,%2,%3}, {%4,%5,%6,%7}, {%8,%9}, {%0,%1,%2,%3};\n"
        : "+f"(c[0]), "+f"(c[1]), "+f"(c[2]), "+f"(c[3])
        : "r"(a.x), "r"(a.y), "r"(a.z), "r"(a.w), "r"(b0), "r"(b1));
}

__device__ __forceinline__ float gelu_f(float v) {
    return 0.5f * v * (1.f + erff(v * 0.70710678118654752f));
}

__device__ __forceinline__ void gemm_main(float acc[2][6][4], const uint4* As4,
                                          const uint4* Bs4, int mg, int nh, int lane) {
#pragma unroll
    for (int m = 0; m < 2; ++m)
#pragma unroll
        for (int j = 0; j < 6; ++j)
#pragma unroll
            for (int i = 0; i < 4; ++i) acc[m][j][i] = 0.f;
#pragma unroll
    for (int kt = 0; kt < 6; ++kt) {
        uint4 a0 = As4[(kt * 8 + mg * 2) * 32 + lane];
        uint4 a1 = As4[(kt * 8 + mg * 2 + 1) * 32 + lane];
        uint4 b0 = Bs4[(kt * 6 + nh * 3) * 32 + lane];
        uint4 b1 = Bs4[(kt * 6 + nh * 3 + 1) * 32 + lane];
        uint4 b2 = Bs4[(kt * 6 + nh * 3 + 2) * 32 + lane];
        mma16(acc[0][0], a0, b0.x, b0.y); mma16(acc[0][1], a0, b0.z, b0.w);
        mma16(acc[0][2], a0, b1.x, b1.y); mma16(acc[0][3], a0, b1.z, b1.w);
        mma16(acc[0][4], a0, b2.x, b2.y); mma16(acc[0][5], a0, b2.z, b2.w);
        mma16(acc[1][0], a1, b0.x, b0.y); mma16(acc[1][1], a1, b0.z, b0.w);
        mma16(acc[1][2], a1, b1.x, b1.y); mma16(acc[1][3], a1, b1.z, b1.w);
        mma16(acc[1][4], a1, b2.x, b2.y); mma16(acc[1][5], a1, b2.z, b2.w);
    }
}

__device__ __forceinline__ void stage_B(unsigned* Bs, const float* W, int ldw,
                                        int ncol0, int tid) {
    for (int idx = tid; idx < BS_U4 * 4; idx += 256) {
        int kt = idx / 768;
        int r = idx - kt * 768;
        int jp = r >> 7;
        int r2 = r & 127;
        int ln = r2 >> 2, c = r2 & 3;
        int tig = ln & 3, gid = ln >> 2;
        int n = ncol0 + ((jp << 1) + (c >> 1)) * 8 + gid;
        int k = kt * 16 + 2 * tig + ((c & 1) << 3);
        Bs[idx] = f2h2(__ldg(&W[k * ldw + n]), __ldg(&W[(k + 1) * ldw + n]));
    }
}

// stage fp16 A rows (no LN): pure repack, 2 threads/row
__device__ __forceinline__ void stage_A_half(unsigned* As, const __half* A,
                                             int row0, int tid) {
    const int row = tid >> 1, sub = tid & 1;
    const int mt = row >> 4, r16 = row & 15;
    const int gid8 = r16 & 7, rowhi = r16 >> 3;
    const uint4* ap = (const uint4*)(A + (size_t)(row0 + row) * 96 + sub * 48);
#pragma unroll
    for (int j = 0; j < 6; ++j) {
        uint4 u = __ldg(&ap[j]);
        unsigned w[4] = {u.x, u.y, u.z, u.w};
#pragma unroll
        for (int wi = 0; wi < 4; ++wi) {
            int P = sub * 24 + j * 4 + wi;
            int kt = P >> 3, hi = (P >> 2) & 1, tg = P & 3;
            As[(((kt * 8 + mt) * 32) + (gid8 << 2) + tg) * 4 + (rowhi | (hi << 1))] = w[wi];
        }
    }
}

// ---------------------------------------------------------------------------
// generic GEMM. TA/TO in {float,__half}; LNF; GELU; EPI 0/1/2; DUAL; NCH
// chunks; MULTI: blockIdx.x spans concatenated scales, W/bias/LN offset by
// scale (stride 96*ldw / 96).
// ---------------------------------------------------------------------------
template <class TA, class TO, bool LNF, bool GELU, int EPI, bool DUAL, int NCH, bool MULTI>
__global__ __launch_bounds__(256, 3) void gemm_tc(const TA* __restrict__ A,
                                                  const float* __restrict__ W,
                                                  const float* __restrict__ W2,
                                                  const float* __restrict__ bias,
                                                  const float* __restrict__ lng,
                                                  const float* __restrict__ lnb,
                                                  const TA* __restrict__ res,
                                                  TO* __restrict__ out,
                                                  TO* __restrict__ out2, int ldw) {
    constexpr bool TAH = (sizeof(TA) == 2);
    constexpr bool TOH = (sizeof(TO) == 2);
    __shared__ uint4 As4[AS_U4];
    __shared__ uint4 Bs4[BS_U4];
    unsigned* As = (unsigned*)As4;
    unsigned* Bs = (unsigned*)Bs4;
    const int tid = threadIdx.x, lane = tid & 31, warp = tid >> 5;
    const int row0 = blockIdx.x * 128;
    int ncbase = 0;
    if (MULTI) {
        int s = (blockIdx.x < BLK0) ? 0 : (blockIdx.x < BLK01) ? 1 : 2;
        W += (size_t)s * 96 * ldw;
        if (bias) bias += s * 96;
        if (LNF) { lng += s * 96; lnb += s * 96; }
    } else if (DUAL) {
        if (blockIdx.y) { W = W2; out = out2; }
    } else if (NCH == 1) {
        ncbase = blockIdx.y * 96;
    }

    stage_B(Bs, W, ldw, ncbase, tid);

    // ---- stage A ----
    if constexpr (TAH && !LNF) {
        stage_A_half(As, (const __half*)A, row0, tid);
    } else {
        const int row = tid >> 1, sub = tid & 1;
        const int mt = row >> 4, r16 = row & 15;
        const int gid8 = r16 & 7, rowhi = r16 >> 3;
        float4 vals[12];
        if constexpr (TAH) {
            const uint4* ap = (const uint4*)((const __half*)A + (size_t)(row0 + row) * 96 + sub * 48);
#pragma unroll
            for (int j = 0; j < 6; ++j) {
                uint4 u = __ldg(&ap[j]);
                __half2* h2 = (__half2*)&u;
                float2 f0 = __half22float2(h2[0]);
                float2 f1 = __half22float2(h2[1]);
                float2 f2v = __half22float2(h2[2]);
                float2 f3 = __half22float2(h2[3]);
                vals[2 * j] = make_float4(f0.x, f0.y, f1.x, f1.y);
                vals[2 * j + 1] = make_float4(f2v.x, f2v.y, f3.x, f3.y);
            }
        } else {
            const float* ap = (const float*)A + (size_t)(row0 + row) * 96 + sub * 48;
#pragma unroll
            for (int j = 0; j < 12; ++j) vals[j] = __ldg((const float4*)(ap + j * 4));
        }
        float mean = 0.f, rstd = 0.f;
        if (LNF) {
            float s = 0.f, s2 = 0.f;
#pragma unroll
            for (int j = 0; j < 12; ++j) {
                float4 v = vals[j];
                s += v.x + v.y + v.z + v.w;
                s2 += v.x * v.x + v.y * v.y + v.z * v.z + v.w * v.w;
            }
            s += __shfl_xor_sync(0xffffffffu, s, 1);
            s2 += __shfl_xor_sync(0xffffffffu, s2, 1);
            mean = s * (1.f / 96.f);
            float var = fmaf(-mean, mean, s2 * (1.f / 96.f));
            rstd = rsqrtf(var + 1e-5f);
        }
#pragma unroll
        for (int j = 0; j < 12; ++j) {
            int k0 = sub * 48 + j * 4;
            float4 v = vals[j];
            if (LNF) {
                float4 g = __ldg((const float4*)(lng + k0));
                float4 bb = __ldg((const float4*)(lnb + k0));
                v.x = (v.x - mean) * rstd * g.x + bb.x;
                v.y = (v.y - mean) * rstd * g.y + bb.y;
                v.z = (v.z - mean) * rstd * g.z + bb.z;
                v.w = (v.w - mean) * rstd * g.w + bb.w;
            }
            int kt = k0 >> 4, kk = k0 & 15;
            int hi = kk >> 3, tig = (kk & 7) >> 1;
            unsigned base = (((kt * 8 + mt) * 32) + (gid8 << 2) + tig) * 4;
            As[base + (rowhi | (hi << 1))] = f2h2(v.x, v.y);
            As[base + 4 + (rowhi | (hi << 1))] = f2h2(v.z, v.w);
        }
    }
    __syncthreads();

    const int mg = warp & 3, nh = warp >> 2;
    const int gid = lane >> 2, tig = lane & 3;
    float acc[2][6][4];

#pragma unroll
    for (int ch = 0; ch < NCH; ++ch) {
        if (ch > 0) {
            __syncthreads();
            int s = 0;
            if (MULTI) s = 0;  // W already offset
            (void)s;
            stage_B(Bs, W, ldw, ch * 96, tid);
            __syncthreads();
        }
        gemm_main(acc, As4, Bs4, mg, nh, lane);
        const int ncol0 = (NCH > 1) ? ch * 96 : ncbase;

#pragma unroll
        for (int m = 0; m < 2; ++m) {
            int rr = row0 + (mg * 2 + m) * 16 + gid;
#pragma unroll
            for (int j = 0; j < 6; ++j) {
                int nc = ncol0 + (nh * 6 + j) * 8 + tig * 2;
                float bx = 0.f, by = 0.f;
                if (bias) {
                    float2 bv = *(const float2*)&bias[nc];
                    bx = bv.x; by = bv.y;
                }
                float x0 = acc[m][j][0] + bx, x1 = acc[m][j][1] + by;
                float x2 = acc[m][j][2] + bx, x3 = acc[m][j][3] + by;
                if (GELU) { x0 = gelu_f(x0); x1 = gelu_f(x1); x2 = gelu_f(x2); x3 = gelu_f(x3); }
                if constexpr (TOH) {
                    __half2* p0 = (__half2*)((__half*)out + (size_t)rr * ldw + nc);
                    __half2* p1 = (__half2*)((__half*)out + (size_t)(rr + 8) * ldw + nc);
                    if constexpr (EPI == 1) {
                        float2 o0 = __half22float2(*p0), o1 = __half22float2(*p1);
                        x0 += o0.x; x1 += o0.y; x2 += o1.x; x3 += o1.y;
                    }
                    *p0 = __floats2half2_rn(x0, x1);
                    *p1 = __floats2half2_rn(x2, x3);
                } else {
                    float* p0 = (float*)out + (size_t)rr * ldw + nc;
                    float* p1 = (float*)out + (size_t)(rr + 8) * ldw + nc;
                    if constexpr (EPI == 0) {
                        *(float2*)p0 = make_float2(x0, x1);
                        *(float2*)p1 = make_float2(x2, x3);
                    } else if constexpr (EPI == 1) {
                        float2 o0 = *(float2*)p0, o1 = *(float2*)p1;
                        *(float2*)p0 = make_float2(o0.x + x0, o0.y + x1);
                        *(float2*)p1 = make_float2(o1.x + x2, o1.y + x3);
                    } else {
                        float2 r0 = __half22float2(*(const __half2*)((const __half*)res + (size_t)rr * 96 + nc));
                        float2 r1 = __half22float2(*(const __half2*)((const __half*)res + (size_t)(rr + 8) * 96 + nc));
                        *(float2*)p0 = make_float2(r0.x + x0, r0.y + x1);
                        *(float2*)p1 = make_float2(r1.x + x2, r1.y + x3);
                    }
                }
            }
        }
    }
}

// ---------------------------------------------------------------------------
// FUSED TAIL: out = t0 + co@Wo + bo; out += gelu(LN(out)@W1+b1)@W2 + b2
// co/t0 fp16, out fp32. 98 blocks, latency-bound -> fusion wins here.
// ---------------------------------------------------------------------------
__global__ __launch_bounds__(256) void resff_final(const __half* __restrict__ co,
                                                   const __half* __restrict__ t0,
                                                   float* __restrict__ out,
                                                   const float* __restrict__ Wo,
                                                   const float* __restrict__ bo,
                                                   const float* __restrict__ lng,
                                                   const float* __restrict__ lnb,
                                                   const float* __restrict__ W1,
                                                   const float* __restrict__ b1,
                                                   const float* __restrict__ W2,
                                                   const float* __restrict__ b2) {
    extern __shared__ float dyn[];
    float* Tf = dyn;                                   // [128][TF_LD]
    unsigned* As = (unsigned*)(dyn + 128 * TF_LD);
    unsigned* Bs = As + AS_U4 * 4;
    uint4* As4 = (uint4*)As;
    uint4* Bs4 = (uint4*)Bs;
    const int tid = threadIdx.x, lane = tid & 31, warp = tid >> 5;
    const int row0 = blockIdx.x * 128;
    const int mg = warp & 3, nh = warp >> 2;
    const int gid = lane >> 2, tig = lane & 3;
    float acc[2][6][4];

    // phase 1: co @ Wo
    stage_A_half(As, co, row0, tid);
    stage_B(Bs, Wo, 96, 0, tid);
    __syncthreads();
    gemm_main(acc, As4, Bs4, mg, nh, lane);

#pragma unroll
    for (int m = 0; m < 2; ++m) {
        int rl = (mg * 2 + m) * 16 + gid;
#pragma unroll
        for (int j = 0; j < 6; ++j) {
            int nc = (nh * 6 + j) * 8 + tig * 2;
            float2 bv = *(const float2*)&bo[nc];
            float2 r0 = __half22float2(*(const __half2*)(t0 + (size_t)(row0 + rl) * 96 + nc));
            float2 r1 = __half22float2(*(const __half2*)(t0 + (size_t)(row0 + rl + 8) * 96 + nc));
            *(float2*)&Tf[rl * TF_LD + nc] =
                make_float2(acc[m][j][0] + bv.x + r0.x, acc[m][j][1] + bv.y + r0.y);
            *(float2*)&Tf[(rl + 8) * TF_LD + nc] =
                make_float2(acc[m][j][2] + bv.x + r1.x, acc[m][j][3] + bv.y + r1.y);
        }
    }
    __syncthreads();

    // phase 2: LN(Tf) @ W1
    {
        const int row = tid >> 1, sub = tid & 1;
        const int mt = row >> 4, r16 = row & 15;
        const int gid8 = r16 & 7, rowhi = r16 >> 3;
        const float* ap = Tf + row * TF_LD + sub * 48;
        float4 vals[12];
#pragma unroll
        for (int j = 0; j < 12; ++j) vals[j] = *(const float4*)(ap + j * 4);
        float s = 0.f, s2 = 0.f;
#pragma unroll
        for (int j = 0; j < 12; ++j) {
            float4 v = vals[j];
            s += v.x + v.y + v.z + v.w;
            s2 += v.x * v.x + v.y * v.y + v.z * v.z + v.w * v.w;
        }
        s += __shfl_xor_sync(0xffffffffu, s, 1);
        s2 += __shfl_xor_sync(0xffffffffu, s2, 1);
        float mean = s * (1.f / 96.f);
        float var = fmaf(-mean, mean, s2 * (1.f / 96.f));
        float rstd = rsqrtf(var + 1e-5f);
#pragma unroll
        for (int j = 0; j < 12; ++j) {
            int k0 = sub * 48 + j * 4;
            float4 v = vals[j];
            float4 g = __ldg((const float4*)(lng + k0));
            float4 bb = __ldg((const float4*)(lnb + k0));
            v.x = (v.x - mean) * rstd * g.x + bb.x;
            v.y = (v.y - mean) * rstd * g.y + bb.y;
            v.z = (v.z - mean) * rstd * g.z + bb.z;
            v.w = (v.w - mean) * rstd * g.w + bb.w;
            int kt = k0 >> 4, kk = k0 & 15;
            int hi = kk >> 3, tg = (kk & 7) >> 1;
            unsigned base = (((kt * 8 + mt) * 32) + (gid8 << 2) + tg) * 4;
            As[base + (rowhi | (hi << 1))] = f2h2(v.x, v.y);
            As[base + 4 + (rowhi | (hi << 1))] = f2h2(v.z, v.w);
        }
    }
    stage_B(Bs, W1, 96, 0, tid);
    __syncthreads();
    gemm_main(acc, As4, Bs4, mg, nh, lane);
    __syncthreads();

    // phase 3: h = gelu(acc + b1) -> As (C->A frag map); W2 -> Bs
#pragma unroll
    for (int m = 0; m < 2; ++m) {
        int mt2 = mg * 2 + m;
#pragma unroll
        for (int j = 0; j < 6; ++j) {
            int col8 = nh * 6 + j;
            int kt = col8 >> 1, hi = col8 & 1;
            int k0 = col8 * 8 + tig * 2;
            float2 bv = *(const float2*)&b1[k0];
            float x0 = gelu_f(acc[m][j][0] + bv.x), x1 = gelu_f(acc[m][j][1] + bv.y);
            float x2 = gelu_f(acc[m][j][2] + bv.x), x3 = gelu_f(acc[m][j][3] + bv.y);
            unsigned base = (((kt * 8 + mt2) * 32) + (gid << 2) + tig) * 4;
            As[base + (hi << 1)] = f2h2(x0, x1);
            As[base + 1 + (hi << 1)] = f2h2(x2, x3);
        }
    }
    stage_B(Bs, W2, 96, 0, tid);
    __syncthreads();
    gemm_main(acc, As4, Bs4, mg, nh, lane);

#pragma unroll
    for (int m = 0; m < 2; ++m) {
        int rl = (mg * 2 + m) * 16 + gid;
#pragma unroll
        for (int j = 0; j < 6; ++j) {
            int nc = (nh * 6 + j) * 8 + tig * 2;
            float2 bv = *(const float2*)&b2[nc];
            float2 t0v = *(const float2*)&Tf[rl * TF_LD + nc];
            float2 t1v = *(const float2*)&Tf[(rl + 8) * TF_LD + nc];
            *(float2*)&out[(size_t)(row0 + rl) * 96 + nc] =
                make_float2(acc[m][j][0] + bv.x + t0v.x, acc[m][j][1] + bv.y + t0v.y);
            *(float2*)&out[(size_t)(row0 + rl + 8) * 96 + nc] =
                make_float2(acc[m][j][2] + bv.x + t1v.x, acc[m][j][3] + bv.y + t1v.y);
        }
    }
}

// ---------------------------------------------------------------------------
// patch merge (fp32 image in, fp16 residual out), fp16 MMA, K chunks of 96
// ---------------------------------------------------------------------------
template <int DF, int KTOT, int WOUT>
__global__ __launch_bounds__(256, 3) void patch_tc(const float* __restrict__ x,
                                                   const float* __restrict__ w,
                                                   const float* __restrict__ bias,
                                                   __half* __restrict__ out) {
    constexpr int KPAD = (KTOT + 15) & ~15;
    __shared__ uint4 As4[AS_U4];
    __shared__ uint4 Bs4[BS_U4];
    unsigned* As = (unsigned*)As4;
    unsigned* Bs = (unsigned*)Bs4;
    const int tid = threadIdx.x, lane = tid & 31, warp = tid >> 5;
    const int row0 = blockIdx.x * 128;
    const int T = WOUT * WOUT;
    const int mg = warp & 3, nh = warp >> 2;

    float acc[2][6][4];
#pragma unroll
    for (int m = 0; m < 2; ++m)
#pragma unroll
        for (int j = 0; j < 6; ++j)
#pragma unroll
            for (int i = 0; i < 4; ++i) acc[m][j][i] = 0.f;

    for (int kc = 0; kc < KPAD; kc += 96) {
        const int cl = (KPAD - kc) < 96 ? (KPAD - kc) : 96;
        const int nkt = cl >> 4;

        for (int idx = tid; idx < nkt * 768; idx += 256) {
            int kt = idx / 768;
            int r = idx - kt * 768;
            int jp = r >> 7;
            int r2 = r & 127;
            int ln = r2 >> 2, c = r2 & 3;
            int tig = ln & 3, gid = ln >> 2;
            int n = ((jp << 1) + (c >> 1)) * 8 + gid;
            int k = kc + kt * 16 + 2 * tig + ((c & 1) << 3);
            float lo = (k < KTOT) ? __ldg(&w[k * 96 + n]) : 0.f;
            float hi = (k + 1 < KTOT) ? __ldg(&w[(k + 1) * 96 + n]) : 0.f;
            Bs[idx] = f2h2(lo, hi);
        }
        {
            const int row = tid >> 1, sub = tid & 1;
            const int tok = row0 + row;
            const int b = tok / T, hw = tok - b * T;
            const int h = hw / WOUT, ww = hw - h * WOUT;
            const int mt = row >> 4, r16 = row & 15;
            const int gid8 = r16 & 7, rowhi = r16 >> 3;
#pragma unroll
            for (int j = 0; j < 12; ++j) {
                int k0 = sub * 48 + j * 4;
                if (k0 >= cl) break;
                float v[4];
#pragma unroll
                for (int e = 0; e < 4; ++e) {
                    int f = kc + k0 + e;
                    float vv = 0.f;
                    if (f < KTOT) {
                        int c2 = f / (DF * DF), rem = f - c2 * DF * DF;
                        int ki = rem / DF, kj = rem - ki * DF;
                        vv = __ldg(&x[((b * 3 + c2) * 224 + h * DF + ki) * 224 + ww * DF + kj]);
                    }
                    v[e] = vv;
                }
                int kt = k0 >> 4, kk = k0 & 15;
                int hi = kk >> 3, tig = (kk & 7) >> 1;
                unsigned base = (((kt * 8 + mt) * 32) + (gid8 << 2) + tig) * 4;
                As[base + (rowhi | (hi << 1))] = f2h2(v[0], v[1]);
                As[base + 4 + (rowhi | (hi << 1))] = f2h2(v[2], v[3]);
            }
        }
        __syncthreads();

        for (int kt = 0; kt < nkt; ++kt) {
            uint4 a0 = As4[(kt * 8 + mg * 2) * 32 + lane];
            uint4 a1 = As4[(kt * 8 + mg * 2 + 1) * 32 + lane];
            uint4 b0 = Bs4[(kt * 6 + nh * 3) * 32 + lane];
            uint4 b1 = Bs4[(kt * 6 + nh * 3 + 1) * 32 + lane];
            uint4 b2 = Bs4[(kt * 6 + nh * 3 + 2) * 32 + lane];
            mma16(acc[0][0], a0, b0.x, b0.y); mma16(acc[0][1], a0, b0.z, b0.w);
            mma16(acc[0][2], a0, b1.x, b1.y); mma16(acc[0][3], a0, b1.z, b1.w);
            mma16(acc[0][4], a0, b2.x, b2.y); mma16(acc[0][5], a0, b2.z, b2.w);
            mma16(acc[1][0], a1, b0.x, b0.y); mma16(acc[1][1], a1, b0.z, b0.w);
            mma16(acc[1][2], a1, b1.x, b1.y); mma16(acc[1][3], a1, b1.z, b1.w);
            mma16(acc[1][4], a1, b2.x, b2.y); mma16(acc[1][5], a1, b2.z, b2.w);
        }
        __syncthreads();
    }

    const int gid = lane >> 2, tig = lane & 3;
#pragma unroll
    for (int m = 0; m < 2; ++m) {
        int rr = row0 + (mg * 2 + m) * 16 + gid;
#pragma unroll
        for (int j = 0; j < 6; ++j) {
            int nc = (nh * 6 + j) * 8 + tig * 2;
            float2 bv = *(const float2*)&bias[nc];
            *(__half2*)&out[(size_t)rr * 96 + nc] =
                __floats2half2_rn(acc[m][j][0] + bv.x, acc[m][j][1] + bv.y);
            *(__half2*)&out[(size_t)(rr + 8) * 96 + nc] =
                __floats2half2_rn(acc[m][j][2] + bv.x, acc[m][j][3] + bv.y);
        }
    }
}

// ---------------------------------------------------------------------------
// window attention body (3 heads parallel, vectorized)
// ---------------------------------------------------------------------------
template <int WS>
__device__ __forceinline__ void win_attn_body(const __half* qkv, __half* o,
                                              int Wout, int nw, int rowbase,
                                              int b, int win, float* wsm) {
    constexpr int NT = WS * WS;
    float* sq = wsm;
    float* sk = sq + 3 * NT * 33;
    float* sv = sk + 3 * NT * 33;
    float* sS = sv + 3 * NT * 33;
    const int wr = win / nw, wc = win % nw;
    const int t = threadIdx.x;
    const int T = Wout * Wout;
    const float scale = 0.17677669529663687f;

    for (int idx = t; idx < NT * 36; idx += 128) {
        int p = idx / 36, u = idx - p * 36;
        int wi = p / WS, wj = p - wi * WS;
        int r = rowbase + b * T + (wr * WS + wi) * Wout + wc * WS + wj;
        uint4 val = __ldg((const uint4*)(qkv + (size_t)r * 288) + u);
        int sec = u / 12, uu = u - sec * 12;
        int head = uu >> 2, c0 = (uu & 3) * 8;
        float* dst = (sec == 0 ? sq : sec == 1 ? sk : sv) + (head * NT + p) * 33 + c0;
        __half2* h2 = (__half2*)&val;
#pragma unroll
        for (int e = 0; e < 4; ++e) {
            float2 f = __half22float2(h2[e]);
            dst[2 * e] = f.x;
            dst[2 * e + 1] = f.y;
        }
    }
    __syncthreads();

    for (int idx = t; idx < 3 * NT * NT; idx += 128) {
        int h = idx / (NT * NT);
        int ij = idx - h * NT * NT;
        int i = ij / NT, j = ij - i * NT;
        const float* qi = sq + (h * NT + i) * 33;
        const float* kj = sk + (h * NT + j) * 33;
        float s = 0.f;
#pragma unroll
        for (int c = 0; c < 32; ++c) s = fmaf(qi[c], kj[c], s);
        sS[idx] = s * scale;
    }
    __syncthreads();

    for (int row = t; row < 3 * NT; row += 128) {
        float* p = sS + row * NT;
        float m = -1e30f;
        for (int j = 0; j < NT; ++j) m = fmaxf(m, p[j]);
        float Z = 0.f;
        for (int j = 0; j < NT; ++j) {
            float e = __expf(p[j] - m);
            p[j] = e;
            Z += e;
        }
        float inv = 1.f / Z;
        for (int j = 0; j < NT; ++j) p[j] *= inv;
    }
    __syncthreads();

    for (int idx = t; idx < 3 * NT * 32; idx += 128) {
        int h = idx / (NT * 32);
        int rest = idx - h * NT * 32;
        int i = rest >> 5, c = rest & 31;
        const float* pw = sS + (h * NT + i) * NT;
        const float* vb = sv + h * NT * 33 + c;
        float acc = 0.f;
        for (int j = 0; j < NT; ++j) acc = fmaf(pw[j], vb[j * 33], acc);
        int wi = i / WS, wj = i - wi * WS;
        int r = rowbase + b * T + (wr * WS + wi) * Wout + wc * WS + wj;
        o[(size_t)r * 96 + h * 32 + c] = __float2half(acc);
    }
}

__global__ __launch_bounds__(128) void win7_k(const __half* __restrict__ qkv,
                                              __half* __restrict__ o) {
    extern __shared__ float wsm[];
    int b = blockIdx.x / 4, win = blockIdx.x % 4;
    win_attn_body<7>(qkv, o, 14, 2, 0, b, win, wsm);
}

// merged scale1 (64*196 blocks) + scale2 (64*64 blocks)
__global__ __launch_bounds__(128) void win4m_k(const __half* __restrict__ qkv,
                                               __half* __restrict__ o) {
    extern __shared__ float wsm[];
    int blk = blockIdx.x;
    if (blk < 64 * 196) {
        int b = blk / 196, win = blk % 196;
        win_attn_body<4>(qkv, o, 56, 14, ROWS0, b, win, wsm);
    } else {
        blk -= 64 * 196;
        int b = blk / 64, win = blk % 64;
        win_attn_body<4>(qkv, o, 32, 8, ROWS0 + ROWS1, b, win, wsm);
    }
}

// ---------------------------------------------------------------------------
// neighbor gather + LN (fp16 inputs), warp-per-row LN
// ---------------------------------------------------------------------------
__global__ __launch_bounds__(256) void gather_ln_k(const __half* __restrict__ t1,
                                                   const __half* __restrict__ t2,
                                                   const float* __restrict__ g,
                                                   const float* __restrict__ bb,
                                                   __half* __restrict__ kv) {
    const int bl = blockIdx.x;
    const int b = bl / 196, l = bl % 196;
    const int i1 = l / 14, j1 = l % 14;
    __shared__ float s1[16 * 100];
    __shared__ float s2[9 * 100];
    const int tid = threadIdx.x, warp = tid >> 5, lane = tid & 31;

    for (int idx = tid; idx < 16 * 12; idx += 256) {
        int p = idx / 12, q = idx - p * 12;
        int ki = p >> 2, kj = p & 3;
        uint4 u = __ldg((const uint4*)(t1 +
            (size_t)((b * 56 + i1 * 4 + ki) * 56 + j1 * 4 + kj) * 96) + q);
        __half2* h2 = (__half2*)&u;
        float* dst = &s1[p * 100 + q * 8];
#pragma unroll
        for (int e = 0; e < 4; ++e) {
            float2 f = __half22float2(h2[e]);
            dst[2 * e] = f.x;
            dst[2 * e + 1] = f.y;
        }
    }
    for (int idx = tid; idx < 9 * 12; idx += 256) {
        int p = idx / 12, q = idx - p * 12;
        int ki = p / 3, kj = p - ki * 3;
        int rr = i1 * 3 + ki - 5, cc = j1 * 3 + kj - 5;
        float* dst = &s2[p * 100 + q * 8];
        if (rr >= 0 && rr < 32 && cc >= 0 && cc < 32) {
            uint4 u = __ldg((const uint4*)(t2 + (size_t)((b * 32 + rr) * 32 + cc) * 96) + q);
            __half2* h2 = (__half2*)&u;
#pragma unroll
            for (int e = 0; e < 4; ++e) {
                float2 f = __half22float2(h2[e]);
                dst[2 * e] = f.x;
                dst[2 * e + 1] = f.y;
            }
        } else {
#pragma unroll
            for (int e = 0; e < 8; ++e) dst[e] = 0.f;
        }
    }
    __syncthreads();

    float gv[3], bv[3];
#pragma unroll
    for (int i = 0; i < 3; ++i) {
        gv[i] = __ldg(&g[lane + 32 * i]);
        bv[i] = __ldg(&bb[lane + 32 * i]);
    }

    for (int k = warp; k < 25; k += 8) {
        float v[3];
#pragma unroll
        for (int i = 0; i < 3; ++i) {
            int c = lane + 32 * i;
            if (k < 16) {
                int F = k * 96 + c;
                v[i] = s1[(F & 15) * 100 + (F >> 4)];
            } else {
                int F = (k - 16) * 96 + c;
                v[i] = s2[(F % 9) * 100 + (F / 9)];
            }
        }
        float s = v[0] + v[1] + v[2];
        float q = v[0] * v[0] + v[1] * v[1] + v[2] * v[2];
#pragma unroll
        for (int off = 16; off > 0; off >>= 1) {
            s += __shfl_xor_sync(0xffffffffu, s, off);
            q += __shfl_xor_sync(0xffffffffu, q, off);
        }
        float mean = s * (1.f / 96.f);
        float var = fmaf(-mean, mean, q * (1.f / 96.f));
        float rstd = rsqrtf(var + 1e-5f);
        __half* dst = kv + ((size_t)bl * 25 + k) * 96;
#pragma unroll
        for (int i = 0; i < 3; ++i)
            dst[lane + 32 * i] = __float2half((v[i] - mean) * rstd * gv[i] + bv[i]);
    }
}

// ---------------------------------------------------------------------------
// cross attention
// ---------------------------------------------------------------------------
__global__ __launch_bounds__(128) void cross_attn_k(const __half* __restrict__ q,
                                                    const __half* __restrict__ kbuf,
                                                    const __half* __restrict__ vbuf,
                                                    __half* __restrict__ o) {
    const int rl = blockIdx.x;
    __shared__ __half hk[2400], hv[2400];
    __shared__ float sqf[96], ss[25];
    const int t = threadIdx.x;

    const uint4* ksrc = (const uint4*)(kbuf + (size_t)rl * 2400);
    const uint4* vsrc = (const uint4*)(vbuf + (size_t)rl * 2400);
    for (int idx = t; idx < 300; idx += 128) {
        ((uint4*)hk)[idx] = __ldg(ksrc + idx);
        ((uint4*)hv)[idx] = __ldg(vsrc + idx);
    }
    if (t < 96) sqf[t] = __half2float(__ldg(q + (size_t)rl * 96 + t));
    __syncthreads();

    if (t < 25) {
        const __half* kr = hk + t * 96;
        float s = 0.f;
#pragma unroll 8
        for (int c = 0; c < 96; ++c) s = fmaf(sqf[c], __half2float(kr[c]), s);
        ss[t] = s * 0.10206207261596575f;
    }
    __syncthreads();

    if (t < 96) {
        float m = -1e30f;
#pragma unroll
        for (int k = 0; k < 25; ++k) m = fmaxf(m, ss[k]);
        float Z = 0.f, acc = 0.f;
#pragma unroll
        for (int k = 0; k < 25; ++k) {
            float e = __expf(ss[k] - m);
            Z += e;
            acc = fmaf(e, __half2float(hv[k * 96 + t]), acc);
        }
        o[(size_t)rl * 96 + t] = __float2half(acc / Z);
    }
}

// ---------------------------------------------------------------------------
extern "C" void kernel_launch(void* const* d_in, const int* in_sizes, int n_in,
                              void* d_out, int out_size) {
    const float* x       = (const float*)d_in[0];
    const float* pw[3]   = {(const float*)d_in[1], (const float*)d_in[3], (const float*)d_in[5]};
    const float* pb[3]   = {(const float*)d_in[2], (const float*)d_in[4], (const float*)d_in[6]};
    const float* wa_ln_g = (const float*)d_in[7];
    const float* wa_ln_b = (const float*)d_in[8];
    const float* wa_qkv  = (const float*)d_in[9];
    const float* wa_ow   = (const float*)d_in[10];
    const float* wa_ob   = (const float*)d_in[11];
    const float* ff_ln_g = (const float*)d_in[12];
    const float* ff_ln_b = (const float*)d_in[13];
    const float* ff_w1   = (const float*)d_in[14];
    const float* ff_b1   = (const float*)d_in[15];
    const float* ff_w2   = (const float*)d_in[16];
    const float* ff_b2   = (const float*)d_in[17];
    const float* lnn_g   = (const float*)d_in[18];
    const float* lnn_b   = (const float*)d_in[19];
    const float* ca_wq   = (const float*)d_in[20];
    const float* ca_wk   = (const float*)d_in[21];
    const float* ca_wv   = (const float*)d_in[22];
    const float* ca_wo   = (const float*)d_in[23];
    const float* ca_bo   = (const float*)d_in[24];
    const float* fi_ln_g = (const float*)d_in[25];
    const float* fi_ln_b = (const float*)d_in[26];
    const float* fi_w1   = (const float*)d_in[27];
    const float* fi_b1   = (const float*)d_in[28];
    const float* fi_w2   = (const float*)d_in[29];
    const float* fi_b2   = (const float*)d_in[30];
    float* out = (float*)d_out;

    __half *t, *qkv, *ob, *kv, *kk, *vv, *qq, *co;
    cudaGetSymbolAddress((void**)&t, g_t);
    cudaGetSymbolAddress((void**)&qkv, g_qkv);
    cudaGetSymbolAddress((void**)&ob, g_ob);
    cudaGetSymbolAddress((void**)&kv, g_kv);
    cudaGetSymbolAddress((void**)&kk, g_k);
    cudaGetSymbolAddress((void**)&vv, g_v);
    cudaGetSymbolAddress((void**)&qq, g_q);
    cudaGetSymbolAddress((void**)&co, g_co);

    __half* t0 = t;
    __half* t1 = t + (size_t)ROWS0 * 96;
    __half* t2 = t + (size_t)(ROWS0 + ROWS1) * 96;

    const int WSM7 = (3 * 49 * 33 * 3 + 3 * 49 * 49) * 4;
    const int WSM4 = (3 * 16 * 33 * 3 + 3 * 16 * 16) * 4;
    cudaFuncSetAttribute(win7_k, cudaFuncAttributeMaxDynamicSharedMemorySize, WSM7);
    cudaFuncSetAttribute(win4m_k, cudaFuncAttributeMaxDynamicSharedMemorySize, WSM4);
    cudaFuncSetAttribute(resff_final, cudaFuncAttributeMaxDynamicSharedMemorySize, RES_SMEM);

    // patch merges (independent)
    patch_tc<16, 768, 14><<<ROWS0 / 128, 256>>>(x, pw[0], pb[0], t0);
    patch_tc<4, 48, 56><<<ROWS1 / 128, 256>>>(x, pw[1], pb[1], t1);
    patch_tc<7, 147, 32><<<ROWS2 / 128, 256>>>(x, pw[2], pb[2], t2);

    // ---- merged per-scale transformer ----
    // qkv = LN(t) @ Wqkv  (all scales, NCH=3)
    gemm_tc<__half, __half, true, false, 0, false, 3, true><<<RTOT / 128, 256>>>(
        t, wa_qkv, nullptr, nullptr, wa_ln_g, wa_ln_b, nullptr, qkv, nullptr, 288);
    // window attention
    win7_k<<<64 * 4, 128, WSM7>>>(qkv, ob);
    win4m_k<<<64 * 196 + 64 * 64, 128, WSM4>>>(qkv, ob);
    // t += ob @ Wo + bo (all scales)
    gemm_tc<__half, __half, false, false, 1, false, 1, true><<<RTOT / 128, 256>>>(
        ob, wa_ow, nullptr, wa_ob, nullptr, nullptr, nullptr, t, nullptr, 96);
    // h = gelu(LN(t) @ W1 + b1)
    gemm_tc<__half, __half, true, true, 0, false, 1, true><<<RTOT / 128, 256>>>(
        t, ff_w1, nullptr, ff_b1, ff_ln_g, ff_ln_b, nullptr, ob, nullptr, 96);
    // t += h @ W2 + b2
    gemm_tc<__half, __half, false, false, 1, false, 1, true><<<RTOT / 128, 256>>>(
        ob, ff_w2, nullptr, ff_b2, nullptr, nullptr, nullptr, t, nullptr, 96);

    // ---- cross-attention fusion ----
    gather_ln_k<<<64 * 196, 256>>>(t1, t2, lnn_g, lnn_b, kv);
    gemm_tc<__half, __half, false, false, 0, true, 1, false><<<dim3(KVROWS / 128, 2), 256>>>(
        kv, ca_wk, ca_wv, nullptr, nullptr, nullptr, nullptr, kk, vv, 96);
    gemm_tc<__half, __half, true, false, 0, false, 1, false><<<ROWS0 / 128, 256>>>(
        t0, ca_wq, nullptr, nullptr, lnn_g, lnn_b, nullptr, qq, nullptr, 96);
    cross_attn_k<<<12544, 128>>>(qq, kk, vv, co);
    // fused tail: out = t0 + co@Wo + bo; out += gelu(LN(out)@w1+b1)@w2 + b2
    resff_final<<<ROWS0 / 128, 256, RES_SMEM>>>(
        co, t0, out, ca_wo, ca_bo, fi_ln_g, fi_ln_b, fi_w1, fi_b1, fi_w2, fi_b2);
}

// round 12
// speedup vs baseline: 1.3162x; 1.2102x over previous
#include <cuda_runtime.h>
#include <cuda_fp16.h>
#include <math.h>

// ---------------------------------------------------------------------------
// MultiScaleCrossAttn — fp16 MMA GEMMs, scale-merged launches,
// coalesced vectorized B staging (padded frag layout), fused tail
// ---------------------------------------------------------------------------

#define ROWS0 12544      // 64*14*14
#define ROWS1 200704     // 64*56*56
#define ROWS2 65536      // 64*32*32
#define RTOT  278784
#define KVROWS 313600    // 64*196*25

#define BLK0 98          // ROWS0/128
#define BLK01 1666       // (ROWS0+ROWS1)/128

__device__ __align__(16) __half g_t[RTOT * 96];
__device__ __align__(16) __half g_qkv[RTOT * 288];
__device__ __align__(16) __half g_ob[RTOT * 96];
__device__ __align__(16) __half g_kv[KVROWS * 96];
__device__ __align__(16) __half g_k[KVROWS * 96];
__device__ __align__(16) __half g_v[KVROWS * 96];
__device__ __align__(16) __half g_q[ROWS0 * 96];
__device__ __align__(16) __half g_co[ROWS0 * 96];

static constexpr int AS_U4 = 6 * 8 * 32;    // 24576 B
static constexpr int BS_U4 = 36 * 33;       // padded: 36 groups x 33 uint4 = 19008 B
static constexpr int TF_LD = 100;
static constexpr int RES_SMEM = 128 * TF_LD * 4 + AS_U4 * 16 + BS_U4 * 16;  // 94784

__device__ __forceinline__ unsigned f2h2(float lo, float hi) {
    __half2 h = __floats2half2_rn(lo, hi);
    return *reinterpret_cast<unsigned*>(&h);
}

__device__ __forceinline__ void mma16(float c[4], uint4 a, unsigned b0, unsigned b1) {
    asm volatile(
        "mma.sync.aligned.m16n8k16.row.col.f32.f16.f16.f32 "
        "{%0,%1,%2,%3}, {%4,%5,%6,%7}, {%8,%9}, {%0,%1,%2,%3};\n"
        : "+f"(c[0]), "+f"(c[1]), "+f"(c[2]), "+f"(c[3])
        : "r"(a.x), "r"(a.y), "r"(a.z), "r"(a.w), "r"(b0), "r"(b1));
}

__device__ __forceinline__ float gelu_f(float v) {
    return 0.5f * v * (1.f + erff(v * 0.70710678118654752f));
}

__device__ __forceinline__ void gemm_main(float acc[2][6][4], const uint4* As4,
                                          const uint4* Bs4, int mg, int nh, int lane) {
#pragma unroll
    for (int m = 0; m < 2; ++m)
#pragma unroll
        for (int j = 0; j < 6; ++j)
#pragma unroll
            for (int i = 0; i < 4; ++i) acc[m][j][i] = 0.f;
#pragma unroll
    for (int kt = 0; kt < 6; ++kt) {
        uint4 a0 = As4[(kt * 8 + mg * 2) * 32 + lane];
        uint4 a1 = As4[(kt * 8 + mg * 2 + 1) * 32 + lane];
        uint4 b0 = Bs4[(kt * 6 + nh * 3) * 33 + lane];
        uint4 b1 = Bs4[(kt * 6 + nh * 3 + 1) * 33 + lane];
        uint4 b2 = Bs4[(kt * 6 + nh * 3 + 2) * 33 + lane];
        mma16(acc[0][0], a0, b0.x, b0.y); mma16(acc[0][1], a0, b0.z, b0.w);
        mma16(acc[0][2], a0, b1.x, b1.y); mma16(acc[0][3], a0, b1.z, b1.w);
        mma16(acc[0][4], a0, b2.x, b2.y); mma16(acc[0][5], a0, b2.z, b2.w);
        mma16(acc[1][0], a1, b0.x, b0.y); mma16(acc[1][1], a1, b0.z, b0.w);
        mma16(acc[1][2], a1, b1.x, b1.y); mma16(acc[1][3], a1, b1.z, b1.w);
        mma16(acc[1][4], a1, b2.x, b2.y); mma16(acc[1][5], a1, b2.z, b2.w);
    }
}

// coalesced vectorized B staging: each thread loads a float4 along a weight
// row (coalesced) and scatters 4 half stores into the padded frag layout.
// rows >= kmax are staged as zero.
__device__ __forceinline__ void stage_B(__half* Bsh, const float* W, int ldw,
                                        int ncol0, int tid, int kmax) {
    for (int idx = tid; idx < 96 * 24; idx += 256) {
        int k = idx / 24;
        int q = idx - k * 24;
        int n = q * 4;
        float4 v = make_float4(0.f, 0.f, 0.f, 0.f);
        if (k < kmax) v = __ldg((const float4*)(W + (size_t)k * ldw + ncol0 + n));
        int kt = k >> 4, kk = k & 15;
        int tig = (kk >> 1) & 3, clo = kk >> 3, half = k & 1;
        float vv[4] = {v.x, v.y, v.z, v.w};
#pragma unroll
        for (int e = 0; e < 4; ++e) {
            int nn = n + e;
            int gid = nn & 7, jp = nn >> 4, chi = (nn >> 3) & 1;
            int word = ((kt * 6 + jp) * 33 + gid * 4 + tig) * 4 + (chi * 2 + clo);
            Bsh[word * 2 + half] = __float2half(vv[e]);
        }
    }
}

// stage fp16 A rows (no LN): pure repack, 2 threads/row
__device__ __forceinline__ void stage_A_half(unsigned* As, const __half* A,
                                             int row0, int tid) {
    const int row = tid >> 1, sub = tid & 1;
    const int mt = row >> 4, r16 = row & 15;
    const int gid8 = r16 & 7, rowhi = r16 >> 3;
    const uint4* ap = (const uint4*)(A + (size_t)(row0 + row) * 96 + sub * 48);
#pragma unroll
    for (int j = 0; j < 6; ++j) {
        uint4 u = __ldg(&ap[j]);
        unsigned w[4] = {u.x, u.y, u.z, u.w};
#pragma unroll
        for (int wi = 0; wi < 4; ++wi) {
            int P = sub * 24 + j * 4 + wi;
            int kt = P >> 3, hi = (P >> 2) & 1, tg = P & 3;
            As[(((kt * 8 + mt) * 32) + (gid8 << 2) + tg) * 4 + (rowhi | (hi << 1))] = w[wi];
        }
    }
}

// ---------------------------------------------------------------------------
// generic GEMM: LNF/GELU/EPI/DUAL/NCH/MULTI
// ---------------------------------------------------------------------------
template <class TA, class TO, bool LNF, bool GELU, int EPI, bool DUAL, int NCH, bool MULTI>
__global__ __launch_bounds__(256, 3) void gemm_tc(const TA* __restrict__ A,
                                                  const float* __restrict__ W,
                                                  const float* __restrict__ W2,
                                                  const float* __restrict__ bias,
                                                  const float* __restrict__ lng,
                                                  const float* __restrict__ lnb,
                                                  const TA* __restrict__ res,
                                                  TO* __restrict__ out,
                                                  TO* __restrict__ out2, int ldw) {
    constexpr bool TAH = (sizeof(TA) == 2);
    constexpr bool TOH = (sizeof(TO) == 2);
    __shared__ uint4 As4[AS_U4];
    __shared__ uint4 Bs4[BS_U4];
    unsigned* As = (unsigned*)As4;
    const int tid = threadIdx.x, lane = tid & 31, warp = tid >> 5;
    const int row0 = blockIdx.x * 128;
    int ncbase = 0;
    if (MULTI) {
        int s = (blockIdx.x < BLK0) ? 0 : (blockIdx.x < BLK01) ? 1 : 2;
        W += (size_t)s * 96 * ldw;
        if (bias) bias += s * 96;
        if (LNF) { lng += s * 96; lnb += s * 96; }
    } else if (DUAL) {
        if (blockIdx.y) { W = W2; out = out2; }
    } else if (NCH == 1) {
        ncbase = blockIdx.y * 96;
    }

    stage_B((__half*)Bs4, W, ldw, ncbase, tid, 96);

    // ---- stage A ----
    if constexpr (TAH && !LNF) {
        stage_A_half(As, (const __half*)A, row0, tid);
    } else {
        const int row = tid >> 1, sub = tid & 1;
        const int mt = row >> 4, r16 = row & 15;
        const int gid8 = r16 & 7, rowhi = r16 >> 3;
        float4 vals[12];
        if constexpr (TAH) {
            const uint4* ap = (const uint4*)((const __half*)A + (size_t)(row0 + row) * 96 + sub * 48);
#pragma unroll
            for (int j = 0; j < 6; ++j) {
                uint4 u = __ldg(&ap[j]);
                __half2* h2 = (__half2*)&u;
                float2 f0 = __half22float2(h2[0]);
                float2 f1 = __half22float2(h2[1]);
                float2 f2v = __half22float2(h2[2]);
                float2 f3 = __half22float2(h2[3]);
                vals[2 * j] = make_float4(f0.x, f0.y, f1.x, f1.y);
                vals[2 * j + 1] = make_float4(f2v.x, f2v.y, f3.x, f3.y);
            }
        } else {
            const float* ap = (const float*)A + (size_t)(row0 + row) * 96 + sub * 48;
#pragma unroll
            for (int j = 0; j < 12; ++j) vals[j] = __ldg((const float4*)(ap + j * 4));
        }
        float mean = 0.f, rstd = 0.f;
        if (LNF) {
            float s = 0.f, s2 = 0.f;
#pragma unroll
            for (int j = 0; j < 12; ++j) {
                float4 v = vals[j];
                s += v.x + v.y + v.z + v.w;
                s2 += v.x * v.x + v.y * v.y + v.z * v.z + v.w * v.w;
            }
            s += __shfl_xor_sync(0xffffffffu, s, 1);
            s2 += __shfl_xor_sync(0xffffffffu, s2, 1);
            mean = s * (1.f / 96.f);
            float var = fmaf(-mean, mean, s2 * (1.f / 96.f));
            rstd = rsqrtf(var + 1e-5f);
        }
#pragma unroll
        for (int j = 0; j < 12; ++j) {
            int k0 = sub * 48 + j * 4;
            float4 v = vals[j];
            if (LNF) {
                float4 g = __ldg((const float4*)(lng + k0));
                float4 bb = __ldg((const float4*)(lnb + k0));
                v.x = (v.x - mean) * rstd * g.x + bb.x;
                v.y = (v.y - mean) * rstd * g.y + bb.y;
                v.z = (v.z - mean) * rstd * g.z + bb.z;
                v.w = (v.w - mean) * rstd * g.w + bb.w;
            }
            int kt = k0 >> 4, kk = k0 & 15;
            int hi = kk >> 3, tig = (kk & 7) >> 1;
            unsigned base = (((kt * 8 + mt) * 32) + (gid8 << 2) + tig) * 4;
            As[base + (rowhi | (hi << 1))] = f2h2(v.x, v.y);
            As[base + 4 + (rowhi | (hi << 1))] = f2h2(v.z, v.w);
        }
    }
    __syncthreads();

    const int mg = warp & 3, nh = warp >> 2;
    const int gid = lane >> 2, tig = lane & 3;
    float acc[2][6][4];

#pragma unroll
    for (int ch = 0; ch < NCH; ++ch) {
        if (ch > 0) {
            __syncthreads();
            stage_B((__half*)Bs4, W, ldw, ch * 96, tid, 96);
            __syncthreads();
        }
        gemm_main(acc, As4, Bs4, mg, nh, lane);
        const int ncol0 = (NCH > 1) ? ch * 96 : ncbase;

#pragma unroll
        for (int m = 0; m < 2; ++m) {
            int rr = row0 + (mg * 2 + m) * 16 + gid;
#pragma unroll
            for (int j = 0; j < 6; ++j) {
                int nc = ncol0 + (nh * 6 + j) * 8 + tig * 2;
                float bx = 0.f, by = 0.f;
                if (bias) {
                    float2 bv = *(const float2*)&bias[nc];
                    bx = bv.x; by = bv.y;
                }
                float x0 = acc[m][j][0] + bx, x1 = acc[m][j][1] + by;
                float x2 = acc[m][j][2] + bx, x3 = acc[m][j][3] + by;
                if (GELU) { x0 = gelu_f(x0); x1 = gelu_f(x1); x2 = gelu_f(x2); x3 = gelu_f(x3); }
                if constexpr (TOH) {
                    __half2* p0 = (__half2*)((__half*)out + (size_t)rr * ldw + nc);
                    __half2* p1 = (__half2*)((__half*)out + (size_t)(rr + 8) * ldw + nc);
                    if constexpr (EPI == 1) {
                        float2 o0 = __half22float2(*p0), o1 = __half22float2(*p1);
                        x0 += o0.x; x1 += o0.y; x2 += o1.x; x3 += o1.y;
                    }
                    *p0 = __floats2half2_rn(x0, x1);
                    *p1 = __floats2half2_rn(x2, x3);
                } else {
                    float* p0 = (float*)out + (size_t)rr * ldw + nc;
                    float* p1 = (float*)out + (size_t)(rr + 8) * ldw + nc;
                    if constexpr (EPI == 0) {
                        *(float2*)p0 = make_float2(x0, x1);
                        *(float2*)p1 = make_float2(x2, x3);
                    } else if constexpr (EPI == 1) {
                        float2 o0 = *(float2*)p0, o1 = *(float2*)p1;
                        *(float2*)p0 = make_float2(o0.x + x0, o0.y + x1);
                        *(float2*)p1 = make_float2(o1.x + x2, o1.y + x3);
                    } else {
                        float2 r0 = __half22float2(*(const __half2*)((const __half*)res + (size_t)rr * 96 + nc));
                        float2 r1 = __half22float2(*(const __half2*)((const __half*)res + (size_t)(rr + 8) * 96 + nc));
                        *(float2*)p0 = make_float2(r0.x + x0, r0.y + x1);
                        *(float2*)p1 = make_float2(r1.x + x2, r1.y + x3);
                    }
                }
            }
        }
    }
}

// ---------------------------------------------------------------------------
// FUSED TAIL: out = t0 + co@Wo + bo; out += gelu(LN(out)@W1+b1)@W2 + b2
// ---------------------------------------------------------------------------
__global__ __launch_bounds__(256) void resff_final(const __half* __restrict__ co,
                                                   const __half* __restrict__ t0,
                                                   float* __restrict__ out,
                                                   const float* __restrict__ Wo,
                                                   const float* __restrict__ bo,
                                                   const float* __restrict__ lng,
                                                   const float* __restrict__ lnb,
                                                   const float* __restrict__ W1,
                                                   const float* __restrict__ b1,
                                                   const float* __restrict__ W2,
                                                   const float* __restrict__ b2) {
    extern __shared__ float dyn[];
    float* Tf = dyn;
    unsigned* As = (unsigned*)(dyn + 128 * TF_LD);
    unsigned* Bs = As + AS_U4 * 4;
    uint4* As4 = (uint4*)As;
    uint4* Bs4 = (uint4*)Bs;
    const int tid = threadIdx.x, lane = tid & 31, warp = tid >> 5;
    const int row0 = blockIdx.x * 128;
    const int mg = warp & 3, nh = warp >> 2;
    const int gid = lane >> 2, tig = lane & 3;
    float acc[2][6][4];

    // phase 1: co @ Wo
    stage_A_half(As, co, row0, tid);
    stage_B((__half*)Bs4, Wo, 96, 0, tid, 96);
    __syncthreads();
    gemm_main(acc, As4, Bs4, mg, nh, lane);

#pragma unroll
    for (int m = 0; m < 2; ++m) {
        int rl = (mg * 2 + m) * 16 + gid;
#pragma unroll
        for (int j = 0; j < 6; ++j) {
            int nc = (nh * 6 + j) * 8 + tig * 2;
            float2 bv = *(const float2*)&bo[nc];
            float2 r0 = __half22float2(*(const __half2*)(t0 + (size_t)(row0 + rl) * 96 + nc));
            float2 r1 = __half22float2(*(const __half2*)(t0 + (size_t)(row0 + rl + 8) * 96 + nc));
            *(float2*)&Tf[rl * TF_LD + nc] =
                make_float2(acc[m][j][0] + bv.x + r0.x, acc[m][j][1] + bv.y + r0.y);
            *(float2*)&Tf[(rl + 8) * TF_LD + nc] =
                make_float2(acc[m][j][2] + bv.x + r1.x, acc[m][j][3] + bv.y + r1.y);
        }
    }
    __syncthreads();

    // phase 2: LN(Tf) @ W1
    {
        const int row = tid >> 1, sub = tid & 1;
        const int mt = row >> 4, r16 = row & 15;
        const int gid8 = r16 & 7, rowhi = r16 >> 3;
        const float* ap = Tf + row * TF_LD + sub * 48;
        float4 vals[12];
#pragma unroll
        for (int j = 0; j < 12; ++j) vals[j] = *(const float4*)(ap + j * 4);
        float s = 0.f, s2 = 0.f;
#pragma unroll
        for (int j = 0; j < 12; ++j) {
            float4 v = vals[j];
            s += v.x + v.y + v.z + v.w;
            s2 += v.x * v.x + v.y * v.y + v.z * v.z + v.w * v.w;
        }
        s += __shfl_xor_sync(0xffffffffu, s, 1);
        s2 += __shfl_xor_sync(0xffffffffu, s2, 1);
        float mean = s * (1.f / 96.f);
        float var = fmaf(-mean, mean, s2 * (1.f / 96.f));
        float rstd = rsqrtf(var + 1e-5f);
#pragma unroll
        for (int j = 0; j < 12; ++j) {
            int k0 = sub * 48 + j * 4;
            float4 v = vals[j];
            float4 g = __ldg((const float4*)(lng + k0));
            float4 bb = __ldg((const float4*)(lnb + k0));
            v.x = (v.x - mean) * rstd * g.x + bb.x;
            v.y = (v.y - mean) * rstd * g.y + bb.y;
            v.z = (v.z - mean) * rstd * g.z + bb.z;
            v.w = (v.w - mean) * rstd * g.w + bb.w;
            int kt = k0 >> 4, kk = k0 & 15;
            int hi = kk >> 3, tg = (kk & 7) >> 1;
            unsigned base = (((kt * 8 + mt) * 32) + (gid8 << 2) + tg) * 4;
            As[base + (rowhi | (hi << 1))] = f2h2(v.x, v.y);
            As[base + 4 + (rowhi | (hi << 1))] = f2h2(v.z, v.w);
        }
    }
    stage_B((__half*)Bs4, W1, 96, 0, tid, 96);
    __syncthreads();
    gemm_main(acc, As4, Bs4, mg, nh, lane);
    __syncthreads();

    // phase 3: h = gelu(acc + b1) -> As (C->A frag map); W2 -> Bs
#pragma unroll
    for (int m = 0; m < 2; ++m) {
        int mt2 = mg * 2 + m;
#pragma unroll
        for (int j = 0; j < 6; ++j) {
            int col8 = nh * 6 + j;
            int kt = col8 >> 1, hi = col8 & 1;
            int k0 = col8 * 8 + tig * 2;
            float2 bv = *(const float2*)&b1[k0];
            float x0 = gelu_f(acc[m][j][0] + bv.x), x1 = gelu_f(acc[m][j][1] + bv.y);
            float x2 = gelu_f(acc[m][j][2] + bv.x), x3 = gelu_f(acc[m][j][3] + bv.y);
            unsigned base = (((kt * 8 + mt2) * 32) + (gid << 2) + tig) * 4;
            As[base + (hi << 1)] = f2h2(x0, x1);
            As[base + 1 + (hi << 1)] = f2h2(x2, x3);
        }
    }
    stage_B((__half*)Bs4, W2, 96, 0, tid, 96);
    __syncthreads();
    gemm_main(acc, As4, Bs4, mg, nh, lane);

#pragma unroll
    for (int m = 0; m < 2; ++m) {
        int rl = (mg * 2 + m) * 16 + gid;
#pragma unroll
        for (int j = 0; j < 6; ++j) {
            int nc = (nh * 6 + j) * 8 + tig * 2;
            float2 bv = *(const float2*)&b2[nc];
            float2 t0v = *(const float2*)&Tf[rl * TF_LD + nc];
            float2 t1v = *(const float2*)&Tf[(rl + 8) * TF_LD + nc];
            *(float2*)&out[(size_t)(row0 + rl) * 96 + nc] =
                make_float2(acc[m][j][0] + bv.x + t0v.x, acc[m][j][1] + bv.y + t0v.y);
            *(float2*)&out[(size_t)(row0 + rl + 8) * 96 + nc] =
                make_float2(acc[m][j][2] + bv.x + t1v.x, acc[m][j][3] + bv.y + t1v.y);
        }
    }
}

// ---------------------------------------------------------------------------
// patch merge body (fp32 image in, fp16 out), shared smem passed in
// ---------------------------------------------------------------------------
template <int DF, int KTOT, int WOUT>
__device__ __forceinline__ void patch_body(const float* __restrict__ x,
                                           const float* __restrict__ w,
                                           const float* __restrict__ bias,
                                           __half* __restrict__ out,
                                           int blk, uint4* As4, uint4* Bs4) {
    constexpr int KPAD = (KTOT + 15) & ~15;
    unsigned* As = (unsigned*)As4;
    const int tid = threadIdx.x, lane = tid & 31, warp = tid >> 5;
    const int row0 = blk * 128;
    const int T = WOUT * WOUT;
    const int mg = warp & 3, nh = warp >> 2;

    float acc[2][6][4];
#pragma unroll
    for (int m = 0; m < 2; ++m)
#pragma unroll
        for (int j = 0; j < 6; ++j)
#pragma unroll
            for (int i = 0; i < 4; ++i) acc[m][j][i] = 0.f;

    for (int kc = 0; kc < KPAD; kc += 96) {
        const int cl = (KPAD - kc) < 96 ? (KPAD - kc) : 96;
        const int nkt = cl >> 4;

        stage_B((__half*)Bs4, w + (size_t)kc * 96, 96, 0, tid, KTOT - kc);
        {
            const int row = tid >> 1, sub = tid & 1;
            const int tok = row0 + row;
            const int b = tok / T, hw = tok - b * T;
            const int h = hw / WOUT, ww = hw - h * WOUT;
            const int mt = row >> 4, r16 = row & 15;
            const int gid8 = r16 & 7, rowhi = r16 >> 3;
#pragma unroll
            for (int j = 0; j < 12; ++j) {
                int k0 = sub * 48 + j * 4;
                if (k0 >= cl) break;
                float v[4];
#pragma unroll
                for (int e = 0; e < 4; ++e) {
                    int f = kc + k0 + e;
                    float vv = 0.f;
                    if (f < KTOT) {
                        int c2 = f / (DF * DF), rem = f - c2 * DF * DF;
                        int ki = rem / DF, kj = rem - ki * DF;
                        vv = __ldg(&x[((b * 3 + c2) * 224 + h * DF + ki) * 224 + ww * DF + kj]);
                    }
                    v[e] = vv;
                }
                int kt = k0 >> 4, kk = k0 & 15;
                int hi = kk >> 3, tig = (kk & 7) >> 1;
                unsigned base = (((kt * 8 + mt) * 32) + (gid8 << 2) + tig) * 4;
                As[base + (rowhi | (hi << 1))] = f2h2(v[0], v[1]);
                As[base + 4 + (rowhi | (hi << 1))] = f2h2(v[2], v[3]);
            }
        }
        __syncthreads();

        for (int kt = 0; kt < nkt; ++kt) {
            uint4 a0 = As4[(kt * 8 + mg * 2) * 32 + lane];
            uint4 a1 = As4[(kt * 8 + mg * 2 + 1) * 32 + lane];
            uint4 b0 = Bs4[(kt * 6 + nh * 3) * 33 + lane];
            uint4 b1 = Bs4[(kt * 6 + nh * 3 + 1) * 33 + lane];
            uint4 b2 = Bs4[(kt * 6 + nh * 3 + 2) * 33 + lane];
            mma16(acc[0][0], a0, b0.x, b0.y); mma16(acc[0][1], a0, b0.z, b0.w);
            mma16(acc[0][2], a0, b1.x, b1.y); mma16(acc[0][3], a0, b1.z, b1.w);
            mma16(acc[0][4], a0, b2.x, b2.y); mma16(acc[0][5], a0, b2.z, b2.w);
            mma16(acc[1][0], a1, b0.x, b0.y); mma16(acc[1][1], a1, b0.z, b0.w);
            mma16(acc[1][2], a1, b1.x, b1.y); mma16(acc[1][3], a1, b1.z, b1.w);
            mma16(acc[1][4], a1, b2.x, b2.y); mma16(acc[1][5], a1, b2.z, b2.w);
        }
        __syncthreads();
    }

    const int gid = lane >> 2, tig = lane & 3;
#pragma unroll
    for (int m = 0; m < 2; ++m) {
        int rr = row0 + (mg * 2 + m) * 16 + gid;
#pragma unroll
        for (int j = 0; j < 6; ++j) {
            int nc = (nh * 6 + j) * 8 + tig * 2;
            float2 bv = *(const float2*)&bias[nc];
            *(__half2*)&out[(size_t)rr * 96 + nc] =
                __floats2half2_rn(acc[m][j][0] + bv.x, acc[m][j][1] + bv.y);
            *(__half2*)&out[(size_t)(rr + 8) * 96 + nc] =
                __floats2half2_rn(acc[m][j][2] + bv.x, acc[m][j][3] + bv.y);
        }
    }
}

__global__ __launch_bounds__(256, 3) void patch_all(
    const float* __restrict__ x,
    const float* __restrict__ pw0, const float* __restrict__ pb0,
    const float* __restrict__ pw1, const float* __restrict__ pb1,
    const float* __restrict__ pw2, const float* __restrict__ pb2,
    __half* __restrict__ t) {
    __shared__ uint4 As4[AS_U4];
    __shared__ uint4 Bs4[BS_U4];
    int blk = blockIdx.x;
    if (blk < BLK0)
        patch_body<16, 768, 14>(x, pw0, pb0, t, blk, As4, Bs4);
    else if (blk < BLK01)
        patch_body<4, 48, 56>(x, pw1, pb1, t + (size_t)ROWS0 * 96, blk - BLK0, As4, Bs4);
    else
        patch_body<7, 147, 32>(x, pw2, pb2, t + (size_t)(ROWS0 + ROWS1) * 96, blk - BLK01, As4, Bs4);
}

// ---------------------------------------------------------------------------
// window attention body (3 heads parallel, vectorized)
// ---------------------------------------------------------------------------
template <int WS>
__device__ __forceinline__ void win_attn_body(const __half* qkv, __half* o,
                                              int Wout, int nw, int rowbase,
                                              int b, int win, float* wsm) {
    constexpr int NT = WS * WS;
    float* sq = wsm;
    float* sk = sq + 3 * NT * 33;
    float* sv = sk + 3 * NT * 33;
    float* sS = sv + 3 * NT * 33;
    const int wr = win / nw, wc = win % nw;
    const int t = threadIdx.x;
    const int T = Wout * Wout;
    const float scale = 0.17677669529663687f;

    for (int idx = t; idx < NT * 36; idx += 128) {
        int p = idx / 36, u = idx - p * 36;
        int wi = p / WS, wj = p - wi * WS;
        int r = rowbase + b * T + (wr * WS + wi) * Wout + wc * WS + wj;
        uint4 val = __ldg((const uint4*)(qkv + (size_t)r * 288) + u);
        int sec = u / 12, uu = u - sec * 12;
        int head = uu >> 2, c0 = (uu & 3) * 8;
        float* dst = (sec == 0 ? sq : sec == 1 ? sk : sv) + (head * NT + p) * 33 + c0;
        __half2* h2 = (__half2*)&val;
#pragma unroll
        for (int e = 0; e < 4; ++e) {
            float2 f = __half22float2(h2[e]);
            dst[2 * e] = f.x;
            dst[2 * e + 1] = f.y;
        }
    }
    __syncthreads();

    for (int idx = t; idx < 3 * NT * NT; idx += 128) {
        int h = idx / (NT * NT);
        int ij = idx - h * NT * NT;
        int i = ij / NT, j = ij - i * NT;
        const float* qi = sq + (h * NT + i) * 33;
        const float* kj = sk + (h * NT + j) * 33;
        float s = 0.f;
#pragma unroll
        for (int c = 0; c < 32; ++c) s = fmaf(qi[c], kj[c], s);
        sS[idx] = s * scale;
    }
    __syncthreads();

    for (int row = t; row < 3 * NT; row += 128) {
        float* p = sS + row * NT;
        float m = -1e30f;
        for (int j = 0; j < NT; ++j) m = fmaxf(m, p[j]);
        float Z = 0.f;
        for (int j = 0; j < NT; ++j) {
            float e = __expf(p[j] - m);
            p[j] = e;
            Z += e;
        }
        float inv = 1.f / Z;
        for (int j = 0; j < NT; ++j) p[j] *= inv;
    }
    __syncthreads();

    for (int idx = t; idx < 3 * NT * 32; idx += 128) {
        int h = idx / (NT * 32);
        int rest = idx - h * NT * 32;
        int i = rest >> 5, c = rest & 31;
        const float* pw = sS + (h * NT + i) * NT;
        const float* vb = sv + h * NT * 33 + c;
        float acc = 0.f;
        for (int j = 0; j < NT; ++j) acc = fmaf(pw[j], vb[j * 33], acc);
        int wi = i / WS, wj = i - wi * WS;
        int r = rowbase + b * T + (wr * WS + wi) * Wout + wc * WS + wj;
        o[(size_t)r * 96 + h * 32 + c] = __float2half(acc);
    }
}

__global__ __launch_bounds__(128) void win7_k(const __half* __restrict__ qkv,
                                              __half* __restrict__ o) {
    extern __shared__ float wsm[];
    int b = blockIdx.x / 4, win = blockIdx.x % 4;
    win_attn_body<7>(qkv, o, 14, 2, 0, b, win, wsm);
}

__global__ __launch_bounds__(128) void win4m_k(const __half* __restrict__ qkv,
                                               __half* __restrict__ o) {
    extern __shared__ float wsm[];
    int blk = blockIdx.x;
    if (blk < 64 * 196) {
        int b = blk / 196, win = blk % 196;
        win_attn_body<4>(qkv, o, 56, 14, ROWS0, b, win, wsm);
    } else {
        blk -= 64 * 196;
        int b = blk / 64, win = blk % 64;
        win_attn_body<4>(qkv, o, 32, 8, ROWS0 + ROWS1, b, win, wsm);
    }
}

// ---------------------------------------------------------------------------
// neighbor gather + LN (fp16 inputs), warp-per-row LN
// ---------------------------------------------------------------------------
__global__ __launch_bounds__(256) void gather_ln_k(const __half* __restrict__ t1,
                                                   const __half* __restrict__ t2,
                                                   const float* __restrict__ g,
                                                   const float* __restrict__ bb,
                                                   __half* __restrict__ kv) {
    const int bl = blockIdx.x;
    const int b = bl / 196, l = bl % 196;
    const int i1 = l / 14, j1 = l % 14;
    __shared__ float s1[16 * 100];
    __shared__ float s2[9 * 100];
    const int tid = threadIdx.x, warp = tid >> 5, lane = tid & 31;

    for (int idx = tid; idx < 16 * 12; idx += 256) {
        int p = idx / 12, q = idx - p * 12;
        int ki = p >> 2, kj = p & 3;
        uint4 u = __ldg((const uint4*)(t1 +
            (size_t)((b * 56 + i1 * 4 + ki) * 56 + j1 * 4 + kj) * 96) + q);
        __half2* h2 = (__half2*)&u;
        float* dst = &s1[p * 100 + q * 8];
#pragma unroll
        for (int e = 0; e < 4; ++e) {
            float2 f = __half22float2(h2[e]);
            dst[2 * e] = f.x;
            dst[2 * e + 1] = f.y;
        }
    }
    for (int idx = tid; idx < 9 * 12; idx += 256) {
        int p = idx / 12, q = idx - p * 12;
        int ki = p / 3, kj = p - ki * 3;
        int rr = i1 * 3 + ki - 5, cc = j1 * 3 + kj - 5;
        float* dst = &s2[p * 100 + q * 8];
        if (rr >= 0 && rr < 32 && cc >= 0 && cc < 32) {
            uint4 u = __ldg((const uint4*)(t2 + (size_t)((b * 32 + rr) * 32 + cc) * 96) + q);
            __half2* h2 = (__half2*)&u;
#pragma unroll
            for (int e = 0; e < 4; ++e) {
                float2 f = __half22float2(h2[e]);
                dst[2 * e] = f.x;
                dst[2 * e + 1] = f.y;
            }
        } else {
#pragma unroll
            for (int e = 0; e < 8; ++e) dst[e] = 0.f;
        }
    }
    __syncthreads();

    float gv[3], bv[3];
#pragma unroll
    for (int i = 0; i < 3; ++i) {
        gv[i] = __ldg(&g[lane + 32 * i]);
        bv[i] = __ldg(&bb[lane + 32 * i]);
    }

    for (int k = warp; k < 25; k += 8) {
        float v[3];
#pragma unroll
        for (int i = 0; i < 3; ++i) {
            int c = lane + 32 * i;
            if (k < 16) {
                int F = k * 96 + c;
                v[i] = s1[(F & 15) * 100 + (F >> 4)];
            } else {
                int F = (k - 16) * 96 + c;
                v[i] = s2[(F % 9) * 100 + (F / 9)];
            }
        }
        float s = v[0] + v[1] + v[2];
        float q = v[0] * v[0] + v[1] * v[1] + v[2] * v[2];
#pragma unroll
        for (int off = 16; off > 0; off >>= 1) {
            s += __shfl_xor_sync(0xffffffffu, s, off);
            q += __shfl_xor_sync(0xffffffffu, q, off);
        }
        float mean = s * (1.f / 96.f);
        float var = fmaf(-mean, mean, q * (1.f / 96.f));
        float rstd = rsqrtf(var + 1e-5f);
        __half* dst = kv + ((size_t)bl * 25 + k) * 96;
#pragma unroll
        for (int i = 0; i < 3; ++i)
            dst[lane + 32 * i] = __float2half((v[i] - mean) * rstd * gv[i] + bv[i]);
    }
}

// ---------------------------------------------------------------------------
// cross attention
// ---------------------------------------------------------------------------
__global__ __launch_bounds__(128) void cross_attn_k(const __half* __restrict__ q,
                                                    const __half* __restrict__ kbuf,
                                                    const __half* __restrict__ vbuf,
                                                    __half* __restrict__ o) {
    const int rl = blockIdx.x;
    __shared__ __half hk[2400], hv[2400];
    __shared__ float sqf[96], ss[25];
    const int t = threadIdx.x;

    const uint4* ksrc = (const uint4*)(kbuf + (size_t)rl * 2400);
    const uint4* vsrc = (const uint4*)(vbuf + (size_t)rl * 2400);
    for (int idx = t; idx < 300; idx += 128) {
        ((uint4*)hk)[idx] = __ldg(ksrc + idx);
        ((uint4*)hv)[idx] = __ldg(vsrc + idx);
    }
    if (t < 96) sqf[t] = __half2float(__ldg(q + (size_t)rl * 96 + t));
    __syncthreads();

    if (t < 25) {
        const __half* kr = hk + t * 96;
        float s = 0.f;
#pragma unroll 8
        for (int c = 0; c < 96; ++c) s = fmaf(sqf[c], __half2float(kr[c]), s);
        ss[t] = s * 0.10206207261596575f;
    }
    __syncthreads();

    if (t < 96) {
        float m = -1e30f;
#pragma unroll
        for (int k = 0; k < 25; ++k) m = fmaxf(m, ss[k]);
        float Z = 0.f, acc = 0.f;
#pragma unroll
        for (int k = 0; k < 25; ++k) {
            float e = __expf(ss[k] - m);
            Z += e;
            acc = fmaf(e, __half2float(hv[k * 96 + t]), acc);
        }
        o[(size_t)rl * 96 + t] = __float2half(acc / Z);
    }
}

// ---------------------------------------------------------------------------
extern "C" void kernel_launch(void* const* d_in, const int* in_sizes, int n_in,
                              void* d_out, int out_size) {
    const float* x       = (const float*)d_in[0];
    const float* pw0     = (const float*)d_in[1];
    const float* pb0     = (const float*)d_in[2];
    const float* pw1     = (const float*)d_in[3];
    const float* pb1     = (const float*)d_in[4];
    const float* pw2     = (const float*)d_in[5];
    const float* pb2     = (const float*)d_in[6];
    const float* wa_ln_g = (const float*)d_in[7];
    const float* wa_ln_b = (const float*)d_in[8];
    const float* wa_qkv  = (const float*)d_in[9];
    const float* wa_ow   = (const float*)d_in[10];
    const float* wa_ob   = (const float*)d_in[11];
    const float* ff_ln_g = (const float*)d_in[12];
    const float* ff_ln_b = (const float*)d_in[13];
    const float* ff_w1   = (const float*)d_in[14];
    const float* ff_b1   = (const float*)d_in[15];
    const float* ff_w2   = (const float*)d_in[16];
    const float* ff_b2   = (const float*)d_in[17];
    const float* lnn_g   = (const float*)d_in[18];
    const float* lnn_b   = (const float*)d_in[19];
    const float* ca_wq   = (const float*)d_in[20];
    const float* ca_wk   = (const float*)d_in[21];
    const float* ca_wv   = (const float*)d_in[22];
    const float* ca_wo   = (const float*)d_in[23];
    const float* ca_bo   = (const float*)d_in[24];
    const float* fi_ln_g = (const float*)d_in[25];
    const float* fi_ln_b = (const float*)d_in[26];
    const float* fi_w1   = (const float*)d_in[27];
    const float* fi_b1   = (const float*)d_in[28];
    const float* fi_w2   = (const float*)d_in[29];
    const float* fi_b2   = (const float*)d_in[30];
    float* out = (float*)d_out;

    __half *t, *qkv, *ob, *kv, *kk, *vv, *qq, *co;
    cudaGetSymbolAddress((void**)&t, g_t);
    cudaGetSymbolAddress((void**)&qkv, g_qkv);
    cudaGetSymbolAddress((void**)&ob, g_ob);
    cudaGetSymbolAddress((void**)&kv, g_kv);
    cudaGetSymbolAddress((void**)&kk, g_k);
    cudaGetSymbolAddress((void**)&vv, g_v);
    cudaGetSymbolAddress((void**)&qq, g_q);
    cudaGetSymbolAddress((void**)&co, g_co);

    __half* t0 = t;
    __half* t1 = t + (size_t)ROWS0 * 96;
    __half* t2 = t + (size_t)(ROWS0 + ROWS1) * 96;

    const int WSM7 = (3 * 49 * 33 * 3 + 3 * 49 * 49) * 4;
    const int WSM4 = (3 * 16 * 33 * 3 + 3 * 16 * 16) * 4;
    cudaFuncSetAttribute(win7_k, cudaFuncAttributeMaxDynamicSharedMemorySize, WSM7);
    cudaFuncSetAttribute(win4m_k, cudaFuncAttributeMaxDynamicSharedMemorySize, WSM4);
    cudaFuncSetAttribute(resff_final, cudaFuncAttributeMaxDynamicSharedMemorySize, RES_SMEM);

    // all patch merges in one launch
    patch_all<<<RTOT / 128, 256>>>(x, pw0, pb0, pw1, pb1, pw2, pb2, t);

    // merged per-scale transformer
    gemm_tc<__half, __half, true, false, 0, false, 3, true><<<RTOT / 128, 256>>>(
        t, wa_qkv, nullptr, nullptr, wa_ln_g, wa_ln_b, nullptr, qkv, nullptr, 288);
    win7_k<<<64 * 4, 128, WSM7>>>(qkv, ob);
    win4m_k<<<64 * 196 + 64 * 64, 128, WSM4>>>(qkv, ob);
    gemm_tc<__half, __half, false, false, 1, false, 1, true><<<RTOT / 128, 256>>>(
        ob, wa_ow, nullptr, wa_ob, nullptr, nullptr, nullptr, t, nullptr, 96);
    gemm_tc<__half, __half, true, true, 0, false, 1, true><<<RTOT / 128, 256>>>(
        t, ff_w1, nullptr, ff_b1, ff_ln_g, ff_ln_b, nullptr, ob, nullptr, 96);
    gemm_tc<__half, __half, false, false, 1, false, 1, true><<<RTOT / 128, 256>>>(
        ob, ff_w2, nullptr, ff_b2, nullptr, nullptr, nullptr, t, nullptr, 96);

    // cross-attention fusion
    gather_ln_k<<<64 * 196, 256>>>(t1, t2, lnn_g, lnn_b, kv);
    gemm_tc<__half, __half, false, false, 0, true, 1, false><<<dim3(KVROWS / 128, 2), 256>>>(
        kv, ca_wk, ca_wv, nullptr, nullptr, nullptr, nullptr, kk, vv, 96);
    gemm_tc<__half, __half, true, false, 0, false, 1, false><<<ROWS0 / 128, 256>>>(
        t0, ca_wq, nullptr, nullptr, lnn_g, lnn_b, nullptr, qq, nullptr, 96);
    cross_attn_k<<<12544, 128>>>(qq, kk, vv, co);
    resff_final<<<ROWS0 / 128, 256, RES_SMEM>>>(
        co, t0, out, ca_wo, ca_bo, fi_ln_g, fi_ln_b, fi_w1, fi_b1, fi_w2, fi_b2);
}

// round 13
// speedup vs baseline: 1.4265x; 1.0838x over previous
#include <cuda_runtime.h>
#include <cuda_fp16.h>
#include <math.h>

// ---------------------------------------------------------------------------
// MultiScaleCrossAttn — fp16 MMA GEMMs, scale-merged launches,
// coalesced B staging, VECTORIZED window attention, fused tail
// ---------------------------------------------------------------------------

#define ROWS0 12544      // 64*14*14
#define ROWS1 200704     // 64*56*56
#define ROWS2 65536      // 64*32*32
#define RTOT  278784
#define KVROWS 313600    // 64*196*25

#define BLK0 98          // ROWS0/128
#define BLK01 1666       // (ROWS0+ROWS1)/128

__device__ __align__(16) __half g_t[RTOT * 96];
__device__ __align__(16) __half g_qkv[RTOT * 288];
__device__ __align__(16) __half g_ob[RTOT * 96];
__device__ __align__(16) __half g_kv[KVROWS * 96];
__device__ __align__(16) __half g_k[KVROWS * 96];
__device__ __align__(16) __half g_v[KVROWS * 96];
__device__ __align__(16) __half g_q[ROWS0 * 96];
__device__ __align__(16) __half g_co[ROWS0 * 96];

static constexpr int AS_U4 = 6 * 8 * 32;    // 24576 B
static constexpr int BS_U4 = 36 * 33;       // padded: 19008 B
static constexpr int TF_LD = 100;
static constexpr int RES_SMEM = 128 * TF_LD * 4 + AS_U4 * 16 + BS_U4 * 16;  // 94784

__device__ __forceinline__ unsigned f2h2(float lo, float hi) {
    __half2 h = __floats2half2_rn(lo, hi);
    return *reinterpret_cast<unsigned*>(&h);
}

__device__ __forceinline__ void mma16(float c[4], uint4 a, unsigned b0, unsigned b1) {
    asm volatile(
        "mma.sync.aligned.m16n8k16.row.col.f32.f16.f16.f32 "
        "{%0,%1,%2,%3}, {%4,%5,%6,%7}, {%8,%9}, {%0,%1,%2,%3};\n"
        : "+f"(c[0]), "+f"(c[1]), "+f"(c[2]), "+f"(c[3])
        : "r"(a.x), "r"(a.y), "r"(a.z), "r"(a.w), "r"(b0), "r"(b1));
}

__device__ __forceinline__ float gelu_f(float v) {
    return 0.5f * v * (1.f + erff(v * 0.70710678118654752f));
}

__device__ __forceinline__ void gemm_main(float acc[2][6][4], const uint4* As4,
                                          const uint4* Bs4, int mg, int nh, int lane) {
#pragma unroll
    for (int m = 0; m < 2; ++m)
#pragma unroll
        for (int j = 0; j < 6; ++j)
#pragma unroll
            for (int i = 0; i < 4; ++i) acc[m][j][i] = 0.f;
#pragma unroll
    for (int kt = 0; kt < 6; ++kt) {
        uint4 a0 = As4[(kt * 8 + mg * 2) * 32 + lane];
        uint4 a1 = As4[(kt * 8 + mg * 2 + 1) * 32 + lane];
        uint4 b0 = Bs4[(kt * 6 + nh * 3) * 33 + lane];
        uint4 b1 = Bs4[(kt * 6 + nh * 3 + 1) * 33 + lane];
        uint4 b2 = Bs4[(kt * 6 + nh * 3 + 2) * 33 + lane];
        mma16(acc[0][0], a0, b0.x, b0.y); mma16(acc[0][1], a0, b0.z, b0.w);
        mma16(acc[0][2], a0, b1.x, b1.y); mma16(acc[0][3], a0, b1.z, b1.w);
        mma16(acc[0][4], a0, b2.x, b2.y); mma16(acc[0][5], a0, b2.z, b2.w);
        mma16(acc[1][0], a1, b0.x, b0.y); mma16(acc[1][1], a1, b0.z, b0.w);
        mma16(acc[1][2], a1, b1.x, b1.y); mma16(acc[1][3], a1, b1.z, b1.w);
        mma16(acc[1][4], a1, b2.x, b2.y); mma16(acc[1][5], a1, b2.z, b2.w);
    }
}

// coalesced vectorized B staging (see R12)
__device__ __forceinline__ void stage_B(__half* Bsh, const float* W, int ldw,
                                        int ncol0, int tid, int kmax) {
    for (int idx = tid; idx < 96 * 24; idx += 256) {
        int k = idx / 24;
        int q = idx - k * 24;
        int n = q * 4;
        float4 v = make_float4(0.f, 0.f, 0.f, 0.f);
        if (k < kmax) v = __ldg((const float4*)(W + (size_t)k * ldw + ncol0 + n));
        int kt = k >> 4, kk = k & 15;
        int tig = (kk >> 1) & 3, clo = kk >> 3, half = k & 1;
        float vv[4] = {v.x, v.y, v.z, v.w};
#pragma unroll
        for (int e = 0; e < 4; ++e) {
            int nn = n + e;
            int gid = nn & 7, jp = nn >> 4, chi = (nn >> 3) & 1;
            int word = ((kt * 6 + jp) * 33 + gid * 4 + tig) * 4 + (chi * 2 + clo);
            Bsh[word * 2 + half] = __float2half(vv[e]);
        }
    }
}

__device__ __forceinline__ void stage_A_half(unsigned* As, const __half* A,
                                             int row0, int tid) {
    const int row = tid >> 1, sub = tid & 1;
    const int mt = row >> 4, r16 = row & 15;
    const int gid8 = r16 & 7, rowhi = r16 >> 3;
    const uint4* ap = (const uint4*)(A + (size_t)(row0 + row) * 96 + sub * 48);
#pragma unroll
    for (int j = 0; j < 6; ++j) {
        uint4 u = __ldg(&ap[j]);
        unsigned w[4] = {u.x, u.y, u.z, u.w};
#pragma unroll
        for (int wi = 0; wi < 4; ++wi) {
            int P = sub * 24 + j * 4 + wi;
            int kt = P >> 3, hi = (P >> 2) & 1, tg = P & 3;
            As[(((kt * 8 + mt) * 32) + (gid8 << 2) + tg) * 4 + (rowhi | (hi << 1))] = w[wi];
        }
    }
}

// ---------------------------------------------------------------------------
// generic GEMM: LNF/GELU/EPI/DUAL/NCH/MULTI (unchanged from R12)
// ---------------------------------------------------------------------------
template <class TA, class TO, bool LNF, bool GELU, int EPI, bool DUAL, int NCH, bool MULTI>
__global__ __launch_bounds__(256, 3) void gemm_tc(const TA* __restrict__ A,
                                                  const float* __restrict__ W,
                                                  const float* __restrict__ W2,
                                                  const float* __restrict__ bias,
                                                  const float* __restrict__ lng,
                                                  const float* __restrict__ lnb,
                                                  const TA* __restrict__ res,
                                                  TO* __restrict__ out,
                                                  TO* __restrict__ out2, int ldw) {
    constexpr bool TAH = (sizeof(TA) == 2);
    constexpr bool TOH = (sizeof(TO) == 2);
    __shared__ uint4 As4[AS_U4];
    __shared__ uint4 Bs4[BS_U4];
    unsigned* As = (unsigned*)As4;
    const int tid = threadIdx.x, lane = tid & 31, warp = tid >> 5;
    const int row0 = blockIdx.x * 128;
    int ncbase = 0;
    if (MULTI) {
        int s = (blockIdx.x < BLK0) ? 0 : (blockIdx.x < BLK01) ? 1 : 2;
        W += (size_t)s * 96 * ldw;
        if (bias) bias += s * 96;
        if (LNF) { lng += s * 96; lnb += s * 96; }
    } else if (DUAL) {
        if (blockIdx.y) { W = W2; out = out2; }
    } else if (NCH == 1) {
        ncbase = blockIdx.y * 96;
    }

    stage_B((__half*)Bs4, W, ldw, ncbase, tid, 96);

    if constexpr (TAH && !LNF) {
        stage_A_half(As, (const __half*)A, row0, tid);
    } else {
        const int row = tid >> 1, sub = tid & 1;
        const int mt = row >> 4, r16 = row & 15;
        const int gid8 = r16 & 7, rowhi = r16 >> 3;
        float4 vals[12];
        if constexpr (TAH) {
            const uint4* ap = (const uint4*)((const __half*)A + (size_t)(row0 + row) * 96 + sub * 48);
#pragma unroll
            for (int j = 0; j < 6; ++j) {
                uint4 u = __ldg(&ap[j]);
                __half2* h2 = (__half2*)&u;
                float2 f0 = __half22float2(h2[0]);
                float2 f1 = __half22float2(h2[1]);
                float2 f2v = __half22float2(h2[2]);
                float2 f3 = __half22float2(h2[3]);
                vals[2 * j] = make_float4(f0.x, f0.y, f1.x, f1.y);
                vals[2 * j + 1] = make_float4(f2v.x, f2v.y, f3.x, f3.y);
            }
        } else {
            const float* ap = (const float*)A + (size_t)(row0 + row) * 96 + sub * 48;
#pragma unroll
            for (int j = 0; j < 12; ++j) vals[j] = __ldg((const float4*)(ap + j * 4));
        }
        float mean = 0.f, rstd = 0.f;
        if (LNF) {
            float s = 0.f, s2 = 0.f;
#pragma unroll
            for (int j = 0; j < 12; ++j) {
                float4 v = vals[j];
                s += v.x + v.y + v.z + v.w;
                s2 += v.x * v.x + v.y * v.y + v.z * v.z + v.w * v.w;
            }
            s += __shfl_xor_sync(0xffffffffu, s, 1);
            s2 += __shfl_xor_sync(0xffffffffu, s2, 1);
            mean = s * (1.f / 96.f);
            float var = fmaf(-mean, mean, s2 * (1.f / 96.f));
            rstd = rsqrtf(var + 1e-5f);
        }
#pragma unroll
        for (int j = 0; j < 12; ++j) {
            int k0 = sub * 48 + j * 4;
            float4 v = vals[j];
            if (LNF) {
                float4 g = __ldg((const float4*)(lng + k0));
                float4 bb = __ldg((const float4*)(lnb + k0));
                v.x = (v.x - mean) * rstd * g.x + bb.x;
                v.y = (v.y - mean) * rstd * g.y + bb.y;
                v.z = (v.z - mean) * rstd * g.z + bb.z;
                v.w = (v.w - mean) * rstd * g.w + bb.w;
            }
            int kt = k0 >> 4, kk = k0 & 15;
            int hi = kk >> 3, tig = (kk & 7) >> 1;
            unsigned base = (((kt * 8 + mt) * 32) + (gid8 << 2) + tig) * 4;
            As[base + (rowhi | (hi << 1))] = f2h2(v.x, v.y);
            As[base + 4 + (rowhi | (hi << 1))] = f2h2(v.z, v.w);
        }
    }
    __syncthreads();

    const int mg = warp & 3, nh = warp >> 2;
    const int gid = lane >> 2, tig = lane & 3;
    float acc[2][6][4];

#pragma unroll
    for (int ch = 0; ch < NCH; ++ch) {
        if (ch > 0) {
            __syncthreads();
            stage_B((__half*)Bs4, W, ldw, ch * 96, tid, 96);
            __syncthreads();
        }
        gemm_main(acc, As4, Bs4, mg, nh, lane);
        const int ncol0 = (NCH > 1) ? ch * 96 : ncbase;

#pragma unroll
        for (int m = 0; m < 2; ++m) {
            int rr = row0 + (mg * 2 + m) * 16 + gid;
#pragma unroll
            for (int j = 0; j < 6; ++j) {
                int nc = ncol0 + (nh * 6 + j) * 8 + tig * 2;
                float bx = 0.f, by = 0.f;
                if (bias) {
                    float2 bv = *(const float2*)&bias[nc];
                    bx = bv.x; by = bv.y;
                }
                float x0 = acc[m][j][0] + bx, x1 = acc[m][j][1] + by;
                float x2 = acc[m][j][2] + bx, x3 = acc[m][j][3] + by;
                if (GELU) { x0 = gelu_f(x0); x1 = gelu_f(x1); x2 = gelu_f(x2); x3 = gelu_f(x3); }
                if constexpr (TOH) {
                    __half2* p0 = (__half2*)((__half*)out + (size_t)rr * ldw + nc);
                    __half2* p1 = (__half2*)((__half*)out + (size_t)(rr + 8) * ldw + nc);
                    if constexpr (EPI == 1) {
                        float2 o0 = __half22float2(*p0), o1 = __half22float2(*p1);
                        x0 += o0.x; x1 += o0.y; x2 += o1.x; x3 += o1.y;
                    }
                    *p0 = __floats2half2_rn(x0, x1);
                    *p1 = __floats2half2_rn(x2, x3);
                } else {
                    float* p0 = (float*)out + (size_t)rr * ldw + nc;
                    float* p1 = (float*)out + (size_t)(rr + 8) * ldw + nc;
                    if constexpr (EPI == 0) {
                        *(float2*)p0 = make_float2(x0, x1);
                        *(float2*)p1 = make_float2(x2, x3);
                    } else if constexpr (EPI == 1) {
                        float2 o0 = *(float2*)p0, o1 = *(float2*)p1;
                        *(float2*)p0 = make_float2(o0.x + x0, o0.y + x1);
                        *(float2*)p1 = make_float2(o1.x + x2, o1.y + x3);
                    } else {
                        float2 r0 = __half22float2(*(const __half2*)((const __half*)res + (size_t)rr * 96 + nc));
                        float2 r1 = __half22float2(*(const __half2*)((const __half*)res + (size_t)(rr + 8) * 96 + nc));
                        *(float2*)p0 = make_float2(r0.x + x0, r0.y + x1);
                        *(float2*)p1 = make_float2(r1.x + x2, r1.y + x3);
                    }
                }
            }
        }
    }
}

// ---------------------------------------------------------------------------
// FUSED TAIL (unchanged from R12)
// ---------------------------------------------------------------------------
__global__ __launch_bounds__(256) void resff_final(const __half* __restrict__ co,
                                                   const __half* __restrict__ t0,
                                                   float* __restrict__ out,
                                                   const float* __restrict__ Wo,
                                                   const float* __restrict__ bo,
                                                   const float* __restrict__ lng,
                                                   const float* __restrict__ lnb,
                                                   const float* __restrict__ W1,
                                                   const float* __restrict__ b1,
                                                   const float* __restrict__ W2,
                                                   const float* __restrict__ b2) {
    extern __shared__ float dyn[];
    float* Tf = dyn;
    unsigned* As = (unsigned*)(dyn + 128 * TF_LD);
    unsigned* Bs = As + AS_U4 * 4;
    uint4* As4 = (uint4*)As;
    uint4* Bs4 = (uint4*)Bs;
    const int tid = threadIdx.x, lane = tid & 31, warp = tid >> 5;
    const int row0 = blockIdx.x * 128;
    const int mg = warp & 3, nh = warp >> 2;
    const int gid = lane >> 2, tig = lane & 3;
    float acc[2][6][4];

    stage_A_half(As, co, row0, tid);
    stage_B((__half*)Bs4, Wo, 96, 0, tid, 96);
    __syncthreads();
    gemm_main(acc, As4, Bs4, mg, nh, lane);

#pragma unroll
    for (int m = 0; m < 2; ++m) {
        int rl = (mg * 2 + m) * 16 + gid;
#pragma unroll
        for (int j = 0; j < 6; ++j) {
            int nc = (nh * 6 + j) * 8 + tig * 2;
            float2 bv = *(const float2*)&bo[nc];
            float2 r0 = __half22float2(*(const __half2*)(t0 + (size_t)(row0 + rl) * 96 + nc));
            float2 r1 = __half22float2(*(const __half2*)(t0 + (size_t)(row0 + rl + 8) * 96 + nc));
            *(float2*)&Tf[rl * TF_LD + nc] =
                make_float2(acc[m][j][0] + bv.x + r0.x, acc[m][j][1] + bv.y + r0.y);
            *(float2*)&Tf[(rl + 8) * TF_LD + nc] =
                make_float2(acc[m][j][2] + bv.x + r1.x, acc[m][j][3] + bv.y + r1.y);
        }
    }
    __syncthreads();

    {
        const int row = tid >> 1, sub = tid & 1;
        const int mt = row >> 4, r16 = row & 15;
        const int gid8 = r16 & 7, rowhi = r16 >> 3;
        const float* ap = Tf + row * TF_LD + sub * 48;
        float4 vals[12];
#pragma unroll
        for (int j = 0; j < 12; ++j) vals[j] = *(const float4*)(ap + j * 4);
        float s = 0.f, s2 = 0.f;
#pragma unroll
        for (int j = 0; j < 12; ++j) {
            float4 v = vals[j];
            s += v.x + v.y + v.z + v.w;
            s2 += v.x * v.x + v.y * v.y + v.z * v.z + v.w * v.w;
        }
        s += __shfl_xor_sync(0xffffffffu, s, 1);
        s2 += __shfl_xor_sync(0xffffffffu, s2, 1);
        float mean = s * (1.f / 96.f);
        float var = fmaf(-mean, mean, s2 * (1.f / 96.f));
        float rstd = rsqrtf(var + 1e-5f);
#pragma unroll
        for (int j = 0; j < 12; ++j) {
            int k0 = sub * 48 + j * 4;
            float4 v = vals[j];
            float4 g = __ldg((const float4*)(lng + k0));
            float4 bb = __ldg((const float4*)(lnb + k0));
            v.x = (v.x - mean) * rstd * g.x + bb.x;
            v.y = (v.y - mean) * rstd * g.y + bb.y;
            v.z = (v.z - mean) * rstd * g.z + bb.z;
            v.w = (v.w - mean) * rstd * g.w + bb.w;
            int kt = k0 >> 4, kk = k0 & 15;
            int hi = kk >> 3, tg = (kk & 7) >> 1;
            unsigned base = (((kt * 8 + mt) * 32) + (gid8 << 2) + tg) * 4;
            As[base + (rowhi | (hi << 1))] = f2h2(v.x, v.y);
            As[base + 4 + (rowhi | (hi << 1))] = f2h2(v.z, v.w);
        }
    }
    stage_B((__half*)Bs4, W1, 96, 0, tid, 96);
    __syncthreads();
    gemm_main(acc, As4, Bs4, mg, nh, lane);
    __syncthreads();

#pragma unroll
    for (int m = 0; m < 2; ++m) {
        int mt2 = mg * 2 + m;
#pragma unroll
        for (int j = 0; j < 6; ++j) {
            int col8 = nh * 6 + j;
            int kt = col8 >> 1, hi = col8 & 1;
            int k0 = col8 * 8 + tig * 2;
            float2 bv = *(const float2*)&b1[k0];
            float x0 = gelu_f(acc[m][j][0] + bv.x), x1 = gelu_f(acc[m][j][1] + bv.y);
            float x2 = gelu_f(acc[m][j][2] + bv.x), x3 = gelu_f(acc[m][j][3] + bv.y);
            unsigned base = (((kt * 8 + mt2) * 32) + (gid << 2) + tig) * 4;
            As[base + (hi << 1)] = f2h2(x0, x1);
            As[base + 1 + (hi << 1)] = f2h2(x2, x3);
        }
    }
    stage_B((__half*)Bs4, W2, 96, 0, tid, 96);
    __syncthreads();
    gemm_main(acc, As4, Bs4, mg, nh, lane);

#pragma unroll
    for (int m = 0; m < 2; ++m) {
        int rl = (mg * 2 + m) * 16 + gid;
#pragma unroll
        for (int j = 0; j < 6; ++j) {
            int nc = (nh * 6 + j) * 8 + tig * 2;
            float2 bv = *(const float2*)&b2[nc];
            float2 t0v = *(const float2*)&Tf[rl * TF_LD + nc];
            float2 t1v = *(const float2*)&Tf[(rl + 8) * TF_LD + nc];
            *(float2*)&out[(size_t)(row0 + rl) * 96 + nc] =
                make_float2(acc[m][j][0] + bv.x + t0v.x, acc[m][j][1] + bv.y + t0v.y);
            *(float2*)&out[(size_t)(row0 + rl + 8) * 96 + nc] =
                make_float2(acc[m][j][2] + bv.x + t1v.x, acc[m][j][3] + bv.y + t1v.y);
        }
    }
}

// ---------------------------------------------------------------------------
// patch merge (unchanged from R12)
// ---------------------------------------------------------------------------
template <int DF, int KTOT, int WOUT>
__device__ __forceinline__ void patch_body(const float* __restrict__ x,
                                           const float* __restrict__ w,
                                           const float* __restrict__ bias,
                                           __half* __restrict__ out,
                                           int blk, uint4* As4, uint4* Bs4) {
    constexpr int KPAD = (KTOT + 15) & ~15;
    unsigned* As = (unsigned*)As4;
    const int tid = threadIdx.x, lane = tid & 31, warp = tid >> 5;
    const int row0 = blk * 128;
    const int T = WOUT * WOUT;
    const int mg = warp & 3, nh = warp >> 2;

    float acc[2][6][4];
#pragma unroll
    for (int m = 0; m < 2; ++m)
#pragma unroll
        for (int j = 0; j < 6; ++j)
#pragma unroll
            for (int i = 0; i < 4; ++i) acc[m][j][i] = 0.f;

    for (int kc = 0; kc < KPAD; kc += 96) {
        const int cl = (KPAD - kc) < 96 ? (KPAD - kc) : 96;
        const int nkt = cl >> 4;

        stage_B((__half*)Bs4, w + (size_t)kc * 96, 96, 0, tid, KTOT - kc);
        {
            const int row = tid >> 1, sub = tid & 1;
            const int tok = row0 + row;
            const int b = tok / T, hw = tok - b * T;
            const int h = hw / WOUT, ww = hw - h * WOUT;
            const int mt = row >> 4, r16 = row & 15;
            const int gid8 = r16 & 7, rowhi = r16 >> 3;
#pragma unroll
            for (int j = 0; j < 12; ++j) {
                int k0 = sub * 48 + j * 4;
                if (k0 >= cl) break;
                float v[4];
#pragma unroll
                for (int e = 0; e < 4; ++e) {
                    int f = kc + k0 + e;
                    float vv = 0.f;
                    if (f < KTOT) {
                        int c2 = f / (DF * DF), rem = f - c2 * DF * DF;
                        int ki = rem / DF, kj = rem - ki * DF;
                        vv = __ldg(&x[((b * 3 + c2) * 224 + h * DF + ki) * 224 + ww * DF + kj]);
                    }
                    v[e] = vv;
                }
                int kt = k0 >> 4, kk = k0 & 15;
                int hi = kk >> 3, tig = (kk & 7) >> 1;
                unsigned base = (((kt * 8 + mt) * 32) + (gid8 << 2) + tig) * 4;
                As[base + (rowhi | (hi << 1))] = f2h2(v[0], v[1]);
                As[base + 4 + (rowhi | (hi << 1))] = f2h2(v[2], v[3]);
            }
        }
        __syncthreads();

        for (int kt = 0; kt < nkt; ++kt) {
            uint4 a0 = As4[(kt * 8 + mg * 2) * 32 + lane];
            uint4 a1 = As4[(kt * 8 + mg * 2 + 1) * 32 + lane];
            uint4 b0 = Bs4[(kt * 6 + nh * 3) * 33 + lane];
            uint4 b1 = Bs4[(kt * 6 + nh * 3 + 1) * 33 + lane];
            uint4 b2 = Bs4[(kt * 6 + nh * 3 + 2) * 33 + lane];
            mma16(acc[0][0], a0, b0.x, b0.y); mma16(acc[0][1], a0, b0.z, b0.w);
            mma16(acc[0][2], a0, b1.x, b1.y); mma16(acc[0][3], a0, b1.z, b1.w);
            mma16(acc[0][4], a0, b2.x, b2.y); mma16(acc[0][5], a0, b2.z, b2.w);
            mma16(acc[1][0], a1, b0.x, b0.y); mma16(acc[1][1], a1, b0.z, b0.w);
            mma16(acc[1][2], a1, b1.x, b1.y); mma16(acc[1][3], a1, b1.z, b1.w);
            mma16(acc[1][4], a1, b2.x, b2.y); mma16(acc[1][5], a1, b2.z, b2.w);
        }
        __syncthreads();
    }

    const int gid = lane >> 2, tig = lane & 3;
#pragma unroll
    for (int m = 0; m < 2; ++m) {
        int rr = row0 + (mg * 2 + m) * 16 + gid;
#pragma unroll
        for (int j = 0; j < 6; ++j) {
            int nc = (nh * 6 + j) * 8 + tig * 2;
            float2 bv = *(const float2*)&bias[nc];
            *(__half2*)&out[(size_t)rr * 96 + nc] =
                __floats2half2_rn(acc[m][j][0] + bv.x, acc[m][j][1] + bv.y);
            *(__half2*)&out[(size_t)(rr + 8) * 96 + nc] =
                __floats2half2_rn(acc[m][j][2] + bv.x, acc[m][j][3] + bv.y);
        }
    }
}

__global__ __launch_bounds__(256, 3) void patch_all(
    const float* __restrict__ x,
    const float* __restrict__ pw0, const float* __restrict__ pb0,
    const float* __restrict__ pw1, const float* __restrict__ pb1,
    const float* __restrict__ pw2, const float* __restrict__ pb2,
    __half* __restrict__ t) {
    __shared__ uint4 As4[AS_U4];
    __shared__ uint4 Bs4[BS_U4];
    int blk = blockIdx.x;
    if (blk < BLK0)
        patch_body<16, 768, 14>(x, pw0, pb0, t, blk, As4, Bs4);
    else if (blk < BLK01)
        patch_body<4, 48, 56>(x, pw1, pb1, t + (size_t)ROWS0 * 96, blk - BLK0, As4, Bs4);
    else
        patch_body<7, 147, 32>(x, pw2, pb2, t + (size_t)(ROWS0 + ROWS1) * 96, blk - BLK01, As4, Bs4);
}

// ---------------------------------------------------------------------------
// window attention body — VECTORIZED: q/k/v rows padded to 36 floats,
// float4 dot products, float4 AV, sS row stride NT+1 when NT even.
// ---------------------------------------------------------------------------
template <int WS>
__device__ __forceinline__ void win_attn_body(const __half* qkv, __half* o,
                                              int Wout, int nw, int rowbase,
                                              int b, int win, float* wsm) {
    constexpr int NT = WS * WS;
    constexpr int RP = 36;                         // row pad (floats), 16B-aligned
    constexpr int SSTR = (NT % 2 == 0) ? NT + 1 : NT;
    float* sq = wsm;
    float* sk = sq + 3 * NT * RP;
    float* sv = sk + 3 * NT * RP;
    float* sS = sv + 3 * NT * RP;
    const int wr = win / nw, wc = win % nw;
    const int t = threadIdx.x;
    const int T = Wout * Wout;
    const float scale = 0.17677669529663687f;  // 1/sqrt(32)

    // load: each window row = 288 halves = 36 uint4; store as 2 float4s
    for (int idx = t; idx < NT * 36; idx += 128) {
        int p = idx / 36, u = idx - p * 36;
        int wi = p / WS, wj = p - wi * WS;
        int r = rowbase + b * T + (wr * WS + wi) * Wout + wc * WS + wj;
        uint4 val = __ldg((const uint4*)(qkv + (size_t)r * 288) + u);
        int sec = u / 12, uu = u - sec * 12;
        int head = uu >> 2, c0 = (uu & 3) * 8;
        float* dst = (sec == 0 ? sq : sec == 1 ? sk : sv) + (head * NT + p) * RP + c0;
        __half2* h2 = (__half2*)&val;
        float2 f0 = __half22float2(h2[0]);
        float2 f1 = __half22float2(h2[1]);
        float2 f2 = __half22float2(h2[2]);
        float2 f3 = __half22float2(h2[3]);
        *(float4*)dst = make_float4(f0.x, f0.y, f1.x, f1.y);
        *(float4*)(dst + 4) = make_float4(f2.x, f2.y, f3.x, f3.y);
    }
    __syncthreads();

    // QK^T: float4 dot products
    for (int idx = t; idx < 3 * NT * NT; idx += 128) {
        int h = idx / (NT * NT);
        int ij = idx - h * NT * NT;
        int i = ij / NT, j = ij - i * NT;
        const float4* qi = (const float4*)(sq + (h * NT + i) * RP);
        const float4* kj = (const float4*)(sk + (h * NT + j) * RP);
        float s = 0.f;
#pragma unroll
        for (int v = 0; v < 8; ++v) {
            float4 a = qi[v], c = kj[v];
            s = fmaf(a.x, c.x, s); s = fmaf(a.y, c.y, s);
            s = fmaf(a.z, c.z, s); s = fmaf(a.w, c.w, s);
        }
        sS[(h * NT + i) * SSTR + j] = s * scale;
    }
    __syncthreads();

    // softmax (rows padded -> conflict-free)
    for (int row = t; row < 3 * NT; row += 128) {
        float* p = sS + row * SSTR;
        float m = -1e30f;
        for (int j = 0; j < NT; ++j) m = fmaxf(m, p[j]);
        float Z = 0.f;
        for (int j = 0; j < NT; ++j) {
            float e = __expf(p[j] - m);
            p[j] = e;
            Z += e;
        }
        float inv = 1.f / Z;
        for (int j = 0; j < NT; ++j) p[j] *= inv;
    }
    __syncthreads();

    // AV: one float4 (4 channels) per work item
    for (int idx = t; idx < 3 * NT * 8; idx += 128) {
        int h = idx / (NT * 8);
        int rest = idx - h * NT * 8;
        int i = rest >> 3, cq = rest & 7;
        const float* pw = sS + (h * NT + i) * SSTR;
        const float4* vb = (const float4*)(sv + h * NT * RP) + cq;
        float4 acc = make_float4(0.f, 0.f, 0.f, 0.f);
        for (int j = 0; j < NT; ++j) {
            float w = pw[j];
            float4 v = vb[j * (RP / 4)];
            acc.x = fmaf(w, v.x, acc.x); acc.y = fmaf(w, v.y, acc.y);
            acc.z = fmaf(w, v.z, acc.z); acc.w = fmaf(w, v.w, acc.w);
        }
        int wi = i / WS, wj = i - wi * WS;
        int r = rowbase + b * T + (wr * WS + wi) * Wout + wc * WS + wj;
        __half2* op = (__half2*)(o + (size_t)r * 96 + h * 32 + cq * 4);
        op[0] = __floats2half2_rn(acc.x, acc.y);
        op[1] = __floats2half2_rn(acc.z, acc.w);
    }
}

__global__ __launch_bounds__(128) void win7_k(const __half* __restrict__ qkv,
                                              __half* __restrict__ o) {
    extern __shared__ float wsm[];
    int b = blockIdx.x / 4, win = blockIdx.x % 4;
    win_attn_body<7>(qkv, o, 14, 2, 0, b, win, wsm);
}

__global__ __launch_bounds__(128) void win4m_k(const __half* __restrict__ qkv,
                                               __half* __restrict__ o) {
    extern __shared__ float wsm[];
    int blk = blockIdx.x;
    if (blk < 64 * 196) {
        int b = blk / 196, win = blk % 196;
        win_attn_body<4>(qkv, o, 56, 14, ROWS0, b, win, wsm);
    } else {
        blk -= 64 * 196;
        int b = blk / 64, win = blk % 64;
        win_attn_body<4>(qkv, o, 32, 8, ROWS0 + ROWS1, b, win, wsm);
    }
}

// ---------------------------------------------------------------------------
// neighbor gather + LN (unchanged from R12)
// ---------------------------------------------------------------------------
__global__ __launch_bounds__(256) void gather_ln_k(const __half* __restrict__ t1,
                                                   const __half* __restrict__ t2,
                                                   const float* __restrict__ g,
                                                   const float* __restrict__ bb,
                                                   __half* __restrict__ kv) {
    const int bl = blockIdx.x;
    const int b = bl / 196, l = bl % 196;
    const int i1 = l / 14, j1 = l % 14;
    __shared__ float s1[16 * 100];
    __shared__ float s2[9 * 100];
    const int tid = threadIdx.x, warp = tid >> 5, lane = tid & 31;

    for (int idx = tid; idx < 16 * 12; idx += 256) {
        int p = idx / 12, q = idx - p * 12;
        int ki = p >> 2, kj = p & 3;
        uint4 u = __ldg((const uint4*)(t1 +
            (size_t)((b * 56 + i1 * 4 + ki) * 56 + j1 * 4 + kj) * 96) + q);
        __half2* h2 = (__half2*)&u;
        float* dst = &s1[p * 100 + q * 8];
#pragma unroll
        for (int e = 0; e < 4; ++e) {
            float2 f = __half22float2(h2[e]);
            dst[2 * e] = f.x;
            dst[2 * e + 1] = f.y;
        }
    }
    for (int idx = tid; idx < 9 * 12; idx += 256) {
        int p = idx / 12, q = idx - p * 12;
        int ki = p / 3, kj = p - ki * 3;
        int rr = i1 * 3 + ki - 5, cc = j1 * 3 + kj - 5;
        float* dst = &s2[p * 100 + q * 8];
        if (rr >= 0 && rr < 32 && cc >= 0 && cc < 32) {
            uint4 u = __ldg((const uint4*)(t2 + (size_t)((b * 32 + rr) * 32 + cc) * 96) + q);
            __half2* h2 = (__half2*)&u;
#pragma unroll
            for (int e = 0; e < 4; ++e) {
                float2 f = __half22float2(h2[e]);
                dst[2 * e] = f.x;
                dst[2 * e + 1] = f.y;
            }
        } else {
#pragma unroll
            for (int e = 0; e < 8; ++e) dst[e] = 0.f;
        }
    }
    __syncthreads();

    float gv[3], bv[3];
#pragma unroll
    for (int i = 0; i < 3; ++i) {
        gv[i] = __ldg(&g[lane + 32 * i]);
        bv[i] = __ldg(&bb[lane + 32 * i]);
    }

    for (int k = warp; k < 25; k += 8) {
        float v[3];
#pragma unroll
        for (int i = 0; i < 3; ++i) {
            int c = lane + 32 * i;
            if (k < 16) {
                int F = k * 96 + c;
                v[i] = s1[(F & 15) * 100 + (F >> 4)];
            } else {
                int F = (k - 16) * 96 + c;
                v[i] = s2[(F % 9) * 100 + (F / 9)];
            }
        }
        float s = v[0] + v[1] + v[2];
        float q = v[0] * v[0] + v[1] * v[1] + v[2] * v[2];
#pragma unroll
        for (int off = 16; off > 0; off >>= 1) {
            s += __shfl_xor_sync(0xffffffffu, s, off);
            q += __shfl_xor_sync(0xffffffffu, q, off);
        }
        float mean = s * (1.f / 96.f);
        float var = fmaf(-mean, mean, q * (1.f / 96.f));
        float rstd = rsqrtf(var + 1e-5f);
        __half* dst = kv + ((size_t)bl * 25 + k) * 96;
#pragma unroll
        for (int i = 0; i < 3; ++i)
            dst[lane + 32 * i] = __float2half((v[i] - mean) * rstd * gv[i] + bv[i]);
    }
}

// ---------------------------------------------------------------------------
// cross attention (unchanged from R12)
// ---------------------------------------------------------------------------
__global__ __launch_bounds__(128) void cross_attn_k(const __half* __restrict__ q,
                                                    const __half* __restrict__ kbuf,
                                                    const __half* __restrict__ vbuf,
                                                    __half* __restrict__ o) {
    const int rl = blockIdx.x;
    __shared__ __half hk[2400], hv[2400];
    __shared__ float sqf[96], ss[25];
    const int t = threadIdx.x;

    const uint4* ksrc = (const uint4*)(kbuf + (size_t)rl * 2400);
    const uint4* vsrc = (const uint4*)(vbuf + (size_t)rl * 2400);
    for (int idx = t; idx < 300; idx += 128) {
        ((uint4*)hk)[idx] = __ldg(ksrc + idx);
        ((uint4*)hv)[idx] = __ldg(vsrc + idx);
    }
    if (t < 96) sqf[t] = __half2float(__ldg(q + (size_t)rl * 96 + t));
    __syncthreads();

    if (t < 25) {
        const __half* kr = hk + t * 96;
        float s = 0.f;
#pragma unroll 8
        for (int c = 0; c < 96; ++c) s = fmaf(sqf[c], __half2float(kr[c]), s);
        ss[t] = s * 0.10206207261596575f;
    }
    __syncthreads();

    if (t < 96) {
        float m = -1e30f;
#pragma unroll
        for (int k = 0; k < 25; ++k) m = fmaxf(m, ss[k]);
        float Z = 0.f, acc = 0.f;
#pragma unroll
        for (int k = 0; k < 25; ++k) {
            float e = __expf(ss[k] - m);
            Z += e;
            acc = fmaf(e, __half2float(hv[k * 96 + t]), acc);
        }
        o[(size_t)rl * 96 + t] = __float2half(acc / Z);
    }
}

// ---------------------------------------------------------------------------
extern "C" void kernel_launch(void* const* d_in, const int* in_sizes, int n_in,
                              void* d_out, int out_size) {
    const float* x       = (const float*)d_in[0];
    const float* pw0     = (const float*)d_in[1];
    const float* pb0     = (const float*)d_in[2];
    const float* pw1     = (const float*)d_in[3];
    const float* pb1     = (const float*)d_in[4];
    const float* pw2     = (const float*)d_in[5];
    const float* pb2     = (const float*)d_in[6];
    const float* wa_ln_g = (const float*)d_in[7];
    const float* wa_ln_b = (const float*)d_in[8];
    const float* wa_qkv  = (const float*)d_in[9];
    const float* wa_ow   = (const float*)d_in[10];
    const float* wa_ob   = (const float*)d_in[11];
    const float* ff_ln_g = (const float*)d_in[12];
    const float* ff_ln_b = (const float*)d_in[13];
    const float* ff_w1   = (const float*)d_in[14];
    const float* ff_b1   = (const float*)d_in[15];
    const float* ff_w2   = (const float*)d_in[16];
    const float* ff_b2   = (const float*)d_in[17];
    const float* lnn_g   = (const float*)d_in[18];
    const float* lnn_b   = (const float*)d_in[19];
    const float* ca_wq   = (const float*)d_in[20];
    const float* ca_wk   = (const float*)d_in[21];
    const float* ca_wv   = (const float*)d_in[22];
    const float* ca_wo   = (const float*)d_in[23];
    const float* ca_bo   = (const float*)d_in[24];
    const float* fi_ln_g = (const float*)d_in[25];
    const float* fi_ln_b = (const float*)d_in[26];
    const float* fi_w1   = (const float*)d_in[27];
    const float* fi_b1   = (const float*)d_in[28];
    const float* fi_w2   = (const float*)d_in[29];
    const float* fi_b2   = (const float*)d_in[30];
    float* out = (float*)d_out;

    __half *t, *qkv, *ob, *kv, *kk, *vv, *qq, *co;
    cudaGetSymbolAddress((void**)&t, g_t);
    cudaGetSymbolAddress((void**)&qkv, g_qkv);
    cudaGetSymbolAddress((void**)&ob, g_ob);
    cudaGetSymbolAddress((void**)&kv, g_kv);
    cudaGetSymbolAddress((void**)&kk, g_k);
    cudaGetSymbolAddress((void**)&vv, g_v);
    cudaGetSymbolAddress((void**)&qq, g_q);
    cudaGetSymbolAddress((void**)&co, g_co);

    __half* t0 = t;
    __half* t1 = t + (size_t)ROWS0 * 96;
    __half* t2 = t + (size_t)(ROWS0 + ROWS1) * 96;

    // smem: q/k/v rows padded to 36 floats; sS rows padded to NT+1 when even
    const int WSM7 = (3 * 49 * 36 * 3 + 3 * 49 * 49) * 4;   // 92316
    const int WSM4 = (3 * 16 * 36 * 3 + 3 * 16 * 17) * 4;   // 23996-ish
    cudaFuncSetAttribute(win7_k, cudaFuncAttributeMaxDynamicSharedMemorySize, WSM7);
    cudaFuncSetAttribute(win4m_k, cudaFuncAttributeMaxDynamicSharedMemorySize, WSM4);
    cudaFuncSetAttribute(resff_final, cudaFuncAttributeMaxDynamicSharedMemorySize, RES_SMEM);

    // all patch merges in one launch
    patch_all<<<RTOT / 128, 256>>>(x, pw0, pb0, pw1, pb1, pw2, pb2, t);

    // merged per-scale transformer
    gemm_tc<__half, __half, true, false, 0, false, 3, true><<<RTOT / 128, 256>>>(
        t, wa_qkv, nullptr, nullptr, wa_ln_g, wa_ln_b, nullptr, qkv, nullptr, 288);
    win7_k<<<64 * 4, 128, WSM7>>>(qkv, ob);
    win4m_k<<<64 * 196 + 64 * 64, 128, WSM4>>>(qkv, ob);
    gemm_tc<__half, __half, false, false, 1, false, 1, true><<<RTOT / 128, 256>>>(
        ob, wa_ow, nullptr, wa_ob, nullptr, nullptr, nullptr, t, nullptr, 96);
    gemm_tc<__half, __half, true, true, 0, false, 1, true><<<RTOT / 128, 256>>>(
        t, ff_w1, nullptr, ff_b1, ff_ln_g, ff_ln_b, nullptr, ob, nullptr, 96);
    gemm_tc<__half, __half, false, false, 1, false, 1, true><<<RTOT / 128, 256>>>(
        ob, ff_w2, nullptr, ff_b2, nullptr, nullptr, nullptr, t, nullptr, 96);

    // cross-attention fusion
    gather_ln_k<<<64 * 196, 256>>>(t1, t2, lnn_g, lnn_b, kv);
    gemm_tc<__half, __half, false, false, 0, true, 1, false><<<dim3(KVROWS / 128, 2), 256>>>(
        kv, ca_wk, ca_wv, nullptr, nullptr, nullptr, nullptr, kk, vv, 96);
    gemm_tc<__half, __half, true, false, 0, false, 1, false><<<ROWS0 / 128, 256>>>(
        t0, ca_wq, nullptr, nullptr, lnn_g, lnn_b, nullptr, qq, nullptr, 96);
    cross_attn_k<<<12544, 128>>>(qq, kk, vv, co);
    resff_final<<<ROWS0 / 128, 256, RES_SMEM>>>(
        co, t0, out, ca_wo, ca_bo, fi_ln_g, fi_ln_b, fi_w1, fi_b1, fi_w2, fi_b2);
}

// round 14
// speedup vs baseline: 1.5299x; 1.0725x over previous
#include <cuda_runtime.h>
#include <cuda_fp16.h>
#include <math.h>

// ---------------------------------------------------------------------------
// MultiScaleCrossAttn — fp16 MMA GEMMs, scale-merged launches,
// coalesced B staging, fp16-resident tiled window attention, fused tail
// ---------------------------------------------------------------------------

#define ROWS0 12544      // 64*14*14
#define ROWS1 200704     // 64*56*56
#define ROWS2 65536      // 64*32*32
#define RTOT  278784
#define KVROWS 313600    // 64*196*25

#define BLK0 98          // ROWS0/128
#define BLK01 1666       // (ROWS0+ROWS1)/128

__device__ __align__(16) __half g_t[RTOT * 96];
__device__ __align__(16) __half g_qkv[RTOT * 288];
__device__ __align__(16) __half g_ob[RTOT * 96];
__device__ __align__(16) __half g_kv[KVROWS * 96];
__device__ __align__(16) __half g_k[KVROWS * 96];
__device__ __align__(16) __half g_v[KVROWS * 96];
__device__ __align__(16) __half g_q[ROWS0 * 96];
__device__ __align__(16) __half g_co[ROWS0 * 96];

static constexpr int AS_U4 = 6 * 8 * 32;    // 24576 B
static constexpr int BS_U4 = 36 * 33;       // padded: 19008 B
static constexpr int TF_LD = 100;
static constexpr int RES_SMEM = 128 * TF_LD * 4 + AS_U4 * 16 + BS_U4 * 16;  // 94784

__device__ __forceinline__ unsigned f2h2(float lo, float hi) {
    __half2 h = __floats2half2_rn(lo, hi);
    return *reinterpret_cast<unsigned*>(&h);
}

__device__ __forceinline__ void mma16(float c[4], uint4 a, unsigned b0, unsigned b1) {
    asm volatile(
        "mma.sync.aligned.m16n8k16.row.col.f32.f16.f16.f32 "
        "{%0,%1,%2,%3}, {%4,%5,%6,%7}, {%8,%9}, {%0,%1,%2,%3};\n"
        : "+f"(c[0]), "+f"(c[1]), "+f"(c[2]), "+f"(c[3])
        : "r"(a.x), "r"(a.y), "r"(a.z), "r"(a.w), "r"(b0), "r"(b1));
}

__device__ __forceinline__ float gelu_f(float v) {
    return 0.5f * v * (1.f + erff(v * 0.70710678118654752f));
}

__device__ __forceinline__ void gemm_main(float acc[2][6][4], const uint4* As4,
                                          const uint4* Bs4, int mg, int nh, int lane) {
#pragma unroll
    for (int m = 0; m < 2; ++m)
#pragma unroll
        for (int j = 0; j < 6; ++j)
#pragma unroll
            for (int i = 0; i < 4; ++i) acc[m][j][i] = 0.f;
#pragma unroll
    for (int kt = 0; kt < 6; ++kt) {
        uint4 a0 = As4[(kt * 8 + mg * 2) * 32 + lane];
        uint4 a1 = As4[(kt * 8 + mg * 2 + 1) * 32 + lane];
        uint4 b0 = Bs4[(kt * 6 + nh * 3) * 33 + lane];
        uint4 b1 = Bs4[(kt * 6 + nh * 3 + 1) * 33 + lane];
        uint4 b2 = Bs4[(kt * 6 + nh * 3 + 2) * 33 + lane];
        mma16(acc[0][0], a0, b0.x, b0.y); mma16(acc[0][1], a0, b0.z, b0.w);
        mma16(acc[0][2], a0, b1.x, b1.y); mma16(acc[0][3], a0, b1.z, b1.w);
        mma16(acc[0][4], a0, b2.x, b2.y); mma16(acc[0][5], a0, b2.z, b2.w);
        mma16(acc[1][0], a1, b0.x, b0.y); mma16(acc[1][1], a1, b0.z, b0.w);
        mma16(acc[1][2], a1, b1.x, b1.y); mma16(acc[1][3], a1, b1.z, b1.w);
        mma16(acc[1][4], a1, b2.x, b2.y); mma16(acc[1][5], a1, b2.z, b2.w);
    }
}

// coalesced vectorized B staging (see R12)
__device__ __forceinline__ void stage_B(__half* Bsh, const float* W, int ldw,
                                        int ncol0, int tid, int kmax) {
    for (int idx = tid; idx < 96 * 24; idx += 256) {
        int k = idx / 24;
        int q = idx - k * 24;
        int n = q * 4;
        float4 v = make_float4(0.f, 0.f, 0.f, 0.f);
        if (k < kmax) v = __ldg((const float4*)(W + (size_t)k * ldw + ncol0 + n));
        int kt = k >> 4, kk = k & 15;
        int tig = (kk >> 1) & 3, clo = kk >> 3, half = k & 1;
        float vv[4] = {v.x, v.y, v.z, v.w};
#pragma unroll
        for (int e = 0; e < 4; ++e) {
            int nn = n + e;
            int gid = nn & 7, jp = nn >> 4, chi = (nn >> 3) & 1;
            int word = ((kt * 6 + jp) * 33 + gid * 4 + tig) * 4 + (chi * 2 + clo);
            Bsh[word * 2 + half] = __float2half(vv[e]);
        }
    }
}

__device__ __forceinline__ void stage_A_half(unsigned* As, const __half* A,
                                             int row0, int tid) {
    const int row = tid >> 1, sub = tid & 1;
    const int mt = row >> 4, r16 = row & 15;
    const int gid8 = r16 & 7, rowhi = r16 >> 3;
    const uint4* ap = (const uint4*)(A + (size_t)(row0 + row) * 96 + sub * 48);
#pragma unroll
    for (int j = 0; j < 6; ++j) {
        uint4 u = __ldg(&ap[j]);
        unsigned w[4] = {u.x, u.y, u.z, u.w};
#pragma unroll
        for (int wi = 0; wi < 4; ++wi) {
            int P = sub * 24 + j * 4 + wi;
            int kt = P >> 3, hi = (P >> 2) & 1, tg = P & 3;
            As[(((kt * 8 + mt) * 32) + (gid8 << 2) + tg) * 4 + (rowhi | (hi << 1))] = w[wi];
        }
    }
}

// ---------------------------------------------------------------------------
// generic GEMM: LNF/GELU/EPI/DUAL/NCH/MULTI (unchanged from R13)
// ---------------------------------------------------------------------------
template <class TA, class TO, bool LNF, bool GELU, int EPI, bool DUAL, int NCH, bool MULTI>
__global__ __launch_bounds__(256, 3) void gemm_tc(const TA* __restrict__ A,
                                                  const float* __restrict__ W,
                                                  const float* __restrict__ W2,
                                                  const float* __restrict__ bias,
                                                  const float* __restrict__ lng,
                                                  const float* __restrict__ lnb,
                                                  const TA* __restrict__ res,
                                                  TO* __restrict__ out,
                                                  TO* __restrict__ out2, int ldw) {
    constexpr bool TAH = (sizeof(TA) == 2);
    constexpr bool TOH = (sizeof(TO) == 2);
    __shared__ uint4 As4[AS_U4];
    __shared__ uint4 Bs4[BS_U4];
    unsigned* As = (unsigned*)As4;
    const int tid = threadIdx.x, lane = tid & 31, warp = tid >> 5;
    const int row0 = blockIdx.x * 128;
    int ncbase = 0;
    if (MULTI) {
        int s = (blockIdx.x < BLK0) ? 0 : (blockIdx.x < BLK01) ? 1 : 2;
        W += (size_t)s * 96 * ldw;
        if (bias) bias += s * 96;
        if (LNF) { lng += s * 96; lnb += s * 96; }
    } else if (DUAL) {
        if (blockIdx.y) { W = W2; out = out2; }
    } else if (NCH == 1) {
        ncbase = blockIdx.y * 96;
    }

    stage_B((__half*)Bs4, W, ldw, ncbase, tid, 96);

    if constexpr (TAH && !LNF) {
        stage_A_half(As, (const __half*)A, row0, tid);
    } else {
        const int row = tid >> 1, sub = tid & 1;
        const int mt = row >> 4, r16 = row & 15;
        const int gid8 = r16 & 7, rowhi = r16 >> 3;
        float4 vals[12];
        if constexpr (TAH) {
            const uint4* ap = (const uint4*)((const __half*)A + (size_t)(row0 + row) * 96 + sub * 48);
#pragma unroll
            for (int j = 0; j < 6; ++j) {
                uint4 u = __ldg(&ap[j]);
                __half2* h2 = (__half2*)&u;
                float2 f0 = __half22float2(h2[0]);
                float2 f1 = __half22float2(h2[1]);
                float2 f2v = __half22float2(h2[2]);
                float2 f3 = __half22float2(h2[3]);
                vals[2 * j] = make_float4(f0.x, f0.y, f1.x, f1.y);
                vals[2 * j + 1] = make_float4(f2v.x, f2v.y, f3.x, f3.y);
            }
        } else {
            const float* ap = (const float*)A + (size_t)(row0 + row) * 96 + sub * 48;
#pragma unroll
            for (int j = 0; j < 12; ++j) vals[j] = __ldg((const float4*)(ap + j * 4));
        }
        float mean = 0.f, rstd = 0.f;
        if (LNF) {
            float s = 0.f, s2 = 0.f;
#pragma unroll
            for (int j = 0; j < 12; ++j) {
                float4 v = vals[j];
                s += v.x + v.y + v.z + v.w;
                s2 += v.x * v.x + v.y * v.y + v.z * v.z + v.w * v.w;
            }
            s += __shfl_xor_sync(0xffffffffu, s, 1);
            s2 += __shfl_xor_sync(0xffffffffu, s2, 1);
            mean = s * (1.f / 96.f);
            float var = fmaf(-mean, mean, s2 * (1.f / 96.f));
            rstd = rsqrtf(var + 1e-5f);
        }
#pragma unroll
        for (int j = 0; j < 12; ++j) {
            int k0 = sub * 48 + j * 4;
            float4 v = vals[j];
            if (LNF) {
                float4 g = __ldg((const float4*)(lng + k0));
                float4 bb = __ldg((const float4*)(lnb + k0));
                v.x = (v.x - mean) * rstd * g.x + bb.x;
                v.y = (v.y - mean) * rstd * g.y + bb.y;
                v.z = (v.z - mean) * rstd * g.z + bb.z;
                v.w = (v.w - mean) * rstd * g.w + bb.w;
            }
            int kt = k0 >> 4, kk = k0 & 15;
            int hi = kk >> 3, tig = (kk & 7) >> 1;
            unsigned base = (((kt * 8 + mt) * 32) + (gid8 << 2) + tig) * 4;
            As[base + (rowhi | (hi << 1))] = f2h2(v.x, v.y);
            As[base + 4 + (rowhi | (hi << 1))] = f2h2(v.z, v.w);
        }
    }
    __syncthreads();

    const int mg = warp & 3, nh = warp >> 2;
    const int gid = lane >> 2, tig = lane & 3;
    float acc[2][6][4];

#pragma unroll
    for (int ch = 0; ch < NCH; ++ch) {
        if (ch > 0) {
            __syncthreads();
            stage_B((__half*)Bs4, W, ldw, ch * 96, tid, 96);
            __syncthreads();
        }
        gemm_main(acc, As4, Bs4, mg, nh, lane);
        const int ncol0 = (NCH > 1) ? ch * 96 : ncbase;

#pragma unroll
        for (int m = 0; m < 2; ++m) {
            int rr = row0 + (mg * 2 + m) * 16 + gid;
#pragma unroll
            for (int j = 0; j < 6; ++j) {
                int nc = ncol0 + (nh * 6 + j) * 8 + tig * 2;
                float bx = 0.f, by = 0.f;
                if (bias) {
                    float2 bv = *(const float2*)&bias[nc];
                    bx = bv.x; by = bv.y;
                }
                float x0 = acc[m][j][0] + bx, x1 = acc[m][j][1] + by;
                float x2 = acc[m][j][2] + bx, x3 = acc[m][j][3] + by;
                if (GELU) { x0 = gelu_f(x0); x1 = gelu_f(x1); x2 = gelu_f(x2); x3 = gelu_f(x3); }
                if constexpr (TOH) {
                    __half2* p0 = (__half2*)((__half*)out + (size_t)rr * ldw + nc);
                    __half2* p1 = (__half2*)((__half*)out + (size_t)(rr + 8) * ldw + nc);
                    if constexpr (EPI == 1) {
                        float2 o0 = __half22float2(*p0), o1 = __half22float2(*p1);
                        x0 += o0.x; x1 += o0.y; x2 += o1.x; x3 += o1.y;
                    }
                    *p0 = __floats2half2_rn(x0, x1);
                    *p1 = __floats2half2_rn(x2, x3);
                } else {
                    float* p0 = (float*)out + (size_t)rr * ldw + nc;
                    float* p1 = (float*)out + (size_t)(rr + 8) * ldw + nc;
                    if constexpr (EPI == 0) {
                        *(float2*)p0 = make_float2(x0, x1);
                        *(float2*)p1 = make_float2(x2, x3);
                    } else if constexpr (EPI == 1) {
                        float2 o0 = *(float2*)p0, o1 = *(float2*)p1;
                        *(float2*)p0 = make_float2(o0.x + x0, o0.y + x1);
                        *(float2*)p1 = make_float2(o1.x + x2, o1.y + x3);
                    } else {
                        float2 r0 = __half22float2(*(const __half2*)((const __half*)res + (size_t)rr * 96 + nc));
                        float2 r1 = __half22float2(*(const __half2*)((const __half*)res + (size_t)(rr + 8) * 96 + nc));
                        *(float2*)p0 = make_float2(r0.x + x0, r0.y + x1);
                        *(float2*)p1 = make_float2(r1.x + x2, r1.y + x3);
                    }
                }
            }
        }
    }
}

// ---------------------------------------------------------------------------
// FUSED TAIL (unchanged from R13)
// ---------------------------------------------------------------------------
__global__ __launch_bounds__(256) void resff_final(const __half* __restrict__ co,
                                                   const __half* __restrict__ t0,
                                                   float* __restrict__ out,
                                                   const float* __restrict__ Wo,
                                                   const float* __restrict__ bo,
                                                   const float* __restrict__ lng,
                                                   const float* __restrict__ lnb,
                                                   const float* __restrict__ W1,
                                                   const float* __restrict__ b1,
                                                   const float* __restrict__ W2,
                                                   const float* __restrict__ b2) {
    extern __shared__ float dyn[];
    float* Tf = dyn;
    unsigned* As = (unsigned*)(dyn + 128 * TF_LD);
    unsigned* Bs = As + AS_U4 * 4;
    uint4* As4 = (uint4*)As;
    uint4* Bs4 = (uint4*)Bs;
    const int tid = threadIdx.x, lane = tid & 31, warp = tid >> 5;
    const int row0 = blockIdx.x * 128;
    const int mg = warp & 3, nh = warp >> 2;
    const int gid = lane >> 2, tig = lane & 3;
    float acc[2][6][4];

    stage_A_half(As, co, row0, tid);
    stage_B((__half*)Bs4, Wo, 96, 0, tid, 96);
    __syncthreads();
    gemm_main(acc, As4, Bs4, mg, nh, lane);

#pragma unroll
    for (int m = 0; m < 2; ++m) {
        int rl = (mg * 2 + m) * 16 + gid;
#pragma unroll
        for (int j = 0; j < 6; ++j) {
            int nc = (nh * 6 + j) * 8 + tig * 2;
            float2 bv = *(const float2*)&bo[nc];
            float2 r0 = __half22float2(*(const __half2*)(t0 + (size_t)(row0 + rl) * 96 + nc));
            float2 r1 = __half22float2(*(const __half2*)(t0 + (size_t)(row0 + rl + 8) * 96 + nc));
            *(float2*)&Tf[rl * TF_LD + nc] =
                make_float2(acc[m][j][0] + bv.x + r0.x, acc[m][j][1] + bv.y + r0.y);
            *(float2*)&Tf[(rl + 8) * TF_LD + nc] =
                make_float2(acc[m][j][2] + bv.x + r1.x, acc[m][j][3] + bv.y + r1.y);
        }
    }
    __syncthreads();

    {
        const int row = tid >> 1, sub = tid & 1;
        const int mt = row >> 4, r16 = row & 15;
        const int gid8 = r16 & 7, rowhi = r16 >> 3;
        const float* ap = Tf + row * TF_LD + sub * 48;
        float4 vals[12];
#pragma unroll
        for (int j = 0; j < 12; ++j) vals[j] = *(const float4*)(ap + j * 4);
        float s = 0.f, s2 = 0.f;
#pragma unroll
        for (int j = 0; j < 12; ++j) {
            float4 v = vals[j];
            s += v.x + v.y + v.z + v.w;
            s2 += v.x * v.x + v.y * v.y + v.z * v.z + v.w * v.w;
        }
        s += __shfl_xor_sync(0xffffffffu, s, 1);
        s2 += __shfl_xor_sync(0xffffffffu, s2, 1);
        float mean = s * (1.f / 96.f);
        float var = fmaf(-mean, mean, s2 * (1.f / 96.f));
        float rstd = rsqrtf(var + 1e-5f);
#pragma unroll
        for (int j = 0; j < 12; ++j) {
            int k0 = sub * 48 + j * 4;
            float4 v = vals[j];
            float4 g = __ldg((const float4*)(lng + k0));
            float4 bb = __ldg((const float4*)(lnb + k0));
            v.x = (v.x - mean) * rstd * g.x + bb.x;
            v.y = (v.y - mean) * rstd * g.y + bb.y;
            v.z = (v.z - mean) * rstd * g.z + bb.z;
            v.w = (v.w - mean) * rstd * g.w + bb.w;
            int kt = k0 >> 4, kk = k0 & 15;
            int hi = kk >> 3, tg = (kk & 7) >> 1;
            unsigned base = (((kt * 8 + mt) * 32) + (gid8 << 2) + tg) * 4;
            As[base + (rowhi | (hi << 1))] = f2h2(v.x, v.y);
            As[base + 4 + (rowhi | (hi << 1))] = f2h2(v.z, v.w);
        }
    }
    stage_B((__half*)Bs4, W1, 96, 0, tid, 96);
    __syncthreads();
    gemm_main(acc, As4, Bs4, mg, nh, lane);
    __syncthreads();

#pragma unroll
    for (int m = 0; m < 2; ++m) {
        int mt2 = mg * 2 + m;
#pragma unroll
        for (int j = 0; j < 6; ++j) {
            int col8 = nh * 6 + j;
            int kt = col8 >> 1, hi = col8 & 1;
            int k0 = col8 * 8 + tig * 2;
            float2 bv = *(const float2*)&b1[k0];
            float x0 = gelu_f(acc[m][j][0] + bv.x), x1 = gelu_f(acc[m][j][1] + bv.y);
            float x2 = gelu_f(acc[m][j][2] + bv.x), x3 = gelu_f(acc[m][j][3] + bv.y);
            unsigned base = (((kt * 8 + mt2) * 32) + (gid << 2) + tig) * 4;
            As[base + (hi << 1)] = f2h2(x0, x1);
            As[base + 1 + (hi << 1)] = f2h2(x2, x3);
        }
    }
    stage_B((__half*)Bs4, W2, 96, 0, tid, 96);
    __syncthreads();
    gemm_main(acc, As4, Bs4, mg, nh, lane);

#pragma unroll
    for (int m = 0; m < 2; ++m) {
        int rl = (mg * 2 + m) * 16 + gid;
#pragma unroll
        for (int j = 0; j < 6; ++j) {
            int nc = (nh * 6 + j) * 8 + tig * 2;
            float2 bv = *(const float2*)&b2[nc];
            float2 t0v = *(const float2*)&Tf[rl * TF_LD + nc];
            float2 t1v = *(const float2*)&Tf[(rl + 8) * TF_LD + nc];
            *(float2*)&out[(size_t)(row0 + rl) * 96 + nc] =
                make_float2(acc[m][j][0] + bv.x + t0v.x, acc[m][j][1] + bv.y + t0v.y);
            *(float2*)&out[(size_t)(row0 + rl + 8) * 96 + nc] =
                make_float2(acc[m][j][2] + bv.x + t1v.x, acc[m][j][3] + bv.y + t1v.y);
        }
    }
}

// ---------------------------------------------------------------------------
// patch merge (unchanged from R13)
// ---------------------------------------------------------------------------
template <int DF, int KTOT, int WOUT>
__device__ __forceinline__ void patch_body(const float* __restrict__ x,
                                           const float* __restrict__ w,
                                           const float* __restrict__ bias,
                                           __half* __restrict__ out,
                                           int blk, uint4* As4, uint4* Bs4) {
    constexpr int KPAD = (KTOT + 15) & ~15;
    unsigned* As = (unsigned*)As4;
    const int tid = threadIdx.x, lane = tid & 31, warp = tid >> 5;
    const int row0 = blk * 128;
    const int T = WOUT * WOUT;
    const int mg = warp & 3, nh = warp >> 2;

    float acc[2][6][4];
#pragma unroll
    for (int m = 0; m < 2; ++m)
#pragma unroll
        for (int j = 0; j < 6; ++j)
#pragma unroll
            for (int i = 0; i < 4; ++i) acc[m][j][i] = 0.f;

    for (int kc = 0; kc < KPAD; kc += 96) {
        const int cl = (KPAD - kc) < 96 ? (KPAD - kc) : 96;
        const int nkt = cl >> 4;

        stage_B((__half*)Bs4, w + (size_t)kc * 96, 96, 0, tid, KTOT - kc);
        {
            const int row = tid >> 1, sub = tid & 1;
            const int tok = row0 + row;
            const int b = tok / T, hw = tok - b * T;
            const int h = hw / WOUT, ww = hw - h * WOUT;
            const int mt = row >> 4, r16 = row & 15;
            const int gid8 = r16 & 7, rowhi = r16 >> 3;
#pragma unroll
            for (int j = 0; j < 12; ++j) {
                int k0 = sub * 48 + j * 4;
                if (k0 >= cl) break;
                float v[4];
#pragma unroll
                for (int e = 0; e < 4; ++e) {
                    int f = kc + k0 + e;
                    float vv = 0.f;
                    if (f < KTOT) {
                        int c2 = f / (DF * DF), rem = f - c2 * DF * DF;
                        int ki = rem / DF, kj = rem - ki * DF;
                        vv = __ldg(&x[((b * 3 + c2) * 224 + h * DF + ki) * 224 + ww * DF + kj]);
                    }
                    v[e] = vv;
                }
                int kt = k0 >> 4, kk = k0 & 15;
                int hi = kk >> 3, tig = (kk & 7) >> 1;
                unsigned base = (((kt * 8 + mt) * 32) + (gid8 << 2) + tig) * 4;
                As[base + (rowhi | (hi << 1))] = f2h2(v[0], v[1]);
                As[base + 4 + (rowhi | (hi << 1))] = f2h2(v[2], v[3]);
            }
        }
        __syncthreads();

        for (int kt = 0; kt < nkt; ++kt) {
            uint4 a0 = As4[(kt * 8 + mg * 2) * 32 + lane];
            uint4 a1 = As4[(kt * 8 + mg * 2 + 1) * 32 + lane];
            uint4 b0 = Bs4[(kt * 6 + nh * 3) * 33 + lane];
            uint4 b1 = Bs4[(kt * 6 + nh * 3 + 1) * 33 + lane];
            uint4 b2 = Bs4[(kt * 6 + nh * 3 + 2) * 33 + lane];
            mma16(acc[0][0], a0, b0.x, b0.y); mma16(acc[0][1], a0, b0.z, b0.w);
            mma16(acc[0][2], a0, b1.x, b1.y); mma16(acc[0][3], a0, b1.z, b1.w);
            mma16(acc[0][4], a0, b2.x, b2.y); mma16(acc[0][5], a0, b2.z, b2.w);
            mma16(acc[1][0], a1, b0.x, b0.y); mma16(acc[1][1], a1, b0.z, b0.w);
            mma16(acc[1][2], a1, b1.x, b1.y); mma16(acc[1][3], a1, b1.z, b1.w);
            mma16(acc[1][4], a1, b2.x, b2.y); mma16(acc[1][5], a1, b2.z, b2.w);
        }
        __syncthreads();
    }

    const int gid = lane >> 2, tig = lane & 3;
#pragma unroll
    for (int m = 0; m < 2; ++m) {
        int rr = row0 + (mg * 2 + m) * 16 + gid;
#pragma unroll
        for (int j = 0; j < 6; ++j) {
            int nc = (nh * 6 + j) * 8 + tig * 2;
            float2 bv = *(const float2*)&bias[nc];
            *(__half2*)&out[(size_t)rr * 96 + nc] =
                __floats2half2_rn(acc[m][j][0] + bv.x, acc[m][j][1] + bv.y);
            *(__half2*)&out[(size_t)(rr + 8) * 96 + nc] =
                __floats2half2_rn(acc[m][j][2] + bv.x, acc[m][j][3] + bv.y);
        }
    }
}

__global__ __launch_bounds__(256, 3) void patch_all(
    const float* __restrict__ x,
    const float* __restrict__ pw0, const float* __restrict__ pb0,
    const float* __restrict__ pw1, const float* __restrict__ pb1,
    const float* __restrict__ pw2, const float* __restrict__ pb2,
    __half* __restrict__ t) {
    __shared__ uint4 As4[AS_U4];
    __shared__ uint4 Bs4[BS_U4];
    int blk = blockIdx.x;
    if (blk < BLK0)
        patch_body<16, 768, 14>(x, pw0, pb0, t, blk, As4, Bs4);
    else if (blk < BLK01)
        patch_body<4, 48, 56>(x, pw1, pb1, t + (size_t)ROWS0 * 96, blk - BLK0, As4, Bs4);
    else
        patch_body<7, 147, 32>(x, pw2, pb2, t + (size_t)(ROWS0 + ROWS1) * 96, blk - BLK01, As4, Bs4);
}

// ---------------------------------------------------------------------------
// window attention — fp16-resident smem, 2x2-tiled QK^T, 2-row x 8-ch AV.
// All math fp32; storage fp16 (same data as qkv buffer -> numerics unchanged).
// ---------------------------------------------------------------------------
__device__ __forceinline__ float dot8h(uint4 a, uint4 c, float s) {
    __half2* ah = (__half2*)&a;
    __half2* ch = (__half2*)&c;
#pragma unroll
    for (int e = 0; e < 4; ++e) {
        float2 x = __half22float2(ah[e]);
        float2 y = __half22float2(ch[e]);
        s = fmaf(x.x, y.x, s);
        s = fmaf(x.y, y.y, s);
    }
    return s;
}

template <int WS>
__device__ __forceinline__ void win_attn_body(const __half* qkv, __half* o,
                                              int Wout, int nw, int rowbase,
                                              int b, int win, char* wsm_raw) {
    constexpr int NT = WS * WS;
    constexpr int RPH = 40;                          // halves per row (pad); 80B stride
    constexpr int SSTR = (NT % 2 == 0) ? NT + 1 : NT;
    constexpr int IT2 = (NT + 1) / 2;
    __half* hq = (__half*)wsm_raw;
    __half* hk = hq + 3 * NT * RPH;
    __half* hv = hk + 3 * NT * RPH;
    float* sS = (float*)(hv + 3 * NT * RPH);
    const int wr = win / nw, wc = win % nw;
    const int t = threadIdx.x;
    const int T = Wout * Wout;
    const float scale = 0.17677669529663687f;  // 1/sqrt(32)

    // load: each window row = 36 uint4; store verbatim (fp16-resident)
    for (int idx = t; idx < NT * 36; idx += 128) {
        int p = idx / 36, u = idx - p * 36;
        int wi = p / WS, wj = p - wi * WS;
        int r = rowbase + b * T + (wr * WS + wi) * Wout + wc * WS + wj;
        uint4 val = __ldg((const uint4*)(qkv + (size_t)r * 288) + u);
        int sec = u / 12, uu = u - sec * 12;
        int head = uu >> 2, c0 = (uu & 3) * 8;
        __half* dst = (sec == 0 ? hq : sec == 1 ? hk : hv) + (head * NT + p) * RPH + c0;
        *(uint4*)dst = val;
    }
    __syncthreads();

    // QK^T: 2x2 tiles, 16B loads of fp16 rows
    for (int idx = t; idx < 3 * IT2 * IT2; idx += 128) {
        int h = idx / (IT2 * IT2);
        int r = idx - h * IT2 * IT2;
        int i0 = (r / IT2) * 2, j0 = (r % IT2) * 2;
        bool i1ok = (i0 + 1 < NT), j1ok = (j0 + 1 < NT);
        const uint4* qa = (const uint4*)(hq + (h * NT + i0) * RPH);
        const uint4* qb = (const uint4*)(hq + (h * NT + (i1ok ? i0 + 1 : i0)) * RPH);
        const uint4* ka = (const uint4*)(hk + (h * NT + j0) * RPH);
        const uint4* kb = (const uint4*)(hk + (h * NT + (j1ok ? j0 + 1 : j0)) * RPH);
        float s00 = 0.f, s01 = 0.f, s10 = 0.f, s11 = 0.f;
#pragma unroll
        for (int v = 0; v < 4; ++v) {
            uint4 A0 = qa[v], A1 = qb[v], C0 = ka[v], C1 = kb[v];
            s00 = dot8h(A0, C0, s00);
            s01 = dot8h(A0, C1, s01);
            s10 = dot8h(A1, C0, s10);
            s11 = dot8h(A1, C1, s11);
        }
        float* sr0 = sS + (h * NT + i0) * SSTR;
        sr0[j0] = s00 * scale;
        if (j1ok) sr0[j0 + 1] = s01 * scale;
        if (i1ok) {
            float* sr1 = sr0 + SSTR;
            sr1[j0] = s10 * scale;
            if (j1ok) sr1[j0 + 1] = s11 * scale;
        }
    }
    __syncthreads();

    // softmax
    for (int row = t; row < 3 * NT; row += 128) {
        float* p = sS + row * SSTR;
        float m = -1e30f;
        for (int j = 0; j < NT; ++j) m = fmaxf(m, p[j]);
        float Z = 0.f;
        for (int j = 0; j < NT; ++j) {
            float e = __expf(p[j] - m);
            p[j] = e;
            Z += e;
        }
        float inv = 1.f / Z;
        for (int j = 0; j < NT; ++j) p[j] *= inv;
    }
    __syncthreads();

    // AV: 2 rows x 8 channels per item
    for (int idx = t; idx < 3 * IT2 * 4; idx += 128) {
        int h = idx / (IT2 * 4);
        int r = idx - h * IT2 * 4;
        int i0 = (r >> 2) * 2, c8 = (r & 3) * 8;
        bool i1ok = (i0 + 1 < NT);
        const float* w0 = sS + (h * NT + i0) * SSTR;
        const float* w1 = sS + (h * NT + (i1ok ? i0 + 1 : i0)) * SSTR;
        float a0[8], a1[8];
#pragma unroll
        for (int e = 0; e < 8; ++e) { a0[e] = 0.f; a1[e] = 0.f; }
        for (int j = 0; j < NT; ++j) {
            uint4 v = *(const uint4*)(hv + (h * NT + j) * RPH + c8);
            float x0 = w0[j], x1 = w1[j];
            __half2* hh = (__half2*)&v;
#pragma unroll
            for (int e = 0; e < 4; ++e) {
                float2 f = __half22float2(hh[e]);
                a0[2 * e] = fmaf(x0, f.x, a0[2 * e]);
                a0[2 * e + 1] = fmaf(x0, f.y, a0[2 * e + 1]);
                a1[2 * e] = fmaf(x1, f.x, a1[2 * e]);
                a1[2 * e + 1] = fmaf(x1, f.y, a1[2 * e + 1]);
            }
        }
        {
            int wi = i0 / WS, wj = i0 - wi * WS;
            int rr = rowbase + b * T + (wr * WS + wi) * Wout + wc * WS + wj;
            uint4 outv;
            __half2* o2 = (__half2*)&outv;
#pragma unroll
            for (int e = 0; e < 4; ++e) o2[e] = __floats2half2_rn(a0[2 * e], a0[2 * e + 1]);
            *(uint4*)(o + (size_t)rr * 96 + h * 32 + c8) = outv;
        }
        if (i1ok) {
            int i1 = i0 + 1;
            int wi = i1 / WS, wj = i1 - wi * WS;
            int rr = rowbase + b * T + (wr * WS + wi) * Wout + wc * WS + wj;
            uint4 outv;
            __half2* o2 = (__half2*)&outv;
#pragma unroll
            for (int e = 0; e < 4; ++e) o2[e] = __floats2half2_rn(a1[2 * e], a1[2 * e + 1]);
            *(uint4*)(o + (size_t)rr * 96 + h * 32 + c8) = outv;
        }
    }
}

__global__ __launch_bounds__(128) void win7_k(const __half* __restrict__ qkv,
                                              __half* __restrict__ o) {
    extern __shared__ __align__(16) char wsm_raw[];
    int b = blockIdx.x / 4, win = blockIdx.x % 4;
    win_attn_body<7>(qkv, o, 14, 2, 0, b, win, wsm_raw);
}

__global__ __launch_bounds__(128) void win4m_k(const __half* __restrict__ qkv,
                                               __half* __restrict__ o) {
    extern __shared__ __align__(16) char wsm_raw[];
    int blk = blockIdx.x;
    if (blk < 64 * 196) {
        int b = blk / 196, win = blk % 196;
        win_attn_body<4>(qkv, o, 56, 14, ROWS0, b, win, wsm_raw);
    } else {
        blk -= 64 * 196;
        int b = blk / 64, win = blk % 64;
        win_attn_body<4>(qkv, o, 32, 8, ROWS0 + ROWS1, b, win, wsm_raw);
    }
}

// ---------------------------------------------------------------------------
// neighbor gather + LN (unchanged from R13)
// ---------------------------------------------------------------------------
__global__ __launch_bounds__(256) void gather_ln_k(const __half* __restrict__ t1,
                                                   const __half* __restrict__ t2,
                                                   const float* __restrict__ g,
                                                   const float* __restrict__ bb,
                                                   __half* __restrict__ kv) {
    const int bl = blockIdx.x;
    const int b = bl / 196, l = bl % 196;
    const int i1 = l / 14, j1 = l % 14;
    __shared__ float s1[16 * 100];
    __shared__ float s2[9 * 100];
    const int tid = threadIdx.x, warp = tid >> 5, lane = tid & 31;

    for (int idx = tid; idx < 16 * 12; idx += 256) {
        int p = idx / 12, q = idx - p * 12;
        int ki = p >> 2, kj = p & 3;
        uint4 u = __ldg((const uint4*)(t1 +
            (size_t)((b * 56 + i1 * 4 + ki) * 56 + j1 * 4 + kj) * 96) + q);
        __half2* h2 = (__half2*)&u;
        float* dst = &s1[p * 100 + q * 8];
#pragma unroll
        for (int e = 0; e < 4; ++e) {
            float2 f = __half22float2(h2[e]);
            dst[2 * e] = f.x;
            dst[2 * e + 1] = f.y;
        }
    }
    for (int idx = tid; idx < 9 * 12; idx += 256) {
        int p = idx / 12, q = idx - p * 12;
        int ki = p / 3, kj = p - ki * 3;
        int rr = i1 * 3 + ki - 5, cc = j1 * 3 + kj - 5;
        float* dst = &s2[p * 100 + q * 8];
        if (rr >= 0 && rr < 32 && cc >= 0 && cc < 32) {
            uint4 u = __ldg((const uint4*)(t2 + (size_t)((b * 32 + rr) * 32 + cc) * 96) + q);
            __half2* h2 = (__half2*)&u;
#pragma unroll
            for (int e = 0; e < 4; ++e) {
                float2 f = __half22float2(h2[e]);
                dst[2 * e] = f.x;
                dst[2 * e + 1] = f.y;
            }
        } else {
#pragma unroll
            for (int e = 0; e < 8; ++e) dst[e] = 0.f;
        }
    }
    __syncthreads();

    float gv[3], bv[3];
#pragma unroll
    for (int i = 0; i < 3; ++i) {
        gv[i] = __ldg(&g[lane + 32 * i]);
        bv[i] = __ldg(&bb[lane + 32 * i]);
    }

    for (int k = warp; k < 25; k += 8) {
        float v[3];
#pragma unroll
        for (int i = 0; i < 3; ++i) {
            int c = lane + 32 * i;
            if (k < 16) {
                int F = k * 96 + c;
                v[i] = s1[(F & 15) * 100 + (F >> 4)];
            } else {
                int F = (k - 16) * 96 + c;
                v[i] = s2[(F % 9) * 100 + (F / 9)];
            }
        }
        float s = v[0] + v[1] + v[2];
        float q = v[0] * v[0] + v[1] * v[1] + v[2] * v[2];
#pragma unroll
        for (int off = 16; off > 0; off >>= 1) {
            s += __shfl_xor_sync(0xffffffffu, s, off);
            q += __shfl_xor_sync(0xffffffffu, q, off);
        }
        float mean = s * (1.f / 96.f);
        float var = fmaf(-mean, mean, q * (1.f / 96.f));
        float rstd = rsqrtf(var + 1e-5f);
        __half* dst = kv + ((size_t)bl * 25 + k) * 96;
#pragma unroll
        for (int i = 0; i < 3; ++i)
            dst[lane + 32 * i] = __float2half((v[i] - mean) * rstd * gv[i] + bv[i]);
    }
}

// ---------------------------------------------------------------------------
// cross attention (unchanged from R13)
// ---------------------------------------------------------------------------
__global__ __launch_bounds__(128) void cross_attn_k(const __half* __restrict__ q,
                                                    const __half* __restrict__ kbuf,
                                                    const __half* __restrict__ vbuf,
                                                    __half* __restrict__ o) {
    const int rl = blockIdx.x;
    __shared__ __half hk[2400], hv[2400];
    __shared__ float sqf[96], ss[25];
    const int t = threadIdx.x;

    const uint4* ksrc = (const uint4*)(kbuf + (size_t)rl * 2400);
    const uint4* vsrc = (const uint4*)(vbuf + (size_t)rl * 2400);
    for (int idx = t; idx < 300; idx += 128) {
        ((uint4*)hk)[idx] = __ldg(ksrc + idx);
        ((uint4*)hv)[idx] = __ldg(vsrc + idx);
    }
    if (t < 96) sqf[t] = __half2float(__ldg(q + (size_t)rl * 96 + t));
    __syncthreads();

    if (t < 25) {
        const __half* kr = hk + t * 96;
        float s = 0.f;
#pragma unroll 8
        for (int c = 0; c < 96; ++c) s = fmaf(sqf[c], __half2float(kr[c]), s);
        ss[t] = s * 0.10206207261596575f;
    }
    __syncthreads();

    if (t < 96) {
        float m = -1e30f;
#pragma unroll
        for (int k = 0; k < 25; ++k) m = fmaxf(m, ss[k]);
        float Z = 0.f, acc = 0.f;
#pragma unroll
        for (int k = 0; k < 25; ++k) {
            float e = __expf(ss[k] - m);
            Z += e;
            acc = fmaf(e, __half2float(hv[k * 96 + t]), acc);
        }
        o[(size_t)rl * 96 + t] = __float2half(acc / Z);
    }
}

// ---------------------------------------------------------------------------
extern "C" void kernel_launch(void* const* d_in, const int* in_sizes, int n_in,
                              void* d_out, int out_size) {
    const float* x       = (const float*)d_in[0];
    const float* pw0     = (const float*)d_in[1];
    const float* pb0     = (const float*)d_in[2];
    const float* pw1     = (const float*)d_in[3];
    const float* pb1     = (const float*)d_in[4];
    const float* pw2     = (const float*)d_in[5];
    const float* pb2     = (const float*)d_in[6];
    const float* wa_ln_g = (const float*)d_in[7];
    const float* wa_ln_b = (const float*)d_in[8];
    const float* wa_qkv  = (const float*)d_in[9];
    const float* wa_ow   = (const float*)d_in[10];
    const float* wa_ob   = (const float*)d_in[11];
    const float* ff_ln_g = (const float*)d_in[12];
    const float* ff_ln_b = (const float*)d_in[13];
    const float* ff_w1   = (const float*)d_in[14];
    const float* ff_b1   = (const float*)d_in[15];
    const float* ff_w2   = (const float*)d_in[16];
    const float* ff_b2   = (const float*)d_in[17];
    const float* lnn_g   = (const float*)d_in[18];
    const float* lnn_b   = (const float*)d_in[19];
    const float* ca_wq   = (const float*)d_in[20];
    const float* ca_wk   = (const float*)d_in[21];
    const float* ca_wv   = (const float*)d_in[22];
    const float* ca_wo   = (const float*)d_in[23];
    const float* ca_bo   = (const float*)d_in[24];
    const float* fi_ln_g = (const float*)d_in[25];
    const float* fi_ln_b = (const float*)d_in[26];
    const float* fi_w1   = (const float*)d_in[27];
    const float* fi_b1   = (const float*)d_in[28];
    const float* fi_w2   = (const float*)d_in[29];
    const float* fi_b2   = (const float*)d_in[30];
    float* out = (float*)d_out;

    __half *t, *qkv, *ob, *kv, *kk, *vv, *qq, *co;
    cudaGetSymbolAddress((void**)&t, g_t);
    cudaGetSymbolAddress((void**)&qkv, g_qkv);
    cudaGetSymbolAddress((void**)&ob, g_ob);
    cudaGetSymbolAddress((void**)&kv, g_kv);
    cudaGetSymbolAddress((void**)&kk, g_k);
    cudaGetSymbolAddress((void**)&vv, g_v);
    cudaGetSymbolAddress((void**)&qq, g_q);
    cudaGetSymbolAddress((void**)&co, g_co);

    __half* t0 = t;
    __half* t1 = t + (size_t)ROWS0 * 96;
    __half* t2 = t + (size_t)(ROWS0 + ROWS1) * 96;

    // smem: q/k/v fp16 rows padded to 40 halves + float sS with padded stride
    const int WSM7 = 3 * 3 * 49 * 40 * 2 + 3 * 49 * 49 * 4;   // 35280 + 28812 = 64092
    const int WSM4 = 3 * 3 * 16 * 40 * 2 + 3 * 16 * 17 * 4;   // 11520 + 3264  = 14784
    cudaFuncSetAttribute(win7_k, cudaFuncAttributeMaxDynamicSharedMemorySize, WSM7);
    cudaFuncSetAttribute(win4m_k, cudaFuncAttributeMaxDynamicSharedMemorySize, WSM4);
    cudaFuncSetAttribute(resff_final, cudaFuncAttributeMaxDynamicSharedMemorySize, RES_SMEM);

    // all patch merges in one launch
    patch_all<<<RTOT / 128, 256>>>(x, pw0, pb0, pw1, pb1, pw2, pb2, t);

    // merged per-scale transformer
    gemm_tc<__half, __half, true, false, 0, false, 3, true><<<RTOT / 128, 256>>>(
        t, wa_qkv, nullptr, nullptr, wa_ln_g, wa_ln_b, nullptr, qkv, nullptr, 288);
    win7_k<<<64 * 4, 128, WSM7>>>(qkv, ob);
    win4m_k<<<64 * 196 + 64 * 64, 128, WSM4>>>(qkv, ob);
    gemm_tc<__half, __half, false, false, 1, false, 1, true><<<RTOT / 128, 256>>>(
        ob, wa_ow, nullptr, wa_ob, nullptr, nullptr, nullptr, t, nullptr, 96);
    gemm_tc<__half, __half, true, true, 0, false, 1, true><<<RTOT / 128, 256>>>(
        t, ff_w1, nullptr, ff_b1, ff_ln_g, ff_ln_b, nullptr, ob, nullptr, 96);
    gemm_tc<__half, __half, false, false, 1, false, 1, true><<<RTOT / 128, 256>>>(
        ob, ff_w2, nullptr, ff_b2, nullptr, nullptr, nullptr, t, nullptr, 96);

    // cross-attention fusion
    gather_ln_k<<<64 * 196, 256>>>(t1, t2, lnn_g, lnn_b, kv);
    gemm_tc<__half, __half, false, false, 0, true, 1, false><<<dim3(KVROWS / 128, 2), 256>>>(
        kv, ca_wk, ca_wv, nullptr, nullptr, nullptr, nullptr, kk, vv, 96);
    gemm_tc<__half, __half, true, false, 0, false, 1, false><<<ROWS0 / 128, 256>>>(
        t0, ca_wq, nullptr, nullptr, lnn_g, lnn_b, nullptr, qq, nullptr, 96);
    cross_attn_k<<<12544, 128>>>(qq, kk, vv, co);
    resff_final<<<ROWS0 / 128, 256, RES_SMEM>>>(
        co, t0, out, ca_wo, ca_bo, fi_ln_g, fi_ln_b, fi_w1, fi_b1, fi_w2, fi_b2);
}

// round 15
// speedup vs baseline: 1.9595x; 1.2808x over previous
#include <cuda_runtime.h>
#include <cuda_fp16.h>
#include <math.h>

// ---------------------------------------------------------------------------
// MultiScaleCrossAttn — fp16 MMA GEMMs, scale-merged launches,
// coalesced B staging, fp16 window attention, fused proj+FF chain (all scales)
// ---------------------------------------------------------------------------

#define ROWS0 12544      // 64*14*14
#define ROWS1 200704     // 64*56*56
#define ROWS2 65536      // 64*32*32
#define RTOT  278784
#define KVROWS 313600    // 64*196*25

#define BLK0 98          // ROWS0/128
#define BLK01 1666       // (ROWS0+ROWS1)/128

__device__ __align__(16) __half g_t[RTOT * 96];
__device__ __align__(16) __half g_qkv[RTOT * 288];
__device__ __align__(16) __half g_ob[RTOT * 96];
__device__ __align__(16) __half g_kv[KVROWS * 96];
__device__ __align__(16) __half g_k[KVROWS * 96];
__device__ __align__(16) __half g_v[KVROWS * 96];
__device__ __align__(16) __half g_q[ROWS0 * 96];
__device__ __align__(16) __half g_co[ROWS0 * 96];

static constexpr int AS_U4 = 6 * 8 * 32;    // 24576 B
static constexpr int BS_U4 = 36 * 33;       // padded: 19008 B
static constexpr int TF_LD = 100;           // fp32 pitch (final tail)
static constexpr int RES_SMEM = 128 * TF_LD * 4 + AS_U4 * 16 + BS_U4 * 16;  // 94784
static constexpr int TFH_LD = 104;          // fp16 pitch (mid chain), 208B rows
static constexpr int RSM_MID = 128 * TFH_LD * 2 + AS_U4 * 16 + BS_U4 * 16;  // 70208

__device__ __forceinline__ unsigned f2h2(float lo, float hi) {
    __half2 h = __floats2half2_rn(lo, hi);
    return *reinterpret_cast<unsigned*>(&h);
}

__device__ __forceinline__ void mma16(float c[4], uint4 a, unsigned b0, unsigned b1) {
    asm volatile(
        "mma.sync.aligned.m16n8k16.row.col.f32.f16.f16.f32 "
        "{%0,%1,%2,%3}, {%4,%5,%6,%7}, {%8,%9}, {%0,%1,%2,%3};\n"
        : "+f"(c[0]), "+f"(c[1]), "+f"(c[2]), "+f"(c[3])
        : "r"(a.x), "r"(a.y), "r"(a.z), "r"(a.w), "r"(b0), "r"(b1));
}

__device__ __forceinline__ float gelu_f(float v) {
    return 0.5f * v * (1.f + erff(v * 0.70710678118654752f));
}

__device__ __forceinline__ void gemm_main(float acc[2][6][4], const uint4* As4,
                                          const uint4* Bs4, int mg, int nh, int lane) {
#pragma unroll
    for (int m = 0; m < 2; ++m)
#pragma unroll
        for (int j = 0; j < 6; ++j)
#pragma unroll
            for (int i = 0; i < 4; ++i) acc[m][j][i] = 0.f;
#pragma unroll
    for (int kt = 0; kt < 6; ++kt) {
        uint4 a0 = As4[(kt * 8 + mg * 2) * 32 + lane];
        uint4 a1 = As4[(kt * 8 + mg * 2 + 1) * 32 + lane];
        uint4 b0 = Bs4[(kt * 6 + nh * 3) * 33 + lane];
        uint4 b1 = Bs4[(kt * 6 + nh * 3 + 1) * 33 + lane];
        uint4 b2 = Bs4[(kt * 6 + nh * 3 + 2) * 33 + lane];
        mma16(acc[0][0], a0, b0.x, b0.y); mma16(acc[0][1], a0, b0.z, b0.w);
        mma16(acc[0][2], a0, b1.x, b1.y); mma16(acc[0][3], a0, b1.z, b1.w);
        mma16(acc[0][4], a0, b2.x, b2.y); mma16(acc[0][5], a0, b2.z, b2.w);
        mma16(acc[1][0], a1, b0.x, b0.y); mma16(acc[1][1], a1, b0.z, b0.w);
        mma16(acc[1][2], a1, b1.x, b1.y); mma16(acc[1][3], a1, b1.z, b1.w);
        mma16(acc[1][4], a1, b2.x, b2.y); mma16(acc[1][5], a1, b2.z, b2.w);
    }
}

// coalesced vectorized B staging
__device__ __forceinline__ void stage_B(__half* Bsh, const float* W, int ldw,
                                        int ncol0, int tid, int kmax) {
    for (int idx = tid; idx < 96 * 24; idx += 256) {
        int k = idx / 24;
        int q = idx - k * 24;
        int n = q * 4;
        float4 v = make_float4(0.f, 0.f, 0.f, 0.f);
        if (k < kmax) v = __ldg((const float4*)(W + (size_t)k * ldw + ncol0 + n));
        int kt = k >> 4, kk = k & 15;
        int tig = (kk >> 1) & 3, clo = kk >> 3, half = k & 1;
        float vv[4] = {v.x, v.y, v.z, v.w};
#pragma unroll
        for (int e = 0; e < 4; ++e) {
            int nn = n + e;
            int gid = nn & 7, jp = nn >> 4, chi = (nn >> 3) & 1;
            int word = ((kt * 6 + jp) * 33 + gid * 4 + tig) * 4 + (chi * 2 + clo);
            Bsh[word * 2 + half] = __float2half(vv[e]);
        }
    }
}

__device__ __forceinline__ void stage_A_half(unsigned* As, const __half* A,
                                             int row0, int tid) {
    const int row = tid >> 1, sub = tid & 1;
    const int mt = row >> 4, r16 = row & 15;
    const int gid8 = r16 & 7, rowhi = r16 >> 3;
    const uint4* ap = (const uint4*)(A + (size_t)(row0 + row) * 96 + sub * 48);
#pragma unroll
    for (int j = 0; j < 6; ++j) {
        uint4 u = __ldg(&ap[j]);
        unsigned w[4] = {u.x, u.y, u.z, u.w};
#pragma unroll
        for (int wi = 0; wi < 4; ++wi) {
            int P = sub * 24 + j * 4 + wi;
            int kt = P >> 3, hi = (P >> 2) & 1, tg = P & 3;
            As[(((kt * 8 + mt) * 32) + (gid8 << 2) + tg) * 4 + (rowhi | (hi << 1))] = w[wi];
        }
    }
}

// shared LN+frag-store from float4 vals (per-row, 2 threads/row)
__device__ __forceinline__ void ln_store_A(unsigned* As, float4 vals[12],
                                           const float* lng, const float* lnb,
                                           int row, int sub) {
    const int mt = row >> 4, r16 = row & 15;
    const int gid8 = r16 & 7, rowhi = r16 >> 3;
    float s = 0.f, s2 = 0.f;
#pragma unroll
    for (int j = 0; j < 12; ++j) {
        float4 v = vals[j];
        s += v.x + v.y + v.z + v.w;
        s2 += v.x * v.x + v.y * v.y + v.z * v.z + v.w * v.w;
    }
    s += __shfl_xor_sync(0xffffffffu, s, 1);
    s2 += __shfl_xor_sync(0xffffffffu, s2, 1);
    float mean = s * (1.f / 96.f);
    float var = fmaf(-mean, mean, s2 * (1.f / 96.f));
    float rstd = rsqrtf(var + 1e-5f);
#pragma unroll
    for (int j = 0; j < 12; ++j) {
        int k0 = sub * 48 + j * 4;
        float4 v = vals[j];
        float4 g = __ldg((const float4*)(lng + k0));
        float4 bb = __ldg((const float4*)(lnb + k0));
        v.x = (v.x - mean) * rstd * g.x + bb.x;
        v.y = (v.y - mean) * rstd * g.y + bb.y;
        v.z = (v.z - mean) * rstd * g.z + bb.z;
        v.w = (v.w - mean) * rstd * g.w + bb.w;
        int kt = k0 >> 4, kk = k0 & 15;
        int hi = kk >> 3, tig = (kk & 7) >> 1;
        unsigned base = (((kt * 8 + mt) * 32) + (gid8 << 2) + tig) * 4;
        As[base + (rowhi | (hi << 1))] = f2h2(v.x, v.y);
        As[base + 4 + (rowhi | (hi << 1))] = f2h2(v.z, v.w);
    }
}

// ---------------------------------------------------------------------------
// generic GEMM: LNF/GELU/EPI/DUAL/NCH/MULTI
// ---------------------------------------------------------------------------
template <class TA, class TO, bool LNF, bool GELU, int EPI, bool DUAL, int NCH, bool MULTI>
__global__ __launch_bounds__(256, 3) void gemm_tc(const TA* __restrict__ A,
                                                  const float* __restrict__ W,
                                                  const float* __restrict__ W2,
                                                  const float* __restrict__ bias,
                                                  const float* __restrict__ lng,
                                                  const float* __restrict__ lnb,
                                                  const TA* __restrict__ res,
                                                  TO* __restrict__ out,
                                                  TO* __restrict__ out2, int ldw) {
    constexpr bool TAH = (sizeof(TA) == 2);
    constexpr bool TOH = (sizeof(TO) == 2);
    __shared__ uint4 As4[AS_U4];
    __shared__ uint4 Bs4[BS_U4];
    unsigned* As = (unsigned*)As4;
    const int tid = threadIdx.x, lane = tid & 31, warp = tid >> 5;
    const int row0 = blockIdx.x * 128;
    int ncbase = 0;
    if (MULTI) {
        int s = (blockIdx.x < BLK0) ? 0 : (blockIdx.x < BLK01) ? 1 : 2;
        W += (size_t)s * 96 * ldw;
        if (bias) bias += s * 96;
        if (LNF) { lng += s * 96; lnb += s * 96; }
    } else if (DUAL) {
        if (blockIdx.y) { W = W2; out = out2; }
    } else if (NCH == 1) {
        ncbase = blockIdx.y * 96;
    }

    stage_B((__half*)Bs4, W, ldw, ncbase, tid, 96);

    if constexpr (TAH && !LNF) {
        stage_A_half(As, (const __half*)A, row0, tid);
    } else {
        const int row = tid >> 1, sub = tid & 1;
        float4 vals[12];
        if constexpr (TAH) {
            const uint4* ap = (const uint4*)((const __half*)A + (size_t)(row0 + row) * 96 + sub * 48);
#pragma unroll
            for (int j = 0; j < 6; ++j) {
                uint4 u = __ldg(&ap[j]);
                __half2* h2 = (__half2*)&u;
                float2 f0 = __half22float2(h2[0]);
                float2 f1 = __half22float2(h2[1]);
                float2 f2v = __half22float2(h2[2]);
                float2 f3 = __half22float2(h2[3]);
                vals[2 * j] = make_float4(f0.x, f0.y, f1.x, f1.y);
                vals[2 * j + 1] = make_float4(f2v.x, f2v.y, f3.x, f3.y);
            }
        } else {
            const float* ap = (const float*)A + (size_t)(row0 + row) * 96 + sub * 48;
#pragma unroll
            for (int j = 0; j < 12; ++j) vals[j] = __ldg((const float4*)(ap + j * 4));
        }
        if (LNF) {
            ln_store_A(As, vals, lng, lnb, row, sub);
        } else {
            const int mt = row >> 4, r16 = row & 15;
            const int gid8 = r16 & 7, rowhi = r16 >> 3;
#pragma unroll
            for (int j = 0; j < 12; ++j) {
                int k0 = sub * 48 + j * 4;
                float4 v = vals[j];
                int kt = k0 >> 4, kk = k0 & 15;
                int hi = kk >> 3, tig = (kk & 7) >> 1;
                unsigned base = (((kt * 8 + mt) * 32) + (gid8 << 2) + tig) * 4;
                As[base + (rowhi | (hi << 1))] = f2h2(v.x, v.y);
                As[base + 4 + (rowhi | (hi << 1))] = f2h2(v.z, v.w);
            }
        }
    }
    __syncthreads();

    const int mg = warp & 3, nh = warp >> 2;
    const int gid = lane >> 2, tig = lane & 3;
    float acc[2][6][4];

#pragma unroll
    for (int ch = 0; ch < NCH; ++ch) {
        if (ch > 0) {
            __syncthreads();
            stage_B((__half*)Bs4, W, ldw, ch * 96, tid, 96);
            __syncthreads();
        }
        gemm_main(acc, As4, Bs4, mg, nh, lane);
        const int ncol0 = (NCH > 1) ? ch * 96 : ncbase;

#pragma unroll
        for (int m = 0; m < 2; ++m) {
            int rr = row0 + (mg * 2 + m) * 16 + gid;
#pragma unroll
            for (int j = 0; j < 6; ++j) {
                int nc = ncol0 + (nh * 6 + j) * 8 + tig * 2;
                float bx = 0.f, by = 0.f;
                if (bias) {
                    float2 bv = *(const float2*)&bias[nc];
                    bx = bv.x; by = bv.y;
                }
                float x0 = acc[m][j][0] + bx, x1 = acc[m][j][1] + by;
                float x2 = acc[m][j][2] + bx, x3 = acc[m][j][3] + by;
                if (GELU) { x0 = gelu_f(x0); x1 = gelu_f(x1); x2 = gelu_f(x2); x3 = gelu_f(x3); }
                if constexpr (TOH) {
                    __half2* p0 = (__half2*)((__half*)out + (size_t)rr * ldw + nc);
                    __half2* p1 = (__half2*)((__half*)out + (size_t)(rr + 8) * ldw + nc);
                    if constexpr (EPI == 1) {
                        float2 o0 = __half22float2(*p0), o1 = __half22float2(*p1);
                        x0 += o0.x; x1 += o0.y; x2 += o1.x; x3 += o1.y;
                    }
                    *p0 = __floats2half2_rn(x0, x1);
                    *p1 = __floats2half2_rn(x2, x3);
                } else {
                    float* p0 = (float*)out + (size_t)rr * ldw + nc;
                    float* p1 = (float*)out + (size_t)(rr + 8) * ldw + nc;
                    if constexpr (EPI == 0) {
                        *(float2*)p0 = make_float2(x0, x1);
                        *(float2*)p1 = make_float2(x2, x3);
                    } else if constexpr (EPI == 1) {
                        float2 o0 = *(float2*)p0, o1 = *(float2*)p1;
                        *(float2*)p0 = make_float2(o0.x + x0, o0.y + x1);
                        *(float2*)p1 = make_float2(o1.x + x2, o1.y + x3);
                    } else {
                        float2 r0 = __half22float2(*(const __half2*)((const __half*)res + (size_t)rr * 96 + nc));
                        float2 r1 = __half22float2(*(const __half2*)((const __half*)res + (size_t)(rr + 8) * 96 + nc));
                        *(float2*)p0 = make_float2(r0.x + x0, r0.y + x1);
                        *(float2*)p1 = make_float2(r1.x + x2, r1.y + x3);
                    }
                }
            }
        }
    }
}

// ---------------------------------------------------------------------------
// FUSED MID CHAIN (all scales): t = fp16(t + ob@Wo + bo);
// t += gelu(LN(t)@W1+b1)@W2 + b2.  Tf fp16 in smem (identical rounding to
// the unfused path, where t was stored fp16 between launches).
// ---------------------------------------------------------------------------
__global__ __launch_bounds__(256, 3) void resff_mid(const __half* __restrict__ ob,
                                                    __half* __restrict__ t,
                                                    const float* __restrict__ Wo,
                                                    const float* __restrict__ bo,
                                                    const float* __restrict__ lng,
                                                    const float* __restrict__ lnb,
                                                    const float* __restrict__ W1,
                                                    const float* __restrict__ b1,
                                                    const float* __restrict__ W2,
                                                    const float* __restrict__ b2) {
    extern __shared__ __align__(16) char dynm[];
    __half* Tf = (__half*)dynm;                         // [128][TFH_LD]
    unsigned* As = (unsigned*)(dynm + 128 * TFH_LD * 2);
    unsigned* Bs = As + AS_U4 * 4;
    uint4* As4 = (uint4*)As;
    uint4* Bs4 = (uint4*)Bs;
    const int tid = threadIdx.x, lane = tid & 31, warp = tid >> 5;
    const int row0 = blockIdx.x * 128;
    const int s = (blockIdx.x < BLK0) ? 0 : (blockIdx.x < BLK01) ? 1 : 2;
    Wo += s * 9216; bo += s * 96; lng += s * 96; lnb += s * 96;
    W1 += s * 9216; b1 += s * 96; W2 += s * 9216; b2 += s * 96;
    const int mg = warp & 3, nh = warp >> 2;
    const int gid = lane >> 2, tig = lane & 3;
    float acc[2][6][4];

    // phase 1: ob @ Wo
    stage_A_half(As, ob, row0, tid);
    stage_B((__half*)Bs4, Wo, 96, 0, tid, 96);
    __syncthreads();
    gemm_main(acc, As4, Bs4, mg, nh, lane);

    // Tf = fp16(acc + bo + t)
#pragma unroll
    for (int m = 0; m < 2; ++m) {
        int rl = (mg * 2 + m) * 16 + gid;
#pragma unroll
        for (int j = 0; j < 6; ++j) {
            int nc = (nh * 6 + j) * 8 + tig * 2;
            float2 bv = *(const float2*)&bo[nc];
            float2 r0 = __half22float2(*(const __half2*)(t + (size_t)(row0 + rl) * 96 + nc));
            float2 r1 = __half22float2(*(const __half2*)(t + (size_t)(row0 + rl + 8) * 96 + nc));
            *(__half2*)&Tf[rl * TFH_LD + nc] =
                __floats2half2_rn(acc[m][j][0] + bv.x + r0.x, acc[m][j][1] + bv.y + r0.y);
            *(__half2*)&Tf[(rl + 8) * TFH_LD + nc] =
                __floats2half2_rn(acc[m][j][2] + bv.x + r1.x, acc[m][j][3] + bv.y + r1.y);
        }
    }
    __syncthreads();

    // phase 2: LN(Tf) @ W1
    {
        const int row = tid >> 1, sub = tid & 1;
        const uint4* ap = (const uint4*)(Tf + row * TFH_LD + sub * 48);
        float4 vals[12];
#pragma unroll
        for (int j = 0; j < 6; ++j) {
            uint4 u = ap[j];
            __half2* h2 = (__half2*)&u;
            float2 f0 = __half22float2(h2[0]);
            float2 f1 = __half22float2(h2[1]);
            float2 f2v = __half22float2(h2[2]);
            float2 f3 = __half22float2(h2[3]);
            vals[2 * j] = make_float4(f0.x, f0.y, f1.x, f1.y);
            vals[2 * j + 1] = make_float4(f2v.x, f2v.y, f3.x, f3.y);
        }
        ln_store_A(As, vals, lng, lnb, row, sub);
    }
    stage_B((__half*)Bs4, W1, 96, 0, tid, 96);
    __syncthreads();
    gemm_main(acc, As4, Bs4, mg, nh, lane);
    __syncthreads();

    // phase 3: h = gelu(acc + b1) -> As (C->A frag map); W2 -> Bs
#pragma unroll
    for (int m = 0; m < 2; ++m) {
        int mt2 = mg * 2 + m;
#pragma unroll
        for (int j = 0; j < 6; ++j) {
            int col8 = nh * 6 + j;
            int kt = col8 >> 1, hi = col8 & 1;
            int k0 = col8 * 8 + tig * 2;
            float2 bv = *(const float2*)&b1[k0];
            float x0 = gelu_f(acc[m][j][0] + bv.x), x1 = gelu_f(acc[m][j][1] + bv.y);
            float x2 = gelu_f(acc[m][j][2] + bv.x), x3 = gelu_f(acc[m][j][3] + bv.y);
            unsigned base = (((kt * 8 + mt2) * 32) + (gid << 2) + tig) * 4;
            As[base + (hi << 1)] = f2h2(x0, x1);
            As[base + 1 + (hi << 1)] = f2h2(x2, x3);
        }
    }
    stage_B((__half*)Bs4, W2, 96, 0, tid, 96);
    __syncthreads();
    gemm_main(acc, As4, Bs4, mg, nh, lane);

    // t = fp16(Tf + acc + b2)
#pragma unroll
    for (int m = 0; m < 2; ++m) {
        int rl = (mg * 2 + m) * 16 + gid;
#pragma unroll
        for (int j = 0; j < 6; ++j) {
            int nc = (nh * 6 + j) * 8 + tig * 2;
            float2 bv = *(const float2*)&b2[nc];
            float2 t0v = __half22float2(*(const __half2*)&Tf[rl * TFH_LD + nc]);
            float2 t1v = __half22float2(*(const __half2*)&Tf[(rl + 8) * TFH_LD + nc]);
            *(__half2*)(t + (size_t)(row0 + rl) * 96 + nc) =
                __floats2half2_rn(acc[m][j][0] + bv.x + t0v.x, acc[m][j][1] + bv.y + t0v.y);
            *(__half2*)(t + (size_t)(row0 + rl + 8) * 96 + nc) =
                __floats2half2_rn(acc[m][j][2] + bv.x + t1v.x, acc[m][j][3] + bv.y + t1v.y);
        }
    }
}

// ---------------------------------------------------------------------------
// FUSED FINAL TAIL (fp32 Tf/out, unchanged numerics)
// ---------------------------------------------------------------------------
__global__ __launch_bounds__(256) void resff_final(const __half* __restrict__ co,
                                                   const __half* __restrict__ t0,
                                                   float* __restrict__ out,
                                                   const float* __restrict__ Wo,
                                                   const float* __restrict__ bo,
                                                   const float* __restrict__ lng,
                                                   const float* __restrict__ lnb,
                                                   const float* __restrict__ W1,
                                                   const float* __restrict__ b1,
                                                   const float* __restrict__ W2,
                                                   const float* __restrict__ b2) {
    extern __shared__ float dyn[];
    float* Tf = dyn;
    unsigned* As = (unsigned*)(dyn + 128 * TF_LD);
    unsigned* Bs = As + AS_U4 * 4;
    uint4* As4 = (uint4*)As;
    uint4* Bs4 = (uint4*)Bs;
    const int tid = threadIdx.x, lane = tid & 31, warp = tid >> 5;
    const int row0 = blockIdx.x * 128;
    const int mg = warp & 3, nh = warp >> 2;
    const int gid = lane >> 2, tig = lane & 3;
    float acc[2][6][4];

    stage_A_half(As, co, row0, tid);
    stage_B((__half*)Bs4, Wo, 96, 0, tid, 96);
    __syncthreads();
    gemm_main(acc, As4, Bs4, mg, nh, lane);

#pragma unroll
    for (int m = 0; m < 2; ++m) {
        int rl = (mg * 2 + m) * 16 + gid;
#pragma unroll
        for (int j = 0; j < 6; ++j) {
            int nc = (nh * 6 + j) * 8 + tig * 2;
            float2 bv = *(const float2*)&bo[nc];
            float2 r0 = __half22float2(*(const __half2*)(t0 + (size_t)(row0 + rl) * 96 + nc));
            float2 r1 = __half22float2(*(const __half2*)(t0 + (size_t)(row0 + rl + 8) * 96 + nc));
            *(float2*)&Tf[rl * TF_LD + nc] =
                make_float2(acc[m][j][0] + bv.x + r0.x, acc[m][j][1] + bv.y + r0.y);
            *(float2*)&Tf[(rl + 8) * TF_LD + nc] =
                make_float2(acc[m][j][2] + bv.x + r1.x, acc[m][j][3] + bv.y + r1.y);
        }
    }
    __syncthreads();

    {
        const int row = tid >> 1, sub = tid & 1;
        const float* ap = Tf + row * TF_LD + sub * 48;
        float4 vals[12];
#pragma unroll
        for (int j = 0; j < 12; ++j) vals[j] = *(const float4*)(ap + j * 4);
        ln_store_A(As, vals, lng, lnb, row, sub);
    }
    stage_B((__half*)Bs4, W1, 96, 0, tid, 96);
    __syncthreads();
    gemm_main(acc, As4, Bs4, mg, nh, lane);
    __syncthreads();

#pragma unroll
    for (int m = 0; m < 2; ++m) {
        int mt2 = mg * 2 + m;
#pragma unroll
        for (int j = 0; j < 6; ++j) {
            int col8 = nh * 6 + j;
            int kt = col8 >> 1, hi = col8 & 1;
            int k0 = col8 * 8 + tig * 2;
            float2 bv = *(const float2*)&b1[k0];
            float x0 = gelu_f(acc[m][j][0] + bv.x), x1 = gelu_f(acc[m][j][1] + bv.y);
            float x2 = gelu_f(acc[m][j][2] + bv.x), x3 = gelu_f(acc[m][j][3] + bv.y);
            unsigned base = (((kt * 8 + mt2) * 32) + (gid << 2) + tig) * 4;
            As[base + (hi << 1)] = f2h2(x0, x1);
            As[base + 1 + (hi << 1)] = f2h2(x2, x3);
        }
    }
    stage_B((__half*)Bs4, W2, 96, 0, tid, 96);
    __syncthreads();
    gemm_main(acc, As4, Bs4, mg, nh, lane);

#pragma unroll
    for (int m = 0; m < 2; ++m) {
        int rl = (mg * 2 + m) * 16 + gid;
#pragma unroll
        for (int j = 0; j < 6; ++j) {
            int nc = (nh * 6 + j) * 8 + tig * 2;
            float2 bv = *(const float2*)&b2[nc];
            float2 t0v = *(const float2*)&Tf[rl * TF_LD + nc];
            float2 t1v = *(const float2*)&Tf[(rl + 8) * TF_LD + nc];
            *(float2*)&out[(size_t)(row0 + rl) * 96 + nc] =
                make_float2(acc[m][j][0] + bv.x + t0v.x, acc[m][j][1] + bv.y + t0v.y);
            *(float2*)&out[(size_t)(row0 + rl + 8) * 96 + nc] =
                make_float2(acc[m][j][2] + bv.x + t1v.x, acc[m][j][3] + bv.y + t1v.y);
        }
    }
}

// ---------------------------------------------------------------------------
// patch merge (unchanged)
// ---------------------------------------------------------------------------
template <int DF, int KTOT, int WOUT>
__device__ __forceinline__ void patch_body(const float* __restrict__ x,
                                           const float* __restrict__ w,
                                           const float* __restrict__ bias,
                                           __half* __restrict__ out,
                                           int blk, uint4* As4, uint4* Bs4) {
    constexpr int KPAD = (KTOT + 15) & ~15;
    unsigned* As = (unsigned*)As4;
    const int tid = threadIdx.x, lane = tid & 31, warp = tid >> 5;
    const int row0 = blk * 128;
    const int T = WOUT * WOUT;
    const int mg = warp & 3, nh = warp >> 2;

    float acc[2][6][4];
#pragma unroll
    for (int m = 0; m < 2; ++m)
#pragma unroll
        for (int j = 0; j < 6; ++j)
#pragma unroll
            for (int i = 0; i < 4; ++i) acc[m][j][i] = 0.f;

    for (int kc = 0; kc < KPAD; kc += 96) {
        const int cl = (KPAD - kc) < 96 ? (KPAD - kc) : 96;
        const int nkt = cl >> 4;

        stage_B((__half*)Bs4, w + (size_t)kc * 96, 96, 0, tid, KTOT - kc);
        {
            const int row = tid >> 1, sub = tid & 1;
            const int tok = row0 + row;
            const int b = tok / T, hw = tok - b * T;
            const int h = hw / WOUT, ww = hw - h * WOUT;
            const int mt = row >> 4, r16 = row & 15;
            const int gid8 = r16 & 7, rowhi = r16 >> 3;
#pragma unroll
            for (int j = 0; j < 12; ++j) {
                int k0 = sub * 48 + j * 4;
                if (k0 >= cl) break;
                float v[4];
#pragma unroll
                for (int e = 0; e < 4; ++e) {
                    int f = kc + k0 + e;
                    float vv = 0.f;
                    if (f < KTOT) {
                        int c2 = f / (DF * DF), rem = f - c2 * DF * DF;
                        int ki = rem / DF, kj = rem - ki * DF;
                        vv = __ldg(&x[((b * 3 + c2) * 224 + h * DF + ki) * 224 + ww * DF + kj]);
                    }
                    v[e] = vv;
                }
                int kt = k0 >> 4, kk = k0 & 15;
                int hi = kk >> 3, tig = (kk & 7) >> 1;
                unsigned base = (((kt * 8 + mt) * 32) + (gid8 << 2) + tig) * 4;
                As[base + (rowhi | (hi << 1))] = f2h2(v[0], v[1]);
                As[base + 4 + (rowhi | (hi << 1))] = f2h2(v[2], v[3]);
            }
        }
        __syncthreads();

        for (int kt = 0; kt < nkt; ++kt) {
            uint4 a0 = As4[(kt * 8 + mg * 2) * 32 + lane];
            uint4 a1 = As4[(kt * 8 + mg * 2 + 1) * 32 + lane];
            uint4 b0 = Bs4[(kt * 6 + nh * 3) * 33 + lane];
            uint4 b1 = Bs4[(kt * 6 + nh * 3 + 1) * 33 + lane];
            uint4 b2 = Bs4[(kt * 6 + nh * 3 + 2) * 33 + lane];
            mma16(acc[0][0], a0, b0.x, b0.y); mma16(acc[0][1], a0, b0.z, b0.w);
            mma16(acc[0][2], a0, b1.x, b1.y); mma16(acc[0][3], a0, b1.z, b1.w);
            mma16(acc[0][4], a0, b2.x, b2.y); mma16(acc[0][5], a0, b2.z, b2.w);
            mma16(acc[1][0], a1, b0.x, b0.y); mma16(acc[1][1], a1, b0.z, b0.w);
            mma16(acc[1][2], a1, b1.x, b1.y); mma16(acc[1][3], a1, b1.z, b1.w);
            mma16(acc[1][4], a1, b2.x, b2.y); mma16(acc[1][5], a1, b2.z, b2.w);
        }
        __syncthreads();
    }

    const int gid = lane >> 2, tig = lane & 3;
#pragma unroll
    for (int m = 0; m < 2; ++m) {
        int rr = row0 + (mg * 2 + m) * 16 + gid;
#pragma unroll
        for (int j = 0; j < 6; ++j) {
            int nc = (nh * 6 + j) * 8 + tig * 2;
            float2 bv = *(const float2*)&bias[nc];
            *(__half2*)&out[(size_t)rr * 96 + nc] =
                __floats2half2_rn(acc[m][j][0] + bv.x, acc[m][j][1] + bv.y);
            *(__half2*)&out[(size_t)(rr + 8) * 96 + nc] =
                __floats2half2_rn(acc[m][j][2] + bv.x, acc[m][j][3] + bv.y);
        }
    }
}

__global__ __launch_bounds__(256, 3) void patch_all(
    const float* __restrict__ x,
    const float* __restrict__ pw0, const float* __restrict__ pb0,
    const float* __restrict__ pw1, const float* __restrict__ pb1,
    const float* __restrict__ pw2, const float* __restrict__ pb2,
    __half* __restrict__ t) {
    __shared__ uint4 As4[AS_U4];
    __shared__ uint4 Bs4[BS_U4];
    int blk = blockIdx.x;
    if (blk < BLK0)
        patch_body<16, 768, 14>(x, pw0, pb0, t, blk, As4, Bs4);
    else if (blk < BLK01)
        patch_body<4, 48, 56>(x, pw1, pb1, t + (size_t)ROWS0 * 96, blk - BLK0, As4, Bs4);
    else
        patch_body<7, 147, 32>(x, pw2, pb2, t + (size_t)(ROWS0 + ROWS1) * 96, blk - BLK01, As4, Bs4);
}

// ---------------------------------------------------------------------------
// window attention — fp16-resident smem, 2x2-tiled QK^T, 2-row x 8-ch AV
// (unchanged from R14)
// ---------------------------------------------------------------------------
__device__ __forceinline__ float dot8h(uint4 a, uint4 c, float s) {
    __half2* ah = (__half2*)&a;
    __half2* ch = (__half2*)&c;
#pragma unroll
    for (int e = 0; e < 4; ++e) {
        float2 x = __half22float2(ah[e]);
        float2 y = __half22float2(ch[e]);
        s = fmaf(x.x, y.x, s);
        s = fmaf(x.y, y.y, s);
    }
    return s;
}

template <int WS>
__device__ __forceinline__ void win_attn_body(const __half* qkv, __half* o,
                                              int Wout, int nw, int rowbase,
                                              int b, int win, char* wsm_raw) {
    constexpr int NT = WS * WS;
    constexpr int RPH = 40;
    constexpr int SSTR = (NT % 2 == 0) ? NT + 1 : NT;
    constexpr int IT2 = (NT + 1) / 2;
    __half* hq = (__half*)wsm_raw;
    __half* hk = hq + 3 * NT * RPH;
    __half* hv = hk + 3 * NT * RPH;
    float* sS = (float*)(hv + 3 * NT * RPH);
    const int wr = win / nw, wc = win % nw;
    const int t = threadIdx.x;
    const int T = Wout * Wout;
    const float scale = 0.17677669529663687f;

    for (int idx = t; idx < NT * 36; idx += 128) {
        int p = idx / 36, u = idx - p * 36;
        int wi = p / WS, wj = p - wi * WS;
        int r = rowbase + b * T + (wr * WS + wi) * Wout + wc * WS + wj;
        uint4 val = __ldg((const uint4*)(qkv + (size_t)r * 288) + u);
        int sec = u / 12, uu = u - sec * 12;
        int head = uu >> 2, c0 = (uu & 3) * 8;
        __half* dst = (sec == 0 ? hq : sec == 1 ? hk : hv) + (head * NT + p) * RPH + c0;
        *(uint4*)dst = val;
    }
    __syncthreads();

    for (int idx = t; idx < 3 * IT2 * IT2; idx += 128) {
        int h = idx / (IT2 * IT2);
        int r = idx - h * IT2 * IT2;
        int i0 = (r / IT2) * 2, j0 = (r % IT2) * 2;
        bool i1ok = (i0 + 1 < NT), j1ok = (j0 + 1 < NT);
        const uint4* qa = (const uint4*)(hq + (h * NT + i0) * RPH);
        const uint4* qb = (const uint4*)(hq + (h * NT + (i1ok ? i0 + 1 : i0)) * RPH);
        const uint4* ka = (const uint4*)(hk + (h * NT + j0) * RPH);
        const uint4* kb = (const uint4*)(hk + (h * NT + (j1ok ? j0 + 1 : j0)) * RPH);
        float s00 = 0.f, s01 = 0.f, s10 = 0.f, s11 = 0.f;
#pragma unroll
        for (int v = 0; v < 4; ++v) {
            uint4 A0 = qa[v], A1 = qb[v], C0 = ka[v], C1 = kb[v];
            s00 = dot8h(A0, C0, s00);
            s01 = dot8h(A0, C1, s01);
            s10 = dot8h(A1, C0, s10);
            s11 = dot8h(A1, C1, s11);
        }
        float* sr0 = sS + (h * NT + i0) * SSTR;
        sr0[j0] = s00 * scale;
        if (j1ok) sr0[j0 + 1] = s01 * scale;
        if (i1ok) {
            float* sr1 = sr0 + SSTR;
            sr1[j0] = s10 * scale;
            if (j1ok) sr1[j0 + 1] = s11 * scale;
        }
    }
    __syncthreads();

    for (int row = t; row < 3 * NT; row += 128) {
        float* p = sS + row * SSTR;
        float m = -1e30f;
        for (int j = 0; j < NT; ++j) m = fmaxf(m, p[j]);
        float Z = 0.f;
        for (int j = 0; j < NT; ++j) {
            float e = __expf(p[j] - m);
            p[j] = e;
            Z += e;
        }
        float inv = 1.f / Z;
        for (int j = 0; j < NT; ++j) p[j] *= inv;
    }
    __syncthreads();

    for (int idx = t; idx < 3 * IT2 * 4; idx += 128) {
        int h = idx / (IT2 * 4);
        int r = idx - h * IT2 * 4;
        int i0 = (r >> 2) * 2, c8 = (r & 3) * 8;
        bool i1ok = (i0 + 1 < NT);
        const float* w0 = sS + (h * NT + i0) * SSTR;
        const float* w1 = sS + (h * NT + (i1ok ? i0 + 1 : i0)) * SSTR;
        float a0[8], a1[8];
#pragma unroll
        for (int e = 0; e < 8; ++e) { a0[e] = 0.f; a1[e] = 0.f; }
        for (int j = 0; j < NT; ++j) {
            uint4 v = *(const uint4*)(hv + (h * NT + j) * RPH + c8);
            float x0 = w0[j], x1 = w1[j];
            __half2* hh = (__half2*)&v;
#pragma unroll
            for (int e = 0; e < 4; ++e) {
                float2 f = __half22float2(hh[e]);
                a0[2 * e] = fmaf(x0, f.x, a0[2 * e]);
                a0[2 * e + 1] = fmaf(x0, f.y, a0[2 * e + 1]);
                a1[2 * e] = fmaf(x1, f.x, a1[2 * e]);
                a1[2 * e + 1] = fmaf(x1, f.y, a1[2 * e + 1]);
            }
        }
        {
            int wi = i0 / WS, wj = i0 - wi * WS;
            int rr = rowbase + b * T + (wr * WS + wi) * Wout + wc * WS + wj;
            uint4 outv;
            __half2* o2 = (__half2*)&outv;
#pragma unroll
            for (int e = 0; e < 4; ++e) o2[e] = __floats2half2_rn(a0[2 * e], a0[2 * e + 1]);
            *(uint4*)(o + (size_t)rr * 96 + h * 32 + c8) = outv;
        }
        if (i1ok) {
            int i1 = i0 + 1;
            int wi = i1 / WS, wj = i1 - wi * WS;
            int rr = rowbase + b * T + (wr * WS + wi) * Wout + wc * WS + wj;
            uint4 outv;
            __half2* o2 = (__half2*)&outv;
#pragma unroll
            for (int e = 0; e < 4; ++e) o2[e] = __floats2half2_rn(a1[2 * e], a1[2 * e + 1]);
            *(uint4*)(o + (size_t)rr * 96 + h * 32 + c8) = outv;
        }
    }
}

__global__ __launch_bounds__(128) void win7_k(const __half* __restrict__ qkv,
                                              __half* __restrict__ o) {
    extern __shared__ __align__(16) char wsm_raw[];
    int b = blockIdx.x / 4, win = blockIdx.x % 4;
    win_attn_body<7>(qkv, o, 14, 2, 0, b, win, wsm_raw);
}

__global__ __launch_bounds__(128) void win4m_k(const __half* __restrict__ qkv,
                                               __half* __restrict__ o) {
    extern __shared__ __align__(16) char wsm_raw[];
    int blk = blockIdx.x;
    if (blk < 64 * 196) {
        int b = blk / 196, win = blk % 196;
        win_attn_body<4>(qkv, o, 56, 14, ROWS0, b, win, wsm_raw);
    } else {
        blk -= 64 * 196;
        int b = blk / 64, win = blk % 64;
        win_attn_body<4>(qkv, o, 32, 8, ROWS0 + ROWS1, b, win, wsm_raw);
    }
}

// ---------------------------------------------------------------------------
// neighbor gather + LN (unchanged)
// ---------------------------------------------------------------------------
__global__ __launch_bounds__(256) void gather_ln_k(const __half* __restrict__ t1,
                                                   const __half* __restrict__ t2,
                                                   const float* __restrict__ g,
                                                   const float* __restrict__ bb,
                                                   __half* __restrict__ kv) {
    const int bl = blockIdx.x;
    const int b = bl / 196, l = bl % 196;
    const int i1 = l / 14, j1 = l % 14;
    __shared__ float s1[16 * 100];
    __shared__ float s2[9 * 100];
    const int tid = threadIdx.x, warp = tid >> 5, lane = tid & 31;

    for (int idx = tid; idx < 16 * 12; idx += 256) {
        int p = idx / 12, q = idx - p * 12;
        int ki = p >> 2, kj = p & 3;
        uint4 u = __ldg((const uint4*)(t1 +
            (size_t)((b * 56 + i1 * 4 + ki) * 56 + j1 * 4 + kj) * 96) + q);
        __half2* h2 = (__half2*)&u;
        float* dst = &s1[p * 100 + q * 8];
#pragma unroll
        for (int e = 0; e < 4; ++e) {
            float2 f = __half22float2(h2[e]);
            dst[2 * e] = f.x;
            dst[2 * e + 1] = f.y;
        }
    }
    for (int idx = tid; idx < 9 * 12; idx += 256) {
        int p = idx / 12, q = idx - p * 12;
        int ki = p / 3, kj = p - ki * 3;
        int rr = i1 * 3 + ki - 5, cc = j1 * 3 + kj - 5;
        float* dst = &s2[p * 100 + q * 8];
        if (rr >= 0 && rr < 32 && cc >= 0 && cc < 32) {
            uint4 u = __ldg((const uint4*)(t2 + (size_t)((b * 32 + rr) * 32 + cc) * 96) + q);
            __half2* h2 = (__half2*)&u;
#pragma unroll
            for (int e = 0; e < 4; ++e) {
                float2 f = __half22float2(h2[e]);
                dst[2 * e] = f.x;
                dst[2 * e + 1] = f.y;
            }
        } else {
#pragma unroll
            for (int e = 0; e < 8; ++e) dst[e] = 0.f;
        }
    }
    __syncthreads();

    float gv[3], bv[3];
#pragma unroll
    for (int i = 0; i < 3; ++i) {
        gv[i] = __ldg(&g[lane + 32 * i]);
        bv[i] = __ldg(&bb[lane + 32 * i]);
    }

    for (int k = warp; k < 25; k += 8) {
        float v[3];
#pragma unroll
        for (int i = 0; i < 3; ++i) {
            int c = lane + 32 * i;
            if (k < 16) {
                int F = k * 96 + c;
                v[i] = s1[(F & 15) * 100 + (F >> 4)];
            } else {
                int F = (k - 16) * 96 + c;
                v[i] = s2[(F % 9) * 100 + (F / 9)];
            }
        }
        float s = v[0] + v[1] + v[2];
        float q = v[0] * v[0] + v[1] * v[1] + v[2] * v[2];
#pragma unroll
        for (int off = 16; off > 0; off >>= 1) {
            s += __shfl_xor_sync(0xffffffffu, s, off);
            q += __shfl_xor_sync(0xffffffffu, q, off);
        }
        float mean = s * (1.f / 96.f);
        float var = fmaf(-mean, mean, q * (1.f / 96.f));
        float rstd = rsqrtf(var + 1e-5f);
        __half* dst = kv + ((size_t)bl * 25 + k) * 96;
#pragma unroll
        for (int i = 0; i < 3; ++i)
            dst[lane + 32 * i] = __float2half((v[i] - mean) * rstd * gv[i] + bv[i]);
    }
}

// ---------------------------------------------------------------------------
// cross attention (unchanged)
// ---------------------------------------------------------------------------
__global__ __launch_bounds__(128) void cross_attn_k(const __half* __restrict__ q,
                                                    const __half* __restrict__ kbuf,
                                                    const __half* __restrict__ vbuf,
                                                    __half* __restrict__ o) {
    const int rl = blockIdx.x;
    __shared__ __half hk[2400], hv[2400];
    __shared__ float sqf[96], ss[25];
    const int t = threadIdx.x;

    const uint4* ksrc = (const uint4*)(kbuf + (size_t)rl * 2400);
    const uint4* vsrc = (const uint4*)(vbuf + (size_t)rl * 2400);
    for (int idx = t; idx < 300; idx += 128) {
        ((uint4*)hk)[idx] = __ldg(ksrc + idx);
        ((uint4*)hv)[idx] = __ldg(vsrc + idx);
    }
    if (t < 96) sqf[t] = __half2float(__ldg(q + (size_t)rl * 96 + t));
    __syncthreads();

    if (t < 25) {
        const __half* kr = hk + t * 96;
        float s = 0.f;
#pragma unroll 8
        for (int c = 0; c < 96; ++c) s = fmaf(sqf[c], __half2float(kr[c]), s);
        ss[t] = s * 0.10206207261596575f;
    }
    __syncthreads();

    if (t < 96) {
        float m = -1e30f;
#pragma unroll
        for (int k = 0; k < 25; ++k) m = fmaxf(m, ss[k]);
        float Z = 0.f, acc = 0.f;
#pragma unroll
        for (int k = 0; k < 25; ++k) {
            float e = __expf(ss[k] - m);
            Z += e;
            acc = fmaf(e, __half2float(hv[k * 96 + t]), acc);
        }
        o[(size_t)rl * 96 + t] = __float2half(acc / Z);
    }
}

// ---------------------------------------------------------------------------
extern "C" void kernel_launch(void* const* d_in, const int* in_sizes, int n_in,
                              void* d_out, int out_size) {
    const float* x       = (const float*)d_in[0];
    const float* pw0     = (const float*)d_in[1];
    const float* pb0     = (const float*)d_in[2];
    const float* pw1     = (const float*)d_in[3];
    const float* pb1     = (const float*)d_in[4];
    const float* pw2     = (const float*)d_in[5];
    const float* pb2     = (const float*)d_in[6];
    const float* wa_ln_g = (const float*)d_in[7];
    const float* wa_ln_b = (const float*)d_in[8];
    const float* wa_qkv  = (const float*)d_in[9];
    const float* wa_ow   = (const float*)d_in[10];
    const float* wa_ob   = (const float*)d_in[11];
    const float* ff_ln_g = (const float*)d_in[12];
    const float* ff_ln_b = (const float*)d_in[13];
    const float* ff_w1   = (const float*)d_in[14];
    const float* ff_b1   = (const float*)d_in[15];
    const float* ff_w2   = (const float*)d_in[16];
    const float* ff_b2   = (const float*)d_in[17];
    const float* lnn_g   = (const float*)d_in[18];
    const float* lnn_b   = (const float*)d_in[19];
    const float* ca_wq   = (const float*)d_in[20];
    const float* ca_wk   = (const float*)d_in[21];
    const float* ca_wv   = (const float*)d_in[22];
    const float* ca_wo   = (const float*)d_in[23];
    const float* ca_bo   = (const float*)d_in[24];
    const float* fi_ln_g = (const float*)d_in[25];
    const float* fi_ln_b = (const float*)d_in[26];
    const float* fi_w1   = (const float*)d_in[27];
    const float* fi_b1   = (const float*)d_in[28];
    const float* fi_w2   = (const float*)d_in[29];
    const float* fi_b2   = (const float*)d_in[30];
    float* out = (float*)d_out;

    __half *t, *qkv, *ob, *kv, *kk, *vv, *qq, *co;
    cudaGetSymbolAddress((void**)&t, g_t);
    cudaGetSymbolAddress((void**)&qkv, g_qkv);
    cudaGetSymbolAddress((void**)&ob, g_ob);
    cudaGetSymbolAddress((void**)&kv, g_kv);
    cudaGetSymbolAddress((void**)&kk, g_k);
    cudaGetSymbolAddress((void**)&vv, g_v);
    cudaGetSymbolAddress((void**)&qq, g_q);
    cudaGetSymbolAddress((void**)&co, g_co);

    __half* t0 = t;
    __half* t1 = t + (size_t)ROWS0 * 96;
    __half* t2 = t + (size_t)(ROWS0 + ROWS1) * 96;

    const int WSM7 = 3 * 3 * 49 * 40 * 2 + 3 * 49 * 49 * 4;
    const int WSM4 = 3 * 3 * 16 * 40 * 2 + 3 * 16 * 17 * 4;
    cudaFuncSetAttribute(win7_k, cudaFuncAttributeMaxDynamicSharedMemorySize, WSM7);
    cudaFuncSetAttribute(win4m_k, cudaFuncAttributeMaxDynamicSharedMemorySize, WSM4);
    cudaFuncSetAttribute(resff_final, cudaFuncAttributeMaxDynamicSharedMemorySize, RES_SMEM);
    cudaFuncSetAttribute(resff_mid, cudaFuncAttributeMaxDynamicSharedMemorySize, RSM_MID);

    // all patch merges in one launch
    patch_all<<<RTOT / 128, 256>>>(x, pw0, pb0, pw1, pb1, pw2, pb2, t);

    // merged per-scale transformer
    gemm_tc<__half, __half, true, false, 0, false, 3, true><<<RTOT / 128, 256>>>(
        t, wa_qkv, nullptr, nullptr, wa_ln_g, wa_ln_b, nullptr, qkv, nullptr, 288);
    win7_k<<<64 * 4, 128, WSM7>>>(qkv, ob);
    win4m_k<<<64 * 196 + 64 * 64, 128, WSM4>>>(qkv, ob);
    // FUSED: t = t + ob@Wo + bo; t += gelu(LN(t)@W1+b1)@W2 + b2  (all scales)
    resff_mid<<<RTOT / 128, 256, RSM_MID>>>(
        ob, t, wa_ow, wa_ob, ff_ln_g, ff_ln_b, ff_w1, ff_b1, ff_w2, ff_b2);

    // cross-attention fusion
    gather_ln_k<<<64 * 196, 256>>>(t1, t2, lnn_g, lnn_b, kv);
    gemm_tc<__half, __half, false, false, 0, true, 1, false><<<dim3(KVROWS / 128, 2), 256>>>(
        kv, ca_wk, ca_wv, nullptr, nullptr, nullptr, nullptr, kk, vv, 96);
    gemm_tc<__half, __half, true, false, 0, false, 1, false><<<ROWS0 / 128, 256>>>(
        t0, ca_wq, nullptr, nullptr, lnn_g, lnn_b, nullptr, qq, nullptr, 96);
    cross_attn_k<<<12544, 128>>>(qq, kk, vv, co);
    resff_final<<<ROWS0 / 128, 256, RES_SMEM>>>(
        co, t0, out, ca_wo, ca_bo, fi_ln_g, fi_ln_b, fi_w1, fi_b1, fi_w2, fi_b2);
}

// round 16
// speedup vs baseline: 2.0314x; 1.0367x over previous
#include <cuda_runtime.h>
#include <cuda_fp16.h>
#include <math.h>

// ---------------------------------------------------------------------------
// MultiScaleCrossAttn — fp16 MMA GEMMs, scale-merged launches,
// coalesced B staging, fp16 window attention, fused chains (mid + kvq + tail)
// ---------------------------------------------------------------------------

#define ROWS0 12544      // 64*14*14
#define ROWS1 200704     // 64*56*56
#define ROWS2 65536      // 64*32*32
#define RTOT  278784
#define KVROWS 313600    // 64*196*25
#define KVBLK 2450       // KVROWS/128

#define BLK0 98          // ROWS0/128
#define BLK01 1666       // (ROWS0+ROWS1)/128

__device__ __align__(16) __half g_t[RTOT * 96];
__device__ __align__(16) __half g_qkv[RTOT * 288];
__device__ __align__(16) __half g_ob[RTOT * 96];
__device__ __align__(16) __half g_kv[KVROWS * 96];
__device__ __align__(16) __half g_k[KVROWS * 96];
__device__ __align__(16) __half g_v[KVROWS * 96];
__device__ __align__(16) __half g_q[ROWS0 * 96];
__device__ __align__(16) __half g_co[ROWS0 * 96];

static constexpr int AS_U4 = 6 * 8 * 32;    // 24576 B
static constexpr int BS_U4 = 36 * 33;       // padded: 19008 B
static constexpr int TF_LD = 100;           // fp32 pitch (final tail)
static constexpr int RES_SMEM = 128 * TF_LD * 4 + AS_U4 * 16 + BS_U4 * 16;  // 94784
static constexpr int TFH_LD = 104;          // fp16 pitch (mid chain)
static constexpr int RSM_MID = 128 * TFH_LD * 2 + AS_U4 * 16 + BS_U4 * 16;  // 70208

__device__ __forceinline__ unsigned f2h2(float lo, float hi) {
    __half2 h = __floats2half2_rn(lo, hi);
    return *reinterpret_cast<unsigned*>(&h);
}

__device__ __forceinline__ void mma16(float c[4], uint4 a, unsigned b0, unsigned b1) {
    asm volatile(
        "mma.sync.aligned.m16n8k16.row.col.f32.f16.f16.f32 "
        "{%0,%1,%2,%3}, {%4,%5,%6,%7}, {%8,%9}, {%0,%1,%2,%3};\n"
        : "+f"(c[0]), "+f"(c[1]), "+f"(c[2]), "+f"(c[3])
        : "r"(a.x), "r"(a.y), "r"(a.z), "r"(a.w), "r"(b0), "r"(b1));
}

__device__ __forceinline__ float gelu_f(float v) {
    return 0.5f * v * (1.f + erff(v * 0.70710678118654752f));
}

__device__ __forceinline__ void gemm_main(float acc[2][6][4], const uint4* As4,
                                          const uint4* Bs4, int mg, int nh, int lane) {
#pragma unroll
    for (int m = 0; m < 2; ++m)
#pragma unroll
        for (int j = 0; j < 6; ++j)
#pragma unroll
            for (int i = 0; i < 4; ++i) acc[m][j][i] = 0.f;
#pragma unroll
    for (int kt = 0; kt < 6; ++kt) {
        uint4 a0 = As4[(kt * 8 + mg * 2) * 32 + lane];
        uint4 a1 = As4[(kt * 8 + mg * 2 + 1) * 32 + lane];
        uint4 b0 = Bs4[(kt * 6 + nh * 3) * 33 + lane];
        uint4 b1 = Bs4[(kt * 6 + nh * 3 + 1) * 33 + lane];
        uint4 b2 = Bs4[(kt * 6 + nh * 3 + 2) * 33 + lane];
        mma16(acc[0][0], a0, b0.x, b0.y); mma16(acc[0][1], a0, b0.z, b0.w);
        mma16(acc[0][2], a0, b1.x, b1.y); mma16(acc[0][3], a0, b1.z, b1.w);
        mma16(acc[0][4], a0, b2.x, b2.y); mma16(acc[0][5], a0, b2.z, b2.w);
        mma16(acc[1][0], a1, b0.x, b0.y); mma16(acc[1][1], a1, b0.z, b0.w);
        mma16(acc[1][2], a1, b1.x, b1.y); mma16(acc[1][3], a1, b1.z, b1.w);
        mma16(acc[1][4], a1, b2.x, b2.y); mma16(acc[1][5], a1, b2.z, b2.w);
    }
}

// coalesced vectorized B staging
__device__ __forceinline__ void stage_B(__half* Bsh, const float* W, int ldw,
                                        int ncol0, int tid, int kmax) {
    for (int idx = tid; idx < 96 * 24; idx += 256) {
        int k = idx / 24;
        int q = idx - k * 24;
        int n = q * 4;
        float4 v = make_float4(0.f, 0.f, 0.f, 0.f);
        if (k < kmax) v = __ldg((const float4*)(W + (size_t)k * ldw + ncol0 + n));
        int kt = k >> 4, kk = k & 15;
        int tig = (kk >> 1) & 3, clo = kk >> 3, half = k & 1;
        float vv[4] = {v.x, v.y, v.z, v.w};
#pragma unroll
        for (int e = 0; e < 4; ++e) {
            int nn = n + e;
            int gid = nn & 7, jp = nn >> 4, chi = (nn >> 3) & 1;
            int word = ((kt * 6 + jp) * 33 + gid * 4 + tig) * 4 + (chi * 2 + clo);
            Bsh[word * 2 + half] = __float2half(vv[e]);
        }
    }
}

__device__ __forceinline__ void stage_A_half(unsigned* As, const __half* A,
                                             int row0, int tid) {
    const int row = tid >> 1, sub = tid & 1;
    const int mt = row >> 4, r16 = row & 15;
    const int gid8 = r16 & 7, rowhi = r16 >> 3;
    const uint4* ap = (const uint4*)(A + (size_t)(row0 + row) * 96 + sub * 48);
#pragma unroll
    for (int j = 0; j < 6; ++j) {
        uint4 u = __ldg(&ap[j]);
        unsigned w[4] = {u.x, u.y, u.z, u.w};
#pragma unroll
        for (int wi = 0; wi < 4; ++wi) {
            int P = sub * 24 + j * 4 + wi;
            int kt = P >> 3, hi = (P >> 2) & 1, tg = P & 3;
            As[(((kt * 8 + mt) * 32) + (gid8 << 2) + tg) * 4 + (rowhi | (hi << 1))] = w[wi];
        }
    }
}

// shared LN+frag-store from float4 vals (per-row, 2 threads/row)
__device__ __forceinline__ void ln_store_A(unsigned* As, float4 vals[12],
                                           const float* lng, const float* lnb,
                                           int row, int sub) {
    const int mt = row >> 4, r16 = row & 15;
    const int gid8 = r16 & 7, rowhi = r16 >> 3;
    float s = 0.f, s2 = 0.f;
#pragma unroll
    for (int j = 0; j < 12; ++j) {
        float4 v = vals[j];
        s += v.x + v.y + v.z + v.w;
        s2 += v.x * v.x + v.y * v.y + v.z * v.z + v.w * v.w;
    }
    s += __shfl_xor_sync(0xffffffffu, s, 1);
    s2 += __shfl_xor_sync(0xffffffffu, s2, 1);
    float mean = s * (1.f / 96.f);
    float var = fmaf(-mean, mean, s2 * (1.f / 96.f));
    float rstd = rsqrtf(var + 1e-5f);
#pragma unroll
    for (int j = 0; j < 12; ++j) {
        int k0 = sub * 48 + j * 4;
        float4 v = vals[j];
        float4 g = __ldg((const float4*)(lng + k0));
        float4 bb = __ldg((const float4*)(lnb + k0));
        v.x = (v.x - mean) * rstd * g.x + bb.x;
        v.y = (v.y - mean) * rstd * g.y + bb.y;
        v.z = (v.z - mean) * rstd * g.z + bb.z;
        v.w = (v.w - mean) * rstd * g.w + bb.w;
        int kt = k0 >> 4, kk = k0 & 15;
        int hi = kk >> 3, tig = (kk & 7) >> 1;
        unsigned base = (((kt * 8 + mt) * 32) + (gid8 << 2) + tig) * 4;
        As[base + (rowhi | (hi << 1))] = f2h2(v.x, v.y);
        As[base + 4 + (rowhi | (hi << 1))] = f2h2(v.z, v.w);
    }
}

// half-store epilogue, no bias
__device__ __forceinline__ void epi_half(float acc[2][6][4], __half* out, int row0,
                                         int mg, int nh, int gid, int tig) {
#pragma unroll
    for (int m = 0; m < 2; ++m) {
        int rr = row0 + (mg * 2 + m) * 16 + gid;
#pragma unroll
        for (int j = 0; j < 6; ++j) {
            int nc = (nh * 6 + j) * 8 + tig * 2;
            *(__half2*)(out + (size_t)rr * 96 + nc) =
                __floats2half2_rn(acc[m][j][0], acc[m][j][1]);
            *(__half2*)(out + (size_t)(rr + 8) * 96 + nc) =
                __floats2half2_rn(acc[m][j][2], acc[m][j][3]);
        }
    }
}

// ---------------------------------------------------------------------------
// generic GEMM: LNF/GELU/EPI/DUAL/NCH/MULTI
// ---------------------------------------------------------------------------
template <class TA, class TO, bool LNF, bool GELU, int EPI, bool DUAL, int NCH, bool MULTI>
__global__ __launch_bounds__(256, 3) void gemm_tc(const TA* __restrict__ A,
                                                  const float* __restrict__ W,
                                                  const float* __restrict__ W2,
                                                  const float* __restrict__ bias,
                                                  const float* __restrict__ lng,
                                                  const float* __restrict__ lnb,
                                                  const TA* __restrict__ res,
                                                  TO* __restrict__ out,
                                                  TO* __restrict__ out2, int ldw) {
    constexpr bool TAH = (sizeof(TA) == 2);
    constexpr bool TOH = (sizeof(TO) == 2);
    __shared__ uint4 As4[AS_U4];
    __shared__ uint4 Bs4[BS_U4];
    unsigned* As = (unsigned*)As4;
    const int tid = threadIdx.x, lane = tid & 31, warp = tid >> 5;
    const int row0 = blockIdx.x * 128;
    int ncbase = 0;
    if (MULTI) {
        int s = (blockIdx.x < BLK0) ? 0 : (blockIdx.x < BLK01) ? 1 : 2;
        W += (size_t)s * 96 * ldw;
        if (bias) bias += s * 96;
        if (LNF) { lng += s * 96; lnb += s * 96; }
    } else if (DUAL) {
        if (blockIdx.y) { W = W2; out = out2; }
    } else if (NCH == 1) {
        ncbase = blockIdx.y * 96;
    }

    stage_B((__half*)Bs4, W, ldw, ncbase, tid, 96);

    if constexpr (TAH && !LNF) {
        stage_A_half(As, (const __half*)A, row0, tid);
    } else {
        const int row = tid >> 1, sub = tid & 1;
        float4 vals[12];
        if constexpr (TAH) {
            const uint4* ap = (const uint4*)((const __half*)A + (size_t)(row0 + row) * 96 + sub * 48);
#pragma unroll
            for (int j = 0; j < 6; ++j) {
                uint4 u = __ldg(&ap[j]);
                __half2* h2 = (__half2*)&u;
                float2 f0 = __half22float2(h2[0]);
                float2 f1 = __half22float2(h2[1]);
                float2 f2v = __half22float2(h2[2]);
                float2 f3 = __half22float2(h2[3]);
                vals[2 * j] = make_float4(f0.x, f0.y, f1.x, f1.y);
                vals[2 * j + 1] = make_float4(f2v.x, f2v.y, f3.x, f3.y);
            }
        } else {
            const float* ap = (const float*)A + (size_t)(row0 + row) * 96 + sub * 48;
#pragma unroll
            for (int j = 0; j < 12; ++j) vals[j] = __ldg((const float4*)(ap + j * 4));
        }
        if (LNF) {
            ln_store_A(As, vals, lng, lnb, row, sub);
        } else {
            const int mt = row >> 4, r16 = row & 15;
            const int gid8 = r16 & 7, rowhi = r16 >> 3;
#pragma unroll
            for (int j = 0; j < 12; ++j) {
                int k0 = sub * 48 + j * 4;
                float4 v = vals[j];
                int kt = k0 >> 4, kk = k0 & 15;
                int hi = kk >> 3, tig = (kk & 7) >> 1;
                unsigned base = (((kt * 8 + mt) * 32) + (gid8 << 2) + tig) * 4;
                As[base + (rowhi | (hi << 1))] = f2h2(v.x, v.y);
                As[base + 4 + (rowhi | (hi << 1))] = f2h2(v.z, v.w);
            }
        }
    }
    __syncthreads();

    const int mg = warp & 3, nh = warp >> 2;
    const int gid = lane >> 2, tig = lane & 3;
    float acc[2][6][4];

#pragma unroll
    for (int ch = 0; ch < NCH; ++ch) {
        if (ch > 0) {
            __syncthreads();
            stage_B((__half*)Bs4, W, ldw, ch * 96, tid, 96);
            __syncthreads();
        }
        gemm_main(acc, As4, Bs4, mg, nh, lane);
        const int ncol0 = (NCH > 1) ? ch * 96 : ncbase;

#pragma unroll
        for (int m = 0; m < 2; ++m) {
            int rr = row0 + (mg * 2 + m) * 16 + gid;
#pragma unroll
            for (int j = 0; j < 6; ++j) {
                int nc = ncol0 + (nh * 6 + j) * 8 + tig * 2;
                float bx = 0.f, by = 0.f;
                if (bias) {
                    float2 bv = *(const float2*)&bias[nc];
                    bx = bv.x; by = bv.y;
                }
                float x0 = acc[m][j][0] + bx, x1 = acc[m][j][1] + by;
                float x2 = acc[m][j][2] + bx, x3 = acc[m][j][3] + by;
                if (GELU) { x0 = gelu_f(x0); x1 = gelu_f(x1); x2 = gelu_f(x2); x3 = gelu_f(x3); }
                if constexpr (TOH) {
                    __half2* p0 = (__half2*)((__half*)out + (size_t)rr * ldw + nc);
                    __half2* p1 = (__half2*)((__half*)out + (size_t)(rr + 8) * ldw + nc);
                    if constexpr (EPI == 1) {
                        float2 o0 = __half22float2(*p0), o1 = __half22float2(*p1);
                        x0 += o0.x; x1 += o0.y; x2 += o1.x; x3 += o1.y;
                    }
                    *p0 = __floats2half2_rn(x0, x1);
                    *p1 = __floats2half2_rn(x2, x3);
                } else {
                    float* p0 = (float*)out + (size_t)rr * ldw + nc;
                    float* p1 = (float*)out + (size_t)(rr + 8) * ldw + nc;
                    if constexpr (EPI == 0) {
                        *(float2*)p0 = make_float2(x0, x1);
                        *(float2*)p1 = make_float2(x2, x3);
                    } else if constexpr (EPI == 1) {
                        float2 o0 = *(float2*)p0, o1 = *(float2*)p1;
                        *(float2*)p0 = make_float2(o0.x + x0, o0.y + x1);
                        *(float2*)p1 = make_float2(o1.x + x2, o1.y + x3);
                    } else {
                        float2 r0 = __half22float2(*(const __half2*)((const __half*)res + (size_t)rr * 96 + nc));
                        float2 r1 = __half22float2(*(const __half2*)((const __half*)res + (size_t)(rr + 8) * 96 + nc));
                        *(float2*)p0 = make_float2(r0.x + x0, r0.y + x1);
                        *(float2*)p1 = make_float2(r1.x + x2, r1.y + x3);
                    }
                }
            }
        }
    }
}

// ---------------------------------------------------------------------------
// FUSED K/V/Q projections: blocks [0,KVBLK): kk = kv@Wk, vv = kv@Wv (single
// A stage); blocks [KVBLK,...): qq = LN(t0)@Wq. Identical per-output numerics
// to the unfused launches.
// ---------------------------------------------------------------------------
__global__ __launch_bounds__(256, 3) void kvq_tc(const __half* __restrict__ kv,
                                                 const __half* __restrict__ t0,
                                                 const float* __restrict__ Wk,
                                                 const float* __restrict__ Wv,
                                                 const float* __restrict__ Wq,
                                                 const float* __restrict__ lng,
                                                 const float* __restrict__ lnb,
                                                 __half* __restrict__ kk,
                                                 __half* __restrict__ vv,
                                                 __half* __restrict__ qq) {
    __shared__ uint4 As4[AS_U4];
    __shared__ uint4 Bs4[BS_U4];
    unsigned* As = (unsigned*)As4;
    const int tid = threadIdx.x, lane = tid & 31, warp = tid >> 5;
    const int mg = warp & 3, nh = warp >> 2;
    const int gid = lane >> 2, tig = lane & 3;
    float acc[2][6][4];

    if (blockIdx.x < KVBLK) {
        const int row0 = blockIdx.x * 128;
        stage_A_half(As, kv, row0, tid);
        stage_B((__half*)Bs4, Wk, 96, 0, tid, 96);
        __syncthreads();
        gemm_main(acc, As4, Bs4, mg, nh, lane);
        epi_half(acc, kk, row0, mg, nh, gid, tig);
        __syncthreads();
        stage_B((__half*)Bs4, Wv, 96, 0, tid, 96);
        __syncthreads();
        gemm_main(acc, As4, Bs4, mg, nh, lane);
        epi_half(acc, vv, row0, mg, nh, gid, tig);
    } else {
        const int row0 = (blockIdx.x - KVBLK) * 128;
        {
            const int row = tid >> 1, sub = tid & 1;
            const uint4* ap = (const uint4*)(t0 + (size_t)(row0 + row) * 96 + sub * 48);
            float4 vals[12];
#pragma unroll
            for (int j = 0; j < 6; ++j) {
                uint4 u = __ldg(&ap[j]);
                __half2* h2 = (__half2*)&u;
                float2 f0 = __half22float2(h2[0]);
                float2 f1 = __half22float2(h2[1]);
                float2 f2v = __half22float2(h2[2]);
                float2 f3 = __half22float2(h2[3]);
                vals[2 * j] = make_float4(f0.x, f0.y, f1.x, f1.y);
                vals[2 * j + 1] = make_float4(f2v.x, f2v.y, f3.x, f3.y);
            }
            ln_store_A(As, vals, lng, lnb, row, sub);
        }
        stage_B((__half*)Bs4, Wq, 96, 0, tid, 96);
        __syncthreads();
        gemm_main(acc, As4, Bs4, mg, nh, lane);
        epi_half(acc, qq, row0, mg, nh, gid, tig);
    }
}

// ---------------------------------------------------------------------------
// FUSED MID CHAIN (all scales) — unchanged from R15
// ---------------------------------------------------------------------------
__global__ __launch_bounds__(256, 3) void resff_mid(const __half* __restrict__ ob,
                                                    __half* __restrict__ t,
                                                    const float* __restrict__ Wo,
                                                    const float* __restrict__ bo,
                                                    const float* __restrict__ lng,
                                                    const float* __restrict__ lnb,
                                                    const float* __restrict__ W1,
                                                    const float* __restrict__ b1,
                                                    const float* __restrict__ W2,
                                                    const float* __restrict__ b2) {
    extern __shared__ __align__(16) char dynm[];
    __half* Tf = (__half*)dynm;
    unsigned* As = (unsigned*)(dynm + 128 * TFH_LD * 2);
    unsigned* Bs = As + AS_U4 * 4;
    uint4* As4 = (uint4*)As;
    uint4* Bs4 = (uint4*)Bs;
    const int tid = threadIdx.x, lane = tid & 31, warp = tid >> 5;
    const int row0 = blockIdx.x * 128;
    const int s = (blockIdx.x < BLK0) ? 0 : (blockIdx.x < BLK01) ? 1 : 2;
    Wo += s * 9216; bo += s * 96; lng += s * 96; lnb += s * 96;
    W1 += s * 9216; b1 += s * 96; W2 += s * 9216; b2 += s * 96;
    const int mg = warp & 3, nh = warp >> 2;
    const int gid = lane >> 2, tig = lane & 3;
    float acc[2][6][4];

    stage_A_half(As, ob, row0, tid);
    stage_B((__half*)Bs4, Wo, 96, 0, tid, 96);
    __syncthreads();
    gemm_main(acc, As4, Bs4, mg, nh, lane);

#pragma unroll
    for (int m = 0; m < 2; ++m) {
        int rl = (mg * 2 + m) * 16 + gid;
#pragma unroll
        for (int j = 0; j < 6; ++j) {
            int nc = (nh * 6 + j) * 8 + tig * 2;
            float2 bv = *(const float2*)&bo[nc];
            float2 r0 = __half22float2(*(const __half2*)(t + (size_t)(row0 + rl) * 96 + nc));
            float2 r1 = __half22float2(*(const __half2*)(t + (size_t)(row0 + rl + 8) * 96 + nc));
            *(__half2*)&Tf[rl * TFH_LD + nc] =
                __floats2half2_rn(acc[m][j][0] + bv.x + r0.x, acc[m][j][1] + bv.y + r0.y);
            *(__half2*)&Tf[(rl + 8) * TFH_LD + nc] =
                __floats2half2_rn(acc[m][j][2] + bv.x + r1.x, acc[m][j][3] + bv.y + r1.y);
        }
    }
    __syncthreads();

    {
        const int row = tid >> 1, sub = tid & 1;
        const uint4* ap = (const uint4*)(Tf + row * TFH_LD + sub * 48);
        float4 vals[12];
#pragma unroll
        for (int j = 0; j < 6; ++j) {
            uint4 u = ap[j];
            __half2* h2 = (__half2*)&u;
            float2 f0 = __half22float2(h2[0]);
            float2 f1 = __half22float2(h2[1]);
            float2 f2v = __half22float2(h2[2]);
            float2 f3 = __half22float2(h2[3]);
            vals[2 * j] = make_float4(f0.x, f0.y, f1.x, f1.y);
            vals[2 * j + 1] = make_float4(f2v.x, f2v.y, f3.x, f3.y);
        }
        ln_store_A(As, vals, lng, lnb, row, sub);
    }
    stage_B((__half*)Bs4, W1, 96, 0, tid, 96);
    __syncthreads();
    gemm_main(acc, As4, Bs4, mg, nh, lane);
    __syncthreads();

#pragma unroll
    for (int m = 0; m < 2; ++m) {
        int mt2 = mg * 2 + m;
#pragma unroll
        for (int j = 0; j < 6; ++j) {
            int col8 = nh * 6 + j;
            int kt = col8 >> 1, hi = col8 & 1;
            int k0 = col8 * 8 + tig * 2;
            float2 bv = *(const float2*)&b1[k0];
            float x0 = gelu_f(acc[m][j][0] + bv.x), x1 = gelu_f(acc[m][j][1] + bv.y);
            float x2 = gelu_f(acc[m][j][2] + bv.x), x3 = gelu_f(acc[m][j][3] + bv.y);
            unsigned base = (((kt * 8 + mt2) * 32) + (gid << 2) + tig) * 4;
            As[base + (hi << 1)] = f2h2(x0, x1);
            As[base + 1 + (hi << 1)] = f2h2(x2, x3);
        }
    }
    stage_B((__half*)Bs4, W2, 96, 0, tid, 96);
    __syncthreads();
    gemm_main(acc, As4, Bs4, mg, nh, lane);

#pragma unroll
    for (int m = 0; m < 2; ++m) {
        int rl = (mg * 2 + m) * 16 + gid;
#pragma unroll
        for (int j = 0; j < 6; ++j) {
            int nc = (nh * 6 + j) * 8 + tig * 2;
            float2 bv = *(const float2*)&b2[nc];
            float2 t0v = __half22float2(*(const __half2*)&Tf[rl * TFH_LD + nc]);
            float2 t1v = __half22float2(*(const __half2*)&Tf[(rl + 8) * TFH_LD + nc]);
            *(__half2*)(t + (size_t)(row0 + rl) * 96 + nc) =
                __floats2half2_rn(acc[m][j][0] + bv.x + t0v.x, acc[m][j][1] + bv.y + t0v.y);
            *(__half2*)(t + (size_t)(row0 + rl + 8) * 96 + nc) =
                __floats2half2_rn(acc[m][j][2] + bv.x + t1v.x, acc[m][j][3] + bv.y + t1v.y);
        }
    }
}

// ---------------------------------------------------------------------------
// FUSED FINAL TAIL — unchanged from R15
// ---------------------------------------------------------------------------
__global__ __launch_bounds__(256) void resff_final(const __half* __restrict__ co,
                                                   const __half* __restrict__ t0,
                                                   float* __restrict__ out,
                                                   const float* __restrict__ Wo,
                                                   const float* __restrict__ bo,
                                                   const float* __restrict__ lng,
                                                   const float* __restrict__ lnb,
                                                   const float* __restrict__ W1,
                                                   const float* __restrict__ b1,
                                                   const float* __restrict__ W2,
                                                   const float* __restrict__ b2) {
    extern __shared__ float dyn[];
    float* Tf = dyn;
    unsigned* As = (unsigned*)(dyn + 128 * TF_LD);
    unsigned* Bs = As + AS_U4 * 4;
    uint4* As4 = (uint4*)As;
    uint4* Bs4 = (uint4*)Bs;
    const int tid = threadIdx.x, lane = tid & 31, warp = tid >> 5;
    const int row0 = blockIdx.x * 128;
    const int mg = warp & 3, nh = warp >> 2;
    const int gid = lane >> 2, tig = lane & 3;
    float acc[2][6][4];

    stage_A_half(As, co, row0, tid);
    stage_B((__half*)Bs4, Wo, 96, 0, tid, 96);
    __syncthreads();
    gemm_main(acc, As4, Bs4, mg, nh, lane);

#pragma unroll
    for (int m = 0; m < 2; ++m) {
        int rl = (mg * 2 + m) * 16 + gid;
#pragma unroll
        for (int j = 0; j < 6; ++j) {
            int nc = (nh * 6 + j) * 8 + tig * 2;
            float2 bv = *(const float2*)&bo[nc];
            float2 r0 = __half22float2(*(const __half2*)(t0 + (size_t)(row0 + rl) * 96 + nc));
            float2 r1 = __half22float2(*(const __half2*)(t0 + (size_t)(row0 + rl + 8) * 96 + nc));
            *(float2*)&Tf[rl * TF_LD + nc] =
                make_float2(acc[m][j][0] + bv.x + r0.x, acc[m][j][1] + bv.y + r0.y);
            *(float2*)&Tf[(rl + 8) * TF_LD + nc] =
                make_float2(acc[m][j][2] + bv.x + r1.x, acc[m][j][3] + bv.y + r1.y);
        }
    }
    __syncthreads();

    {
        const int row = tid >> 1, sub = tid & 1;
        const float* ap = Tf + row * TF_LD + sub * 48;
        float4 vals[12];
#pragma unroll
        for (int j = 0; j < 12; ++j) vals[j] = *(const float4*)(ap + j * 4);
        ln_store_A(As, vals, lng, lnb, row, sub);
    }
    stage_B((__half*)Bs4, W1, 96, 0, tid, 96);
    __syncthreads();
    gemm_main(acc, As4, Bs4, mg, nh, lane);
    __syncthreads();

#pragma unroll
    for (int m = 0; m < 2; ++m) {
        int mt2 = mg * 2 + m;
#pragma unroll
        for (int j = 0; j < 6; ++j) {
            int col8 = nh * 6 + j;
            int kt = col8 >> 1, hi = col8 & 1;
            int k0 = col8 * 8 + tig * 2;
            float2 bv = *(const float2*)&b1[k0];
            float x0 = gelu_f(acc[m][j][0] + bv.x), x1 = gelu_f(acc[m][j][1] + bv.y);
            float x2 = gelu_f(acc[m][j][2] + bv.x), x3 = gelu_f(acc[m][j][3] + bv.y);
            unsigned base = (((kt * 8 + mt2) * 32) + (gid << 2) + tig) * 4;
            As[base + (hi << 1)] = f2h2(x0, x1);
            As[base + 1 + (hi << 1)] = f2h2(x2, x3);
        }
    }
    stage_B((__half*)Bs4, W2, 96, 0, tid, 96);
    __syncthreads();
    gemm_main(acc, As4, Bs4, mg, nh, lane);

#pragma unroll
    for (int m = 0; m < 2; ++m) {
        int rl = (mg * 2 + m) * 16 + gid;
#pragma unroll
        for (int j = 0; j < 6; ++j) {
            int nc = (nh * 6 + j) * 8 + tig * 2;
            float2 bv = *(const float2*)&b2[nc];
            float2 t0v = *(const float2*)&Tf[rl * TF_LD + nc];
            float2 t1v = *(const float2*)&Tf[(rl + 8) * TF_LD + nc];
            *(float2*)&out[(size_t)(row0 + rl) * 96 + nc] =
                make_float2(acc[m][j][0] + bv.x + t0v.x, acc[m][j][1] + bv.y + t0v.y);
            *(float2*)&out[(size_t)(row0 + rl + 8) * 96 + nc] =
                make_float2(acc[m][j][2] + bv.x + t1v.x, acc[m][j][3] + bv.y + t1v.y);
        }
    }
}

// ---------------------------------------------------------------------------
// patch merge (unchanged)
// ---------------------------------------------------------------------------
template <int DF, int KTOT, int WOUT>
__device__ __forceinline__ void patch_body(const float* __restrict__ x,
                                           const float* __restrict__ w,
                                           const float* __restrict__ bias,
                                           __half* __restrict__ out,
                                           int blk, uint4* As4, uint4* Bs4) {
    constexpr int KPAD = (KTOT + 15) & ~15;
    unsigned* As = (unsigned*)As4;
    const int tid = threadIdx.x, lane = tid & 31, warp = tid >> 5;
    const int row0 = blk * 128;
    const int T = WOUT * WOUT;
    const int mg = warp & 3, nh = warp >> 2;

    float acc[2][6][4];
#pragma unroll
    for (int m = 0; m < 2; ++m)
#pragma unroll
        for (int j = 0; j < 6; ++j)
#pragma unroll
            for (int i = 0; i < 4; ++i) acc[m][j][i] = 0.f;

    for (int kc = 0; kc < KPAD; kc += 96) {
        const int cl = (KPAD - kc) < 96 ? (KPAD - kc) : 96;
        const int nkt = cl >> 4;

        stage_B((__half*)Bs4, w + (size_t)kc * 96, 96, 0, tid, KTOT - kc);
        {
            const int row = tid >> 1, sub = tid & 1;
            const int tok = row0 + row;
            const int b = tok / T, hw = tok - b * T;
            const int h = hw / WOUT, ww = hw - h * WOUT;
            const int mt = row >> 4, r16 = row & 15;
            const int gid8 = r16 & 7, rowhi = r16 >> 3;
#pragma unroll
            for (int j = 0; j < 12; ++j) {
                int k0 = sub * 48 + j * 4;
                if (k0 >= cl) break;
                float v[4];
#pragma unroll
                for (int e = 0; e < 4; ++e) {
                    int f = kc + k0 + e;
                    float vv = 0.f;
                    if (f < KTOT) {
                        int c2 = f / (DF * DF), rem = f - c2 * DF * DF;
                        int ki = rem / DF, kj = rem - ki * DF;
                        vv = __ldg(&x[((b * 3 + c2) * 224 + h * DF + ki) * 224 + ww * DF + kj]);
                    }
                    v[e] = vv;
                }
                int kt = k0 >> 4, kk = k0 & 15;
                int hi = kk >> 3, tig = (kk & 7) >> 1;
                unsigned base = (((kt * 8 + mt) * 32) + (gid8 << 2) + tig) * 4;
                As[base + (rowhi | (hi << 1))] = f2h2(v[0], v[1]);
                As[base + 4 + (rowhi | (hi << 1))] = f2h2(v[2], v[3]);
            }
        }
        __syncthreads();

        for (int kt = 0; kt < nkt; ++kt) {
            uint4 a0 = As4[(kt * 8 + mg * 2) * 32 + lane];
            uint4 a1 = As4[(kt * 8 + mg * 2 + 1) * 32 + lane];
            uint4 b0 = Bs4[(kt * 6 + nh * 3) * 33 + lane];
            uint4 b1 = Bs4[(kt * 6 + nh * 3 + 1) * 33 + lane];
            uint4 b2 = Bs4[(kt * 6 + nh * 3 + 2) * 33 + lane];
            mma16(acc[0][0], a0, b0.x, b0.y); mma16(acc[0][1], a0, b0.z, b0.w);
            mma16(acc[0][2], a0, b1.x, b1.y); mma16(acc[0][3], a0, b1.z, b1.w);
            mma16(acc[0][4], a0, b2.x, b2.y); mma16(acc[0][5], a0, b2.z, b2.w);
            mma16(acc[1][0], a1, b0.x, b0.y); mma16(acc[1][1], a1, b0.z, b0.w);
            mma16(acc[1][2], a1, b1.x, b1.y); mma16(acc[1][3], a1, b1.z, b1.w);
            mma16(acc[1][4], a1, b2.x, b2.y); mma16(acc[1][5], a1, b2.z, b2.w);
        }
        __syncthreads();
    }

    const int gid = lane >> 2, tig = lane & 3;
#pragma unroll
    for (int m = 0; m < 2; ++m) {
        int rr = row0 + (mg * 2 + m) * 16 + gid;
#pragma unroll
        for (int j = 0; j < 6; ++j) {
            int nc = (nh * 6 + j) * 8 + tig * 2;
            float2 bv = *(const float2*)&bias[nc];
            *(__half2*)&out[(size_t)rr * 96 + nc] =
                __floats2half2_rn(acc[m][j][0] + bv.x, acc[m][j][1] + bv.y);
            *(__half2*)&out[(size_t)(rr + 8) * 96 + nc] =
                __floats2half2_rn(acc[m][j][2] + bv.x, acc[m][j][3] + bv.y);
        }
    }
}

__global__ __launch_bounds__(256, 3) void patch_all(
    const float* __restrict__ x,
    const float* __restrict__ pw0, const float* __restrict__ pb0,
    const float* __restrict__ pw1, const float* __restrict__ pb1,
    const float* __restrict__ pw2, const float* __restrict__ pb2,
    __half* __restrict__ t) {
    __shared__ uint4 As4[AS_U4];
    __shared__ uint4 Bs4[BS_U4];
    int blk = blockIdx.x;
    if (blk < BLK0)
        patch_body<16, 768, 14>(x, pw0, pb0, t, blk, As4, Bs4);
    else if (blk < BLK01)
        patch_body<4, 48, 56>(x, pw1, pb1, t + (size_t)ROWS0 * 96, blk - BLK0, As4, Bs4);
    else
        patch_body<7, 147, 32>(x, pw2, pb2, t + (size_t)(ROWS0 + ROWS1) * 96, blk - BLK01, As4, Bs4);
}

// ---------------------------------------------------------------------------
// window attention — fp16-resident smem, 2x2-tiled QK^T, 2-row x 8-ch AV
// (unchanged from R14/R15)
// ---------------------------------------------------------------------------
__device__ __forceinline__ float dot8h(uint4 a, uint4 c, float s) {
    __half2* ah = (__half2*)&a;
    __half2* ch = (__half2*)&c;
#pragma unroll
    for (int e = 0; e < 4; ++e) {
        float2 x = __half22float2(ah[e]);
        float2 y = __half22float2(ch[e]);
        s = fmaf(x.x, y.x, s);
        s = fmaf(x.y, y.y, s);
    }
    return s;
}

template <int WS>
__device__ __forceinline__ void win_attn_body(const __half* qkv, __half* o,
                                              int Wout, int nw, int rowbase,
                                              int b, int win, char* wsm_raw) {
    constexpr int NT = WS * WS;
    constexpr int RPH = 40;
    constexpr int SSTR = (NT % 2 == 0) ? NT + 1 : NT;
    constexpr int IT2 = (NT + 1) / 2;
    __half* hq = (__half*)wsm_raw;
    __half* hk = hq + 3 * NT * RPH;
    __half* hv = hk + 3 * NT * RPH;
    float* sS = (float*)(hv + 3 * NT * RPH);
    const int wr = win / nw, wc = win % nw;
    const int t = threadIdx.x;
    const int T = Wout * Wout;
    const float scale = 0.17677669529663687f;

    for (int idx = t; idx < NT * 36; idx += 128) {
        int p = idx / 36, u = idx - p * 36;
        int wi = p / WS, wj = p - wi * WS;
        int r = rowbase + b * T + (wr * WS + wi) * Wout + wc * WS + wj;
        uint4 val = __ldg((const uint4*)(qkv + (size_t)r * 288) + u);
        int sec = u / 12, uu = u - sec * 12;
        int head = uu >> 2, c0 = (uu & 3) * 8;
        __half* dst = (sec == 0 ? hq : sec == 1 ? hk : hv) + (head * NT + p) * RPH + c0;
        *(uint4*)dst = val;
    }
    __syncthreads();

    for (int idx = t; idx < 3 * IT2 * IT2; idx += 128) {
        int h = idx / (IT2 * IT2);
        int r = idx - h * IT2 * IT2;
        int i0 = (r / IT2) * 2, j0 = (r % IT2) * 2;
        bool i1ok = (i0 + 1 < NT), j1ok = (j0 + 1 < NT);
        const uint4* qa = (const uint4*)(hq + (h * NT + i0) * RPH);
        const uint4* qb = (const uint4*)(hq + (h * NT + (i1ok ? i0 + 1 : i0)) * RPH);
        const uint4* ka = (const uint4*)(hk + (h * NT + j0) * RPH);
        const uint4* kb = (const uint4*)(hk + (h * NT + (j1ok ? j0 + 1 : j0)) * RPH);
        float s00 = 0.f, s01 = 0.f, s10 = 0.f, s11 = 0.f;
#pragma unroll
        for (int v = 0; v < 4; ++v) {
            uint4 A0 = qa[v], A1 = qb[v], C0 = ka[v], C1 = kb[v];
            s00 = dot8h(A0, C0, s00);
            s01 = dot8h(A0, C1, s01);
            s10 = dot8h(A1, C0, s10);
            s11 = dot8h(A1, C1, s11);
        }
        float* sr0 = sS + (h * NT + i0) * SSTR;
        sr0[j0] = s00 * scale;
        if (j1ok) sr0[j0 + 1] = s01 * scale;
        if (i1ok) {
            float* sr1 = sr0 + SSTR;
            sr1[j0] = s10 * scale;
            if (j1ok) sr1[j0 + 1] = s11 * scale;
        }
    }
    __syncthreads();

    for (int row = t; row < 3 * NT; row += 128) {
        float* p = sS + row * SSTR;
        float m = -1e30f;
        for (int j = 0; j < NT; ++j) m = fmaxf(m, p[j]);
        float Z = 0.f;
        for (int j = 0; j < NT; ++j) {
            float e = __expf(p[j] - m);
            p[j] = e;
            Z += e;
        }
        float inv = 1.f / Z;
        for (int j = 0; j < NT; ++j) p[j] *= inv;
    }
    __syncthreads();

    for (int idx = t; idx < 3 * IT2 * 4; idx += 128) {
        int h = idx / (IT2 * 4);
        int r = idx - h * IT2 * 4;
        int i0 = (r >> 2) * 2, c8 = (r & 3) * 8;
        bool i1ok = (i0 + 1 < NT);
        const float* w0 = sS + (h * NT + i0) * SSTR;
        const float* w1 = sS + (h * NT + (i1ok ? i0 + 1 : i0)) * SSTR;
        float a0[8], a1[8];
#pragma unroll
        for (int e = 0; e < 8; ++e) { a0[e] = 0.f; a1[e] = 0.f; }
        for (int j = 0; j < NT; ++j) {
            uint4 v = *(const uint4*)(hv + (h * NT + j) * RPH + c8);
            float x0 = w0[j], x1 = w1[j];
            __half2* hh = (__half2*)&v;
#pragma unroll
            for (int e = 0; e < 4; ++e) {
                float2 f = __half22float2(hh[e]);
                a0[2 * e] = fmaf(x0, f.x, a0[2 * e]);
                a0[2 * e + 1] = fmaf(x0, f.y, a0[2 * e + 1]);
                a1[2 * e] = fmaf(x1, f.x, a1[2 * e]);
                a1[2 * e + 1] = fmaf(x1, f.y, a1[2 * e + 1]);
            }
        }
        {
            int wi = i0 / WS, wj = i0 - wi * WS;
            int rr = rowbase + b * T + (wr * WS + wi) * Wout + wc * WS + wj;
            uint4 outv;
            __half2* o2 = (__half2*)&outv;
#pragma unroll
            for (int e = 0; e < 4; ++e) o2[e] = __floats2half2_rn(a0[2 * e], a0[2 * e + 1]);
            *(uint4*)(o + (size_t)rr * 96 + h * 32 + c8) = outv;
        }
        if (i1ok) {
            int i1 = i0 + 1;
            int wi = i1 / WS, wj = i1 - wi * WS;
            int rr = rowbase + b * T + (wr * WS + wi) * Wout + wc * WS + wj;
            uint4 outv;
            __half2* o2 = (__half2*)&outv;
#pragma unroll
            for (int e = 0; e < 4; ++e) o2[e] = __floats2half2_rn(a1[2 * e], a1[2 * e + 1]);
            *(uint4*)(o + (size_t)rr * 96 + h * 32 + c8) = outv;
        }
    }
}

__global__ __launch_bounds__(128) void win7_k(const __half* __restrict__ qkv,
                                              __half* __restrict__ o) {
    extern __shared__ __align__(16) char wsm_raw[];
    int b = blockIdx.x / 4, win = blockIdx.x % 4;
    win_attn_body<7>(qkv, o, 14, 2, 0, b, win, wsm_raw);
}

__global__ __launch_bounds__(128) void win4m_k(const __half* __restrict__ qkv,
                                               __half* __restrict__ o) {
    extern __shared__ __align__(16) char wsm_raw[];
    int blk = blockIdx.x;
    if (blk < 64 * 196) {
        int b = blk / 196, win = blk % 196;
        win_attn_body<4>(qkv, o, 56, 14, ROWS0, b, win, wsm_raw);
    } else {
        blk -= 64 * 196;
        int b = blk / 64, win = blk % 64;
        win_attn_body<4>(qkv, o, 32, 8, ROWS0 + ROWS1, b, win, wsm_raw);
    }
}

// ---------------------------------------------------------------------------
// neighbor gather + LN (unchanged)
// ---------------------------------------------------------------------------
__global__ __launch_bounds__(256) void gather_ln_k(const __half* __restrict__ t1,
                                                   const __half* __restrict__ t2,
                                                   const float* __restrict__ g,
                                                   const float* __restrict__ bb,
                                                   __half* __restrict__ kv) {
    const int bl = blockIdx.x;
    const int b = bl / 196, l = bl % 196;
    const int i1 = l / 14, j1 = l % 14;
    __shared__ float s1[16 * 100];
    __shared__ float s2[9 * 100];
    const int tid = threadIdx.x, warp = tid >> 5, lane = tid & 31;

    for (int idx = tid; idx < 16 * 12; idx += 256) {
        int p = idx / 12, q = idx - p * 12;
        int ki = p >> 2, kj = p & 3;
        uint4 u = __ldg((const uint4*)(t1 +
            (size_t)((b * 56 + i1 * 4 + ki) * 56 + j1 * 4 + kj) * 96) + q);
        __half2* h2 = (__half2*)&u;
        float* dst = &s1[p * 100 + q * 8];
#pragma unroll
        for (int e = 0; e < 4; ++e) {
            float2 f = __half22float2(h2[e]);
            dst[2 * e] = f.x;
            dst[2 * e + 1] = f.y;
        }
    }
    for (int idx = tid; idx < 9 * 12; idx += 256) {
        int p = idx / 12, q = idx - p * 12;
        int ki = p / 3, kj = p - ki * 3;
        int rr = i1 * 3 + ki - 5, cc = j1 * 3 + kj - 5;
        float* dst = &s2[p * 100 + q * 8];
        if (rr >= 0 && rr < 32 && cc >= 0 && cc < 32) {
            uint4 u = __ldg((const uint4*)(t2 + (size_t)((b * 32 + rr) * 32 + cc) * 96) + q);
            __half2* h2 = (__half2*)&u;
#pragma unroll
            for (int e = 0; e < 4; ++e) {
                float2 f = __half22float2(h2[e]);
                dst[2 * e] = f.x;
                dst[2 * e + 1] = f.y;
            }
        } else {
#pragma unroll
            for (int e = 0; e < 8; ++e) dst[e] = 0.f;
        }
    }
    __syncthreads();

    float gv[3], bv[3];
#pragma unroll
    for (int i = 0; i < 3; ++i) {
        gv[i] = __ldg(&g[lane + 32 * i]);
        bv[i] = __ldg(&bb[lane + 32 * i]);
    }

    for (int k = warp; k < 25; k += 8) {
        float v[3];
#pragma unroll
        for (int i = 0; i < 3; ++i) {
            int c = lane + 32 * i;
            if (k < 16) {
                int F = k * 96 + c;
                v[i] = s1[(F & 15) * 100 + (F >> 4)];
            } else {
                int F = (k - 16) * 96 + c;
                v[i] = s2[(F % 9) * 100 + (F / 9)];
            }
        }
        float s = v[0] + v[1] + v[2];
        float q = v[0] * v[0] + v[1] * v[1] + v[2] * v[2];
#pragma unroll
        for (int off = 16; off > 0; off >>= 1) {
            s += __shfl_xor_sync(0xffffffffu, s, off);
            q += __shfl_xor_sync(0xffffffffu, q, off);
        }
        float mean = s * (1.f / 96.f);
        float var = fmaf(-mean, mean, q * (1.f / 96.f));
        float rstd = rsqrtf(var + 1e-5f);
        __half* dst = kv + ((size_t)bl * 25 + k) * 96;
#pragma unroll
        for (int i = 0; i < 3; ++i)
            dst[lane + 32 * i] = __float2half((v[i] - mean) * rstd * gv[i] + bv[i]);
    }
}

// ---------------------------------------------------------------------------
// cross attention (unchanged)
// ---------------------------------------------------------------------------
__global__ __launch_bounds__(128) void cross_attn_k(const __half* __restrict__ q,
                                                    const __half* __restrict__ kbuf,
                                                    const __half* __restrict__ vbuf,
                                                    __half* __restrict__ o) {
    const int rl = blockIdx.x;
    __shared__ __half hk[2400], hv[2400];
    __shared__ float sqf[96], ss[25];
    const int t = threadIdx.x;

    const uint4* ksrc = (const uint4*)(kbuf + (size_t)rl * 2400);
    const uint4* vsrc = (const uint4*)(vbuf + (size_t)rl * 2400);
    for (int idx = t; idx < 300; idx += 128) {
        ((uint4*)hk)[idx] = __ldg(ksrc + idx);
        ((uint4*)hv)[idx] = __ldg(vsrc + idx);
    }
    if (t < 96) sqf[t] = __half2float(__ldg(q + (size_t)rl * 96 + t));
    __syncthreads();

    if (t < 25) {
        const __half* kr = hk + t * 96;
        float s = 0.f;
#pragma unroll 8
        for (int c = 0; c < 96; ++c) s = fmaf(sqf[c], __half2float(kr[c]), s);
        ss[t] = s * 0.10206207261596575f;
    }
    __syncthreads();

    if (t < 96) {
        float m = -1e30f;
#pragma unroll
        for (int k = 0; k < 25; ++k) m = fmaxf(m, ss[k]);
        float Z = 0.f, acc = 0.f;
#pragma unroll
        for (int k = 0; k < 25; ++k) {
            float e = __expf(ss[k] - m);
            Z += e;
            acc = fmaf(e, __half2float(hv[k * 96 + t]), acc);
        }
        o[(size_t)rl * 96 + t] = __float2half(acc / Z);
    }
}

// ---------------------------------------------------------------------------
extern "C" void kernel_launch(void* const* d_in, const int* in_sizes, int n_in,
                              void* d_out, int out_size) {
    const float* x       = (const float*)d_in[0];
    const float* pw0     = (const float*)d_in[1];
    const float* pb0     = (const float*)d_in[2];
    const float* pw1     = (const float*)d_in[3];
    const float* pb1     = (const float*)d_in[4];
    const float* pw2     = (const float*)d_in[5];
    const float* pb2     = (const float*)d_in[6];
    const float* wa_ln_g = (const float*)d_in[7];
    const float* wa_ln_b = (const float*)d_in[8];
    const float* wa_qkv  = (const float*)d_in[9];
    const float* wa_ow   = (const float*)d_in[10];
    const float* wa_ob   = (const float*)d_in[11];
    const float* ff_ln_g = (const float*)d_in[12];
    const float* ff_ln_b = (const float*)d_in[13];
    const float* ff_w1   = (const float*)d_in[14];
    const float* ff_b1   = (const float*)d_in[15];
    const float* ff_w2   = (const float*)d_in[16];
    const float* ff_b2   = (const float*)d_in[17];
    const float* lnn_g   = (const float*)d_in[18];
    const float* lnn_b   = (const float*)d_in[19];
    const float* ca_wq   = (const float*)d_in[20];
    const float* ca_wk   = (const float*)d_in[21];
    const float* ca_wv   = (const float*)d_in[22];
    const float* ca_wo   = (const float*)d_in[23];
    const float* ca_bo   = (const float*)d_in[24];
    const float* fi_ln_g = (const float*)d_in[25];
    const float* fi_ln_b = (const float*)d_in[26];
    const float* fi_w1   = (const float*)d_in[27];
    const float* fi_b1   = (const float*)d_in[28];
    const float* fi_w2   = (const float*)d_in[29];
    const float* fi_b2   = (const float*)d_in[30];
    float* out = (float*)d_out;

    __half *t, *qkv, *ob, *kv, *kk, *vv, *qq, *co;
    cudaGetSymbolAddress((void**)&t, g_t);
    cudaGetSymbolAddress((void**)&qkv, g_qkv);
    cudaGetSymbolAddress((void**)&ob, g_ob);
    cudaGetSymbolAddress((void**)&kv, g_kv);
    cudaGetSymbolAddress((void**)&kk, g_k);
    cudaGetSymbolAddress((void**)&vv, g_v);
    cudaGetSymbolAddress((void**)&qq, g_q);
    cudaGetSymbolAddress((void**)&co, g_co);

    __half* t0 = t;
    __half* t1 = t + (size_t)ROWS0 * 96;
    __half* t2 = t + (size_t)(ROWS0 + ROWS1) * 96;

    const int WSM7 = 3 * 3 * 49 * 40 * 2 + 3 * 49 * 49 * 4;
    const int WSM4 = 3 * 3 * 16 * 40 * 2 + 3 * 16 * 17 * 4;
    cudaFuncSetAttribute(win7_k, cudaFuncAttributeMaxDynamicSharedMemorySize, WSM7);
    cudaFuncSetAttribute(win4m_k, cudaFuncAttributeMaxDynamicSharedMemorySize, WSM4);
    cudaFuncSetAttribute(resff_final, cudaFuncAttributeMaxDynamicSharedMemorySize, RES_SMEM);
    cudaFuncSetAttribute(resff_mid, cudaFuncAttributeMaxDynamicSharedMemorySize, RSM_MID);

    // all patch merges in one launch
    patch_all<<<RTOT / 128, 256>>>(x, pw0, pb0, pw1, pb1, pw2, pb2, t);

    // merged per-scale transformer
    gemm_tc<__half, __half, true, false, 0, false, 3, true><<<RTOT / 128, 256>>>(
        t, wa_qkv, nullptr, nullptr, wa_ln_g, wa_ln_b, nullptr, qkv, nullptr, 288);
    win7_k<<<64 * 4, 128, WSM7>>>(qkv, ob);
    win4m_k<<<64 * 196 + 64 * 64, 128, WSM4>>>(qkv, ob);
    resff_mid<<<RTOT / 128, 256, RSM_MID>>>(
        ob, t, wa_ow, wa_ob, ff_ln_g, ff_ln_b, ff_w1, ff_b1, ff_w2, ff_b2);

    // cross-attention fusion
    gather_ln_k<<<64 * 196, 256>>>(t1, t2, lnn_g, lnn_b, kv);
    // FUSED: kk/vv (single A stage) + qq in one launch
    kvq_tc<<<KVBLK + BLK0, 256>>>(kv, t0, ca_wk, ca_wv, ca_wq, lnn_g, lnn_b, kk, vv, qq);
    cross_attn_k<<<12544, 128>>>(qq, kk, vv, co);
    resff_final<<<ROWS0 / 128, 256, RES_SMEM>>>(
        co, t0, out, ca_wo, ca_bo, fi_ln_g, fi_ln_b, fi_w1, fi_b1, fi_w2, fi_b2);
}